// round 7
// baseline (speedup 1.0000x reference)
#include <cuda_runtime.h>
#include <cuda_fp16.h>
#include <math.h>

// Problem dims
#define BB 16
#define TT 256
#define SS 256
#define NA 300
#define DD 512
#define HH 8
#define DKK 64
#define DFF 2048
#define LL 6

#define BT (BB*TT)                 // 4096
#define BHTT ((long)BB*HH*TT*TT)   // 8388608

// d_out layout (floats): x | self_attns | enc_attns | ast_attns
#define SELF_OFF 2097152L
#define ENC_OFF  (SELF_OFF + (long)LL*BHTT)
#define AST_OFF  (ENC_OFF  + (long)LL*BHTT)

// ------------- scratch -------------
__device__ float g_x[BT*DD];
__device__ float g_t[BT*DD];
__device__ float g_qkv[3*BT*DD];
__device__ float g_c[BT*DD];
__device__ float g_h[BT*DFF];
__device__ float g_multi[BB*SS*DD];
__device__ float g_ast1[BB*SS*DD];
__device__ float g_aste[BB*SS*DD];
__device__ float g_mm[BB*SS*SS];
__device__ float g_mmctx[BB*SS*DD];

// ------------- helpers -------------
__device__ __forceinline__ unsigned f2tf(float x) {
    unsigned u; asm("cvt.rna.tf32.f32 %0, %1;" : "=r"(u) : "f"(x)); return u;
}
__device__ __forceinline__ void mma_tf32(float* d,
    unsigned a0, unsigned a1, unsigned a2, unsigned a3,
    unsigned b0, unsigned b1)
{
    asm volatile(
        "mma.sync.aligned.m16n8k8.row.col.f32.tf32.tf32.f32 "
        "{%0,%1,%2,%3},{%4,%5,%6,%7},{%8,%9},{%0,%1,%2,%3};\n"
        : "+f"(d[0]), "+f"(d[1]), "+f"(d[2]), "+f"(d[3])
        : "r"(a0), "r"(a1), "r"(a2), "r"(a3), "r"(b0), "r"(b1));
}
__device__ __forceinline__ unsigned pack_h2(float x, float y) {
    __half2 h = __floats2half2_rn(x, y);
    return *reinterpret_cast<unsigned*>(&h);
}
__device__ __forceinline__ void mma_f16(float* d,
    unsigned a0, unsigned a1, unsigned a2, unsigned a3,
    unsigned b0, unsigned b1)
{
    asm volatile(
        "mma.sync.aligned.m16n8k16.row.col.f32.f16.f16.f32 "
        "{%0,%1,%2,%3},{%4,%5,%6,%7},{%8,%9},{%0,%1,%2,%3};\n"
        : "+f"(d[0]), "+f"(d[1]), "+f"(d[2]), "+f"(d[3])
        : "r"(a0), "r"(a1), "r"(a2), "r"(a3), "r"(b0), "r"(b1));
}

// ---------------------------------------------------------------------
// gemm2 (fp16 MMA, fp32 accum): C[M,N] = A[M,K] @ B[K,N], row-major.
// 128x128x32 tiles, double-buffered, 256 threads (warps 2x4, warp tile
// 64x32). M%128==0, N%128==0, K%32==0. blockIdx.z selects
// (Az, B+z*strB, C+z*strC).
// smem: A half2 V[m][k2] (128 x 16, pad 20); B half2 W[k2][n]
// (16 x 128, pad 136). dyn smem = 2*(128*20 + 16*136)*4 = 37888 B.
// ---------------------------------------------------------------------
#define VP 20
#define WP 136
#define BUFW (128*VP + 16*WP)   // 4736 words

template<bool RELU, bool ACC>
__global__ __launch_bounds__(256, 2) void gemm2(
    const float* __restrict__ A0, const float* __restrict__ A1,
    const float* __restrict__ A2,
    const float* __restrict__ B0, long strB,
    float* __restrict__ C0, long strC,
    int M, int N, int K)
{
    extern __shared__ unsigned smg[];

    const int tid = threadIdx.x, warp = tid >> 5, lane = tid & 31;
    const int g = lane >> 2, tg = lane & 3;
    const int wr = warp >> 2, wc = warp & 3;     // wr 0..1 (64 rows), wc 0..3 (32 cols)
    const int z = blockIdx.z;

    const float* A = (z == 0) ? A0 : (z == 1 ? A1 : A2);
    const float* At = A + (long)blockIdx.y * 128 * K;
    const float* Bt = B0 + (long)z * strB + blockIdx.x * 128;
    float* C = C0 + (long)z * strC;

    const int aR = tid >> 1;          // 0..127
    const int aC = (tid & 1) * 16;    // col offset (floats) within slab
    const int kp = tid >> 5;          // 0..7: B k-pair
    const int bC = (tid & 31) * 4;    // n offset

    float4 ra[4], rb[4];
    #pragma unroll
    for (int u = 0; u < 4; u++)
        ra[u] = *reinterpret_cast<const float4*>(At + (long)aR*K + aC + u*4);
    rb[0] = *reinterpret_cast<const float4*>(Bt + (long)(2*kp     )*N + bC);
    rb[1] = *reinterpret_cast<const float4*>(Bt + (long)(2*kp + 1 )*N + bC);
    rb[2] = *reinterpret_cast<const float4*>(Bt + (long)(2*kp + 16)*N + bC);
    rb[3] = *reinterpret_cast<const float4*>(Bt + (long)(2*kp + 17)*N + bC);

    auto sts = [&](int buf) {
        unsigned* V = smg + buf*BUFW;
        unsigned* W = V + 128*VP;
        {
            uint4 w0, w1;
            w0.x = pack_h2(ra[0].x, ra[0].y); w0.y = pack_h2(ra[0].z, ra[0].w);
            w0.z = pack_h2(ra[1].x, ra[1].y); w0.w = pack_h2(ra[1].z, ra[1].w);
            w1.x = pack_h2(ra[2].x, ra[2].y); w1.y = pack_h2(ra[2].z, ra[2].w);
            w1.z = pack_h2(ra[3].x, ra[3].y); w1.w = pack_h2(ra[3].z, ra[3].w);
            *reinterpret_cast<uint4*>(&V[aR*VP + (aC >> 1)    ]) = w0;
            *reinterpret_cast<uint4*>(&V[aR*VP + (aC >> 1) + 4]) = w1;
        }
        {
            uint4 w0, w1;
            w0.x = pack_h2(rb[0].x, rb[1].x); w0.y = pack_h2(rb[0].y, rb[1].y);
            w0.z = pack_h2(rb[0].z, rb[1].z); w0.w = pack_h2(rb[0].w, rb[1].w);
            *reinterpret_cast<uint4*>(&W[kp*WP + bC]) = w0;
            w1.x = pack_h2(rb[2].x, rb[3].x); w1.y = pack_h2(rb[2].y, rb[3].y);
            w1.z = pack_h2(rb[2].z, rb[3].z); w1.w = pack_h2(rb[2].w, rb[3].w);
            *reinterpret_cast<uint4*>(&W[(kp+8)*WP + bC]) = w1;
        }
    };
    sts(0);
    __syncthreads();

    float acc[16][4];
    #pragma unroll
    for (int i = 0; i < 16; i++) { acc[i][0]=0.f; acc[i][1]=0.f; acc[i][2]=0.f; acc[i][3]=0.f; }

    int cur = 0;
    for (int k0 = 0; k0 < K; k0 += 32) {
        const bool nxt = (k0 + 32) < K;
        if (nxt) {
            #pragma unroll
            for (int u = 0; u < 4; u++)
                ra[u] = *reinterpret_cast<const float4*>(At + (long)aR*K + k0 + 32 + aC + u*4);
            rb[0] = *reinterpret_cast<const float4*>(Bt + (long)(k0 + 32 + 2*kp     )*N + bC);
            rb[1] = *reinterpret_cast<const float4*>(Bt + (long)(k0 + 32 + 2*kp + 1 )*N + bC);
            rb[2] = *reinterpret_cast<const float4*>(Bt + (long)(k0 + 32 + 2*kp + 16)*N + bC);
            rb[3] = *reinterpret_cast<const float4*>(Bt + (long)(k0 + 32 + 2*kp + 17)*N + bC);
        }
        const unsigned* V = smg + cur*BUFW;
        const unsigned* W = V + 128*VP;
        #pragma unroll
        for (int kt = 0; kt < 2; kt++) {
            unsigned a[4][4], b[4][2];
            #pragma unroll
            for (int mi = 0; mi < 4; mi++) {
                int r0 = (wr*64 + mi*16 + g)*VP + kt*8 + tg;
                a[mi][0] = V[r0];
                a[mi][1] = V[r0 + 8*VP];
                a[mi][2] = V[r0 + 4];
                a[mi][3] = V[r0 + 8*VP + 4];
            }
            #pragma unroll
            for (int nj = 0; nj < 4; nj++) {
                int nb = wc*32 + nj*8 + g;
                b[nj][0] = W[(kt*8 + tg    )*WP + nb];
                b[nj][1] = W[(kt*8 + tg + 4)*WP + nb];
            }
            #pragma unroll
            for (int mi = 0; mi < 4; mi++)
                #pragma unroll
                for (int nj = 0; nj < 4; nj++)
                    mma_f16(acc[mi*4+nj], a[mi][0],a[mi][1],a[mi][2],a[mi][3],
                            b[nj][0], b[nj][1]);
        }
        if (nxt) {
            sts(cur ^ 1);
            __syncthreads();
            cur ^= 1;
        }
    }

    #pragma unroll
    for (int mi = 0; mi < 4; mi++) {
        #pragma unroll
        for (int nj = 0; nj < 4; nj++) {
            float* d = acc[mi*4+nj];
            int r0 = blockIdx.y*128 + wr*64 + mi*16 + g;
            int col = blockIdx.x*128 + wc*32 + nj*8 + tg*2;
            float2 v0 = make_float2(d[0], d[1]);
            float2 v1 = make_float2(d[2], d[3]);
            float2* p0 = reinterpret_cast<float2*>(C + (long)r0*N + col);
            float2* p1 = reinterpret_cast<float2*>(C + (long)(r0+8)*N + col);
            if (ACC) { float2 o0 = *p0, o1 = *p1; v0.x+=o0.x; v0.y+=o0.y; v1.x+=o1.x; v1.y+=o1.y; }
            if (RELU) { v0.x=fmaxf(v0.x,0.f); v0.y=fmaxf(v0.y,0.f); v1.x=fmaxf(v1.x,0.f); v1.y=fmaxf(v1.y,0.f); }
            *p0 = v0; *p1 = v1;
        }
    }
}

// ---------------------------------------------------------------------
// attn_fused (fp16 MMA) — unchanged from R6 (proven).
// ---------------------------------------------------------------------
#define QP 36
#define KP 36
#define VBP 68
#define PP 132

template<int MASK, bool CTX>
__global__ __launch_bounds__(256) void attn_fused(
    const float* __restrict__ Q, const float* __restrict__ Km,
    const float* __restrict__ Vm, float* __restrict__ P,
    float* __restrict__ Cctx,
    int Kdim, int lda, int ldb,
    long strA, long offHA, long strB, long offHB,
    int Hh, float scale, const int* __restrict__ tok, int tokStride)
{
    extern __shared__ unsigned sma[];
    unsigned* Qs = sma;
    unsigned* Ks = sma + 64*QP;
    unsigned* Vs = sma + 64*QP + 256*KP;
    unsigned* Ps = sma;
    __shared__ float red[64*4];

    const int tid = threadIdx.x, warp = tid >> 5, lane = tid & 31;
    const int g = lane >> 2, tg = lane & 3;
    const int wr = warp >> 2, wc = warp & 3;
    const int z = blockIdx.y;
    const int bb = z / Hh, hh = z - bb*Hh;
    const int rowTile = blockIdx.x;
    const int rowBase = rowTile * 64;

    const float* Qb = Q + (long)bb*strA + (long)hh*offHA + (long)rowBase*lda;
    const float* Kb = Km + (long)bb*strB + (long)hh*offHB;

    float acc[16][4];
    #pragma unroll
    for (int i = 0; i < 16; i++) { acc[i][0]=0.f; acc[i][1]=0.f; acc[i][2]=0.f; acc[i][3]=0.f; }

    for (int k0 = 0; k0 < Kdim; k0 += 64) {
        #pragma unroll
        for (int p = 0; p < 4; p++) {
            int idx = tid + p*256;
            int r = idx >> 4, c4 = idx & 15;
            float4 v = *reinterpret_cast<const float4*>(Qb + (long)r*lda + k0 + c4*4);
            uint2 w; w.x = pack_h2(v.x, v.y); w.y = pack_h2(v.z, v.w);
            *reinterpret_cast<uint2*>(&Qs[r*QP + c4*2]) = w;
        }
        #pragma unroll
        for (int p = 0; p < 16; p++) {
            int idx = tid + p*256;
            int r = idx >> 4, c4 = idx & 15;
            float4 v = *reinterpret_cast<const float4*>(Kb + (long)r*ldb + k0 + c4*4);
            uint2 w; w.x = pack_h2(v.x, v.y); w.y = pack_h2(v.z, v.w);
            *reinterpret_cast<uint2*>(&Ks[r*KP + c4*2]) = w;
        }
        if (CTX && k0 == 0) {
            const float* Vb = Vm + (long)bb*strB + (long)hh*offHB;
            #pragma unroll
            for (int p = 0; p < 8; p++) {
                int idx = tid + p*256;
                int r2 = idx >> 4, c4 = idx & 15;
                float4 v0 = *reinterpret_cast<const float4*>(Vb + (long)(2*r2  )*ldb + c4*4);
                float4 v1 = *reinterpret_cast<const float4*>(Vb + (long)(2*r2+1)*ldb + c4*4);
                uint4 w;
                w.x = pack_h2(v0.x, v1.x); w.y = pack_h2(v0.y, v1.y);
                w.z = pack_h2(v0.z, v1.z); w.w = pack_h2(v0.w, v1.w);
                *reinterpret_cast<uint4*>(&Vs[r2*VBP + c4*4]) = w;
            }
        }
        __syncthreads();
        #pragma unroll
        for (int kt = 0; kt < 4; kt++) {
            unsigned a[2][4], b[8][2];
            #pragma unroll
            for (int mi = 0; mi < 2; mi++) {
                int mb = wr*32 + mi*16;
                a[mi][0] = Qs[(mb+g  )*QP + kt*8 + tg];
                a[mi][1] = Qs[(mb+g+8)*QP + kt*8 + tg];
                a[mi][2] = Qs[(mb+g  )*QP + kt*8 + tg + 4];
                a[mi][3] = Qs[(mb+g+8)*QP + kt*8 + tg + 4];
            }
            #pragma unroll
            for (int nj = 0; nj < 8; nj++) {
                int nb = wc*64 + nj*8;
                b[nj][0] = Ks[(nb+g)*KP + kt*8 + tg];
                b[nj][1] = Ks[(nb+g)*KP + kt*8 + tg + 4];
            }
            #pragma unroll
            for (int mi = 0; mi < 2; mi++)
                #pragma unroll
                for (int nj = 0; nj < 8; nj++)
                    mma_f16(acc[mi*8+nj], a[mi][0],a[mi][1],a[mi][2],a[mi][3],
                            b[nj][0], b[nj][1]);
        }
        if (k0 + 64 < Kdim) __syncthreads();
    }

    // ---- scale + mask ----
    #pragma unroll
    for (int mi = 0; mi < 2; mi++) {
        #pragma unroll
        for (int nj = 0; nj < 8; nj++) {
            float* d = acc[mi*8+nj];
            int col = wc*64 + nj*8 + tg*2;
            int lr0 = wr*32 + mi*16 + g;
            #pragma unroll
            for (int c = 0; c < 4; c++) {
                int gcol = col + (c & 1);
                int grow = rowBase + lr0 + ((c >> 1) * 8);
                float v = d[c] * scale;
                if (MASK == 1) {
                    if (tok[bb*tokStride + gcol] == 0 || gcol > grow) v = -1e9f;
                } else if (MASK == 2) {
                    if (tok[bb*tokStride + gcol] == 0) v = -1e9f;
                }
                d[c] = v;
            }
        }
    }

    // ---- softmax (fp32) ----
    float rmax[4];
    #pragma unroll
    for (int mi = 0; mi < 2; mi++) {
        float m0 = -1e30f, m1 = -1e30f;
        #pragma unroll
        for (int nj = 0; nj < 8; nj++) {
            float* d = acc[mi*8+nj];
            m0 = fmaxf(m0, fmaxf(d[0], d[1]));
            m1 = fmaxf(m1, fmaxf(d[2], d[3]));
        }
        rmax[mi*2+0] = m0; rmax[mi*2+1] = m1;
    }
    #pragma unroll
    for (int i = 0; i < 4; i++) {
        rmax[i] = fmaxf(rmax[i], __shfl_xor_sync(0xffffffffu, rmax[i], 1));
        rmax[i] = fmaxf(rmax[i], __shfl_xor_sync(0xffffffffu, rmax[i], 2));
    }
    if (tg == 0) {
        #pragma unroll
        for (int mi = 0; mi < 2; mi++) {
            red[(wr*32 + mi*16 + g    )*4 + wc] = rmax[mi*2+0];
            red[(wr*32 + mi*16 + g + 8)*4 + wc] = rmax[mi*2+1];
        }
    }
    __syncthreads();
    float fmax4[4];
    #pragma unroll
    for (int mi = 0; mi < 2; mi++) {
        int r0 = wr*32 + mi*16 + g, r1 = r0 + 8;
        fmax4[mi*2+0] = fmaxf(fmaxf(red[r0*4+0], red[r0*4+1]), fmaxf(red[r0*4+2], red[r0*4+3]));
        fmax4[mi*2+1] = fmaxf(fmaxf(red[r1*4+0], red[r1*4+1]), fmaxf(red[r1*4+2], red[r1*4+3]));
    }
    __syncthreads();

    float rsum[4] = {0.f, 0.f, 0.f, 0.f};
    #pragma unroll
    for (int mi = 0; mi < 2; mi++) {
        #pragma unroll
        for (int nj = 0; nj < 8; nj++) {
            float* d = acc[mi*8+nj];
            d[0] = __expf(d[0] - fmax4[mi*2+0]);
            d[1] = __expf(d[1] - fmax4[mi*2+0]);
            d[2] = __expf(d[2] - fmax4[mi*2+1]);
            d[3] = __expf(d[3] - fmax4[mi*2+1]);
            rsum[mi*2+0] += d[0] + d[1];
            rsum[mi*2+1] += d[2] + d[3];
        }
    }
    #pragma unroll
    for (int i = 0; i < 4; i++) {
        rsum[i] += __shfl_xor_sync(0xffffffffu, rsum[i], 1);
        rsum[i] += __shfl_xor_sync(0xffffffffu, rsum[i], 2);
    }
    if (tg == 0) {
        #pragma unroll
        for (int mi = 0; mi < 2; mi++) {
            red[(wr*32 + mi*16 + g    )*4 + wc] = rsum[mi*2+0];
            red[(wr*32 + mi*16 + g + 8)*4 + wc] = rsum[mi*2+1];
        }
    }
    __syncthreads();
    float rinv[4];
    #pragma unroll
    for (int mi = 0; mi < 2; mi++) {
        int r0 = wr*32 + mi*16 + g, r1 = r0 + 8;
        rinv[mi*2+0] = 1.f / (red[r0*4+0] + red[r0*4+1] + red[r0*4+2] + red[r0*4+3]);
        rinv[mi*2+1] = 1.f / (red[r1*4+0] + red[r1*4+1] + red[r1*4+2] + red[r1*4+3]);
    }

    float* Pb = P + (long)z * 65536L + (long)rowBase * 256;
    #pragma unroll
    for (int mi = 0; mi < 2; mi++) {
        #pragma unroll
        for (int nj = 0; nj < 8; nj++) {
            float* d = acc[mi*8+nj];
            int col = wc*64 + nj*8 + tg*2;
            int r0 = wr*32 + mi*16 + g;
            float p0 = d[0]*rinv[mi*2+0], p1 = d[1]*rinv[mi*2+0];
            float p2 = d[2]*rinv[mi*2+1], p3 = d[3]*rinv[mi*2+1];
            *reinterpret_cast<float2*>(Pb + (long)r0*256 + col) = make_float2(p0, p1);
            *reinterpret_cast<float2*>(Pb + (long)(r0+8)*256 + col) = make_float2(p2, p3);
            if (CTX) {
                int k2 = wc*32 + nj*4 + tg;
                Ps[r0*PP + k2]     = pack_h2(p0, p1);
                Ps[(r0+8)*PP + k2] = pack_h2(p2, p3);
            }
        }
    }

    if (CTX) {
        __syncthreads();
        float acc2[4][4];
        #pragma unroll
        for (int i = 0; i < 4; i++) { acc2[i][0]=0.f; acc2[i][1]=0.f; acc2[i][2]=0.f; acc2[i][3]=0.f; }
        #pragma unroll
        for (int kt = 0; kt < 16; kt++) {
            unsigned a[2][4], b[2][2];
            #pragma unroll
            for (int mi = 0; mi < 2; mi++) {
                int mb = wr*32 + mi*16;
                a[mi][0] = Ps[(mb+g  )*PP + kt*8 + tg];
                a[mi][1] = Ps[(mb+g+8)*PP + kt*8 + tg];
                a[mi][2] = Ps[(mb+g  )*PP + kt*8 + tg + 4];
                a[mi][3] = Ps[(mb+g+8)*PP + kt*8 + tg + 4];
            }
            #pragma unroll
            for (int nj = 0; nj < 2; nj++) {
                int nb = wc*16 + nj*8 + g;
                b[nj][0] = Vs[(kt*8 + tg    )*VBP + nb];
                b[nj][1] = Vs[(kt*8 + tg + 4)*VBP + nb];
            }
            #pragma unroll
            for (int mi = 0; mi < 2; mi++)
                #pragma unroll
                for (int nj = 0; nj < 2; nj++)
                    mma_f16(acc2[mi*2+nj], a[mi][0],a[mi][1],a[mi][2],a[mi][3],
                            b[nj][0], b[nj][1]);
        }
        float* Cb = Cctx + (long)bb*TT*DD + hh*64;
        #pragma unroll
        for (int mi = 0; mi < 2; mi++) {
            #pragma unroll
            for (int nj = 0; nj < 2; nj++) {
                float* d = acc2[mi*2+nj];
                int r0 = rowBase + wr*32 + mi*16 + g;
                int col = wc*16 + nj*8 + tg*2;
                *reinterpret_cast<float2*>(Cb + (long)r0*DD + col) = make_float2(d[0], d[1]);
                *reinterpret_cast<float2*>(Cb + (long)(r0+8)*DD + col) = make_float2(d[2], d[3]);
            }
        }
    }
}

// ---------------------------------------------------------------------
// bgemm_tf32 (preamble) — unchanged.
// ---------------------------------------------------------------------
template<bool ROWBIAS>
__global__ __launch_bounds__(256) void bgemm_tf32(
    const float* __restrict__ A, const float* __restrict__ B,
    float* __restrict__ C, int M, int N, int K,
    int lda, int ldb, int ldc,
    long strA, long offHA, long strB, long offHB, long strC, long offHC,
    int Hh, const float* __restrict__ bias)
{
    __shared__ unsigned As[128*36];
    __shared__ unsigned Bs[32*72];
    const int tid = threadIdx.x, warp = tid >> 5, lane = tid & 31;
    const int g = lane >> 2, tg = lane & 3;
    const int wr = warp >> 1, wc = warp & 1;
    const int z = blockIdx.z;
    const int bb = z / Hh, hh = z - bb*Hh;

    const float* Ab = A + (long)bb*strA + (long)hh*offHA + (long)blockIdx.y*128*lda;
    const float* Bb = B + (long)bb*strB + (long)hh*offHB + (long)blockIdx.x*64;

    float acc[8][4];
    #pragma unroll
    for (int i = 0; i < 8; i++) { acc[i][0]=0.f; acc[i][1]=0.f; acc[i][2]=0.f; acc[i][3]=0.f; }

    for (int k0 = 0; k0 < K; k0 += 32) {
        if (k0 + 32 <= K && (lda & 3) == 0) {
            #pragma unroll
            for (int p = 0; p < 4; p++) {
                int idx = tid + p*256;
                int r = idx >> 3, c4 = idx & 7;
                float4 v = *reinterpret_cast<const float4*>(Ab + (long)r*lda + k0 + c4*4);
                unsigned* d = &As[r*36 + c4*4];
                d[0]=f2tf(v.x); d[1]=f2tf(v.y); d[2]=f2tf(v.z); d[3]=f2tf(v.w);
            }
        } else {
            #pragma unroll
            for (int p = 0; p < 16; p++) {
                int idx = tid + p*256;
                int r = idx >> 5, c = idx & 31;
                float v = (k0 + c < K) ? Ab[(long)r*lda + k0 + c] : 0.f;
                As[r*36 + c] = f2tf(v);
            }
        }
        #pragma unroll
        for (int p = 0; p < 2; p++) {
            int idx = tid + p*256;
            int r = idx >> 4, c4 = idx & 15;
            float4 v;
            if (k0 + r < K)
                v = *reinterpret_cast<const float4*>(Bb + (long)(k0 + r)*ldb + c4*4);
            else
                v = make_float4(0.f, 0.f, 0.f, 0.f);
            unsigned* d = &Bs[r*72 + c4*4];
            d[0]=f2tf(v.x); d[1]=f2tf(v.y); d[2]=f2tf(v.z); d[3]=f2tf(v.w);
        }
        __syncthreads();
        #pragma unroll
        for (int ks = 0; ks < 4; ks++) {
            const int kk = ks * 8;
            unsigned a[2][4], b[4][2];
            #pragma unroll
            for (int mi = 0; mi < 2; mi++) {
                int mb = wr*32 + mi*16;
                a[mi][0] = As[(mb+g  )*36 + kk + tg];
                a[mi][1] = As[(mb+g+8)*36 + kk + tg];
                a[mi][2] = As[(mb+g  )*36 + kk + tg + 4];
                a[mi][3] = As[(mb+g+8)*36 + kk + tg + 4];
            }
            #pragma unroll
            for (int nj = 0; nj < 4; nj++) {
                int nb = wc*32 + nj*8;
                b[nj][0] = Bs[(kk+tg  )*72 + nb + g];
                b[nj][1] = Bs[(kk+tg+4)*72 + nb + g];
            }
            #pragma unroll
            for (int mi = 0; mi < 2; mi++)
                #pragma unroll
                for (int nj = 0; nj < 4; nj++)
                    mma_tf32(acc[mi*4+nj], a[mi][0],a[mi][1],a[mi][2],a[mi][3],
                             b[nj][0], b[nj][1]);
        }
        __syncthreads();
    }

    float* Cb = C + (long)bb*strC + (long)hh*offHC;
    #pragma unroll
    for (int mi = 0; mi < 2; mi++) {
        #pragma unroll
        for (int nj = 0; nj < 4; nj++) {
            float* d = acc[mi*4+nj];
            int r0 = blockIdx.y*128 + wr*32 + mi*16 + g;
            int col = blockIdx.x*64 + wc*32 + nj*8 + tg*2;
            float b0 = ROWBIAS ? bias[r0] : 0.f;
            float b1 = ROWBIAS ? bias[r0+8] : 0.f;
            *reinterpret_cast<float2*>(Cb + (long)r0*ldc + col) =
                make_float2(d[0]+b0, d[1]+b0);
            *reinterpret_cast<float2*>(Cb + (long)(r0+8)*ldc + col) =
                make_float2(d[2]+b1, d[3]+b1);
        }
    }
}

// ---------------------------------------------------------------------
__global__ __launch_bounds__(256) void add_ln(
    const float* __restrict__ a, const float* __restrict__ b,
    float* __restrict__ out, const float* __restrict__ g,
    const float* __restrict__ beta)
{
    long off = (long)blockIdx.x * DD;
    int t = threadIdx.x;
    int warp = t >> 5, lane = t & 31;
    float v0 = a[off + t] + b[off + t];
    float v1 = a[off + t + 256] + b[off + t + 256];
    __shared__ float ws[8], ws2[8];

    float s = v0 + v1;
    #pragma unroll
    for (int o = 16; o > 0; o >>= 1) s += __shfl_xor_sync(0xffffffffu, s, o);
    if (lane == 0) ws[warp] = s;
    __syncthreads();
    float mu = (ws[0]+ws[1]+ws[2]+ws[3]+ws[4]+ws[5]+ws[6]+ws[7]) * (1.f/DD);

    float d0 = v0 - mu, d1 = v1 - mu;
    float q = d0*d0 + d1*d1;
    #pragma unroll
    for (int o = 16; o > 0; o >>= 1) q += __shfl_xor_sync(0xffffffffu, q, o);
    if (lane == 0) ws2[warp] = q;
    __syncthreads();
    float rstd = rsqrtf((ws2[0]+ws2[1]+ws2[2]+ws2[3]+ws2[4]+ws2[5]+ws2[6]+ws2[7]) * (1.f/DD) + 1e-5f);

    float g0 = g ? g[t] : 1.f,       g1 = g ? g[t+256] : 1.f;
    float b0 = beta ? beta[t] : 0.f, b1 = beta ? beta[t+256] : 0.f;
    out[off + t]       = d0 * rstd * g0 + b0;
    out[off + t + 256] = d1 * rstd * g1 + b1;
}

__global__ void embed_pe(const int* __restrict__ dec,
                         const float* __restrict__ emb,
                         float* __restrict__ x)
{
    long idx = (long)blockIdx.x * blockDim.x + threadIdx.x;
    if (idx >= (long)BT*DD) return;
    int d  = (int)(idx % DD);
    long bt = idx / DD;
    int t  = (int)(bt % TT);
    int tokidx = dec[bt];
    int d2 = d & ~1;
    float div = expf(-logf(10000.f) * (float)d2 / (float)DD);
    float ang = (float)t * div;
    float pe = (d & 1) ? cosf(ang) : sinf(ang);
    x[idx] = emb[(long)tokidx*DD + d] + pe;
}

__global__ void add3(const float* __restrict__ a, const float* __restrict__ bias,
                     const float* __restrict__ c, float* __restrict__ out, long n)
{
    long i = (long)blockIdx.x * blockDim.x + threadIdx.x;
    if (i >= n) return;
    out[i] = a[i] + bias[i % DD] + c[i];
}

__global__ void copyk(const float* __restrict__ src, float* __restrict__ dst, long n)
{
    long i = (long)blockIdx.x * blockDim.x + threadIdx.x;
    if (i < n) dst[i] = src[i];
}

// ---------------------------------------------------------------------
extern "C" void kernel_launch(void* const* d_in, const int* in_sizes, int n_in,
                              void* d_out, int out_size)
{
    const int*   dec     = (const int*)  d_in[0];
    const int*   enc     = (const int*)  d_in[1];
    const float* enc_out = (const float*)d_in[2];
    const float* ast_out = (const float*)d_in[3];
    const float* src_emb = (const float*)d_in[4];
    const float* ast_emb = (const float*)d_in[5];
    const float* emb     = (const float*)d_in[7];
    const float* attn_W  = (const float*)d_in[8];
    const float* ln_g    = (const float*)d_in[9];
    const float* ln_b    = (const float*)d_in[10];
    const float* W1      = (const float*)d_in[11];
    const float* W2      = (const float*)d_in[12];
    const float* conv_w  = (const float*)d_in[13];
    const float* conv_b  = (const float*)d_in[14];
    const float* mffnW   = (const float*)d_in[15];
    const float* mffnb   = (const float*)d_in[16];
    float* out = (float*)d_out;

    float *x,*t,*qkv,*c,*h,*multi,*ast1,*aste,*mm,*mmctx;
    cudaGetSymbolAddress((void**)&x,     g_x);
    cudaGetSymbolAddress((void**)&t,     g_t);
    cudaGetSymbolAddress((void**)&qkv,   g_qkv);
    cudaGetSymbolAddress((void**)&c,     g_c);
    cudaGetSymbolAddress((void**)&h,     g_h);
    cudaGetSymbolAddress((void**)&multi, g_multi);
    cudaGetSymbolAddress((void**)&ast1,  g_ast1);
    cudaGetSymbolAddress((void**)&aste,  g_aste);
    cudaGetSymbolAddress((void**)&mm,    g_mm);
    cudaGetSymbolAddress((void**)&mmctx, g_mmctx);

    const int GM_SMEM  = 2*BUFW*4;                              // 37888
    const int AT_SMEM  = (64*QP + 256*KP + 128*VBP)*4;          // 80896 (CTX)
    const int MM_SMEM  = (64*QP + 256*KP)*4;                    // 46080 (no CTX)
    cudaFuncSetAttribute(gemm2<false,false>, cudaFuncAttributeMaxDynamicSharedMemorySize, GM_SMEM);
    cudaFuncSetAttribute(gemm2<false,true >, cudaFuncAttributeMaxDynamicSharedMemorySize, GM_SMEM);
    cudaFuncSetAttribute(gemm2<true ,false>, cudaFuncAttributeMaxDynamicSharedMemorySize, GM_SMEM);
    cudaFuncSetAttribute(attn_fused<0,false>, cudaFuncAttributeMaxDynamicSharedMemorySize, MM_SMEM);
    cudaFuncSetAttribute(attn_fused<0,true >, cudaFuncAttributeMaxDynamicSharedMemorySize, AT_SMEM);
    cudaFuncSetAttribute(attn_fused<1,true >, cudaFuncAttributeMaxDynamicSharedMemorySize, AT_SMEM);
    cudaFuncSetAttribute(attn_fused<2,true >, cudaFuncAttributeMaxDynamicSharedMemorySize, AT_SMEM);

    float* q = qkv;
    float* k = qkv + (long)BT*DD;
    float* v = qkv + 2L*BT*DD;

    // ---------------- multi_model preamble ----------------
    {
        dim3 grid(DD/64, SS/128, BB);
        bgemm_tf32<true><<<grid, 256>>>(conv_w, ast_out, ast1,
            SS, DD, NA, NA, DD, DD,
            0L, 0L, (long)NA*DD, 0L, (long)SS*DD, 0L, 1, conv_b);
        bgemm_tf32<true><<<grid, 256>>>(conv_w, ast_emb, aste,
            SS, DD, NA, NA, DD, DD,
            0L, 0L, (long)NA*DD, 0L, (long)SS*DD, 0L, 1, conv_b);
    }
    {
        dim3 gs(SS/64, BB);
        attn_fused<0,false><<<gs, 256, MM_SMEM>>>(ast1, enc_out, nullptr, mm, nullptr,
            DD, DD, DD, (long)SS*DD, 0L, (long)SS*DD, 0L,
            1, 0.125f, nullptr, 0);
        dim3 grid2(DD/64, SS/128, BB);
        bgemm_tf32<false><<<grid2, 256>>>(mm, enc_out, mmctx,
            SS, DD, SS, SS, DD, DD,
            (long)SS*SS, 0L, (long)SS*DD, 0L, (long)SS*DD, 0L, 1, nullptr);
    }
    {
        dim3 grid(DD/128, BT/128, 1);
        gemm2<false,false><<<grid, 256, GM_SMEM>>>(src_emb, src_emb, src_emb,
            mffnW, 0L, t, 0L, BT, DD, DD);
        gemm2<false,true ><<<grid, 256, GM_SMEM>>>(aste, aste, aste,
            mffnW + DD*DD, 0L, t, 0L, BT, DD, DD);
        long n = (long)BB*SS*DD;
        add3<<<(int)((n + 255)/256), 256>>>(t, mffnb, mmctx, multi, n);
    }
    embed_pe<<<(BT*DD + 255)/256, 256>>>(dec, emb, x);

    // ---------------- decoder layers ----------------
    dim3 gQKV(DD/128, BT/128, 3);
    dim3 gProj(DD/128, BT/128, 1);
    dim3 gF1(DFF/128, BT/128, 1);
    dim3 gScore(TT/64, BB*HH);

    for (int l = 0; l < LL; l++) {
        for (int a = 0; a < 3; a++) {
            const float* W = attn_W + ((long)(l*3 + a) * 4) * DD * DD;
            const float* Wo = W + 3L*DD*DD;
            const float* xk = (a == 0) ? x : (a == 1 ? enc_out : multi);

            gemm2<false,false><<<gQKV, 256, GM_SMEM>>>(x, xk, xk,
                W, (long)DD*DD, qkv, (long)BT*DD, BT, DD, DD);

            long attnBase = (a == 0 ? SELF_OFF : (a == 1 ? ENC_OFF : AST_OFF))
                            + (long)l * BHTT;
            float* P = out + attnBase;

            if (a == 0)
                attn_fused<1,true><<<gScore, 256, AT_SMEM>>>(q, k, v, P, c,
                    DKK, DD, DD, (long)TT*DD, 64L, (long)TT*DD, 64L,
                    HH, 0.125f, dec, TT);
            else if (a == 1)
                attn_fused<2,true><<<gScore, 256, AT_SMEM>>>(q, k, v, P, c,
                    DKK, DD, DD, (long)TT*DD, 64L, (long)TT*DD, 64L,
                    HH, 0.125f, enc, SS);
            else
                attn_fused<0,true><<<gScore, 256, AT_SMEM>>>(q, k, v, P, c,
                    DKK, DD, DD, (long)TT*DD, 64L, (long)TT*DD, 64L,
                    HH, 0.125f, nullptr, 0);

            gemm2<false,false><<<gProj, 256, GM_SMEM>>>(c, c, c,
                Wo, 0L, t, 0L, BT, DD, DD);
            add_ln<<<BT, 256>>>(t, x, x,
                ln_g + (long)(l*3 + a)*DD, ln_b + (long)(l*3 + a)*DD);
        }
        gemm2<true ,false><<<gF1, 256, GM_SMEM>>>(x, x, x,
            W1 + (long)l*DD*DFF, 0L, h, 0L, BT, DFF, DD);
        gemm2<false,false><<<gProj, 256, GM_SMEM>>>(h, h, h,
            W2 + (long)l*DFF*DD, 0L, t, 0L, BT, DD, DFF);
        add_ln<<<BT, 256>>>(t, x, x, nullptr, nullptr);
    }

    copyk<<<(BT*DD + 255)/256, 256>>>(x, out, (long)BT*DD);
}

// round 8
// speedup vs baseline: 1.1345x; 1.1345x over previous
#include <cuda_runtime.h>
#include <cuda_fp16.h>
#include <math.h>

// Problem dims
#define BB 16
#define TT 256
#define SS 256
#define NA 300
#define DD 512
#define HH 8
#define DKK 64
#define DFF 2048
#define LL 6

#define BT (BB*TT)                 // 4096
#define BHTT ((long)BB*HH*TT*TT)   // 8388608

// d_out layout (floats): x | self_attns | enc_attns | ast_attns
#define SELF_OFF 2097152L
#define ENC_OFF  (SELF_OFF + (long)LL*BHTT)
#define AST_OFF  (ENC_OFF  + (long)LL*BHTT)

// ------------- scratch -------------
__device__ float g_x[BT*DD];
__device__ float g_t[BT*DD];
__device__ float g_qkv[3*BT*DD];
__device__ float g_c[BT*DD];
__device__ float g_h[BT*DFF];
__device__ float g_multi[BB*SS*DD];
__device__ float g_ast1[BB*SS*DD];
__device__ float g_aste[BB*SS*DD];
__device__ float g_mm[BB*SS*SS];
__device__ float g_mmctx[BB*SS*DD];

// ------------- helpers -------------
__device__ __forceinline__ unsigned f2tf(float x) {
    unsigned u; asm("cvt.rna.tf32.f32 %0, %1;" : "=r"(u) : "f"(x)); return u;
}
__device__ __forceinline__ void mma_tf32(float* d,
    unsigned a0, unsigned a1, unsigned a2, unsigned a3,
    unsigned b0, unsigned b1)
{
    asm volatile(
        "mma.sync.aligned.m16n8k8.row.col.f32.tf32.tf32.f32 "
        "{%0,%1,%2,%3},{%4,%5,%6,%7},{%8,%9},{%0,%1,%2,%3};\n"
        : "+f"(d[0]), "+f"(d[1]), "+f"(d[2]), "+f"(d[3])
        : "r"(a0), "r"(a1), "r"(a2), "r"(a3), "r"(b0), "r"(b1));
}
__device__ __forceinline__ unsigned pack_h2(float x, float y) {
    __half2 h = __floats2half2_rn(x, y);
    return *reinterpret_cast<unsigned*>(&h);
}
__device__ __forceinline__ void mma_f16(float* d,
    unsigned a0, unsigned a1, unsigned a2, unsigned a3,
    unsigned b0, unsigned b1)
{
    asm volatile(
        "mma.sync.aligned.m16n8k16.row.col.f32.f16.f16.f32 "
        "{%0,%1,%2,%3},{%4,%5,%6,%7},{%8,%9},{%0,%1,%2,%3};\n"
        : "+f"(d[0]), "+f"(d[1]), "+f"(d[2]), "+f"(d[3])
        : "r"(a0), "r"(a1), "r"(a2), "r"(a3), "r"(b0), "r"(b1));
}
__device__ __forceinline__ void ldsm_x4(unsigned& r0, unsigned& r1,
                                        unsigned& r2, unsigned& r3, unsigned addr)
{
    asm volatile("ldmatrix.sync.aligned.m8n8.x4.shared.b16 {%0,%1,%2,%3}, [%4];"
        : "=r"(r0), "=r"(r1), "=r"(r2), "=r"(r3) : "r"(addr));
}

// ---------------------------------------------------------------------
// gemm2 (fp16 MMA, fp32 accum): C[M,N] = A[M,K] @ B[K,N], row-major.
// 64x128x32 tiles, double-buffered, 256 threads (warps 2x4, warp 32x32).
// A fragments loaded via ldmatrix.x4 (layout identical to R6).
// smem: A half2 V[m][k2] (64 x 16, pad 20); B half2 W[k2][n] (16 x 128,
// pad 136). dyn smem = 2*(64*20 + 16*136)*4 = 27648 B.
// ---------------------------------------------------------------------
#define VP 20
#define WP 136
#define BUFW (64*VP + 16*WP)   // 3456 words

template<bool RELU, bool ACC>
__global__ __launch_bounds__(256, 2) void gemm2(
    const float* __restrict__ A0, const float* __restrict__ A1,
    const float* __restrict__ A2,
    const float* __restrict__ B0, long strB,
    float* __restrict__ C0, long strC,
    int M, int N, int K)
{
    extern __shared__ unsigned smg[];

    const int tid = threadIdx.x, warp = tid >> 5, lane = tid & 31;
    const int g = lane >> 2, tg = lane & 3;
    const int wr = warp >> 2, wc = warp & 3;     // wr 0..1 (32 rows), wc 0..3 (32 cols)
    const int z = blockIdx.z;

    const float* A = (z == 0) ? A0 : (z == 1 ? A1 : A2);
    const float* At = A + (long)blockIdx.y * 64 * K;
    const float* Bt = B0 + (long)z * strB + blockIdx.x * 128;
    float* C = C0 + (long)z * strC;

    const int aR = tid >> 3;
    const int aC = (tid & 7) * 4;
    const int kp = tid >> 5;
    const int bC = (tid & 31) * 4;

    // ldmatrix per-lane A address offset (bytes, within a buffer):
    // lanes 0-7: rows m0-7 seg0 | 8-15: m8-15 seg0 | 16-23: m0-7 seg1 | 24-31: m8-15 seg1
    const int laneRow = (lane & 7) + ((lane >> 3) & 1) * 8;
    const int laneSeg = (lane >> 4) * 4;
    const unsigned vbase = (unsigned)__cvta_generic_to_shared(smg);
    const unsigned aLane = vbase + ((wr*32 + laneRow)*VP + laneSeg) * 4;

    float4 ra[2], rb[4];
    #pragma unroll
    for (int p = 0; p < 2; p++)
        ra[p] = *reinterpret_cast<const float4*>(At + (long)(aR + p*32)*K + aC);
    rb[0] = *reinterpret_cast<const float4*>(Bt + (long)(2*kp     )*N + bC);
    rb[1] = *reinterpret_cast<const float4*>(Bt + (long)(2*kp + 1 )*N + bC);
    rb[2] = *reinterpret_cast<const float4*>(Bt + (long)(2*kp + 16)*N + bC);
    rb[3] = *reinterpret_cast<const float4*>(Bt + (long)(2*kp + 17)*N + bC);

    auto sts = [&](int buf) {
        unsigned* V = smg + buf*BUFW;
        unsigned* W = V + 64*VP;
        #pragma unroll
        for (int p = 0; p < 2; p++) {
            int m = aR + p*32;
            uint2 w;
            w.x = pack_h2(ra[p].x, ra[p].y);
            w.y = pack_h2(ra[p].z, ra[p].w);
            *reinterpret_cast<uint2*>(&V[m*VP + (aC >> 1)]) = w;
        }
        {
            uint4 w0, w1;
            w0.x = pack_h2(rb[0].x, rb[1].x); w0.y = pack_h2(rb[0].y, rb[1].y);
            w0.z = pack_h2(rb[0].z, rb[1].z); w0.w = pack_h2(rb[0].w, rb[1].w);
            *reinterpret_cast<uint4*>(&W[kp*WP + bC]) = w0;
            w1.x = pack_h2(rb[2].x, rb[3].x); w1.y = pack_h2(rb[2].y, rb[3].y);
            w1.z = pack_h2(rb[2].z, rb[3].z); w1.w = pack_h2(rb[2].w, rb[3].w);
            *reinterpret_cast<uint4*>(&W[(kp+8)*WP + bC]) = w1;
        }
    };
    sts(0);
    __syncthreads();

    float acc[8][4];
    #pragma unroll
    for (int i = 0; i < 8; i++) { acc[i][0]=0.f; acc[i][1]=0.f; acc[i][2]=0.f; acc[i][3]=0.f; }

    int cur = 0;
    for (int k0 = 0; k0 < K; k0 += 32) {
        const bool nxt = (k0 + 32) < K;
        if (nxt) {
            #pragma unroll
            for (int p = 0; p < 2; p++)
                ra[p] = *reinterpret_cast<const float4*>(At + (long)(aR + p*32)*K + k0 + 32 + aC);
            rb[0] = *reinterpret_cast<const float4*>(Bt + (long)(k0 + 32 + 2*kp     )*N + bC);
            rb[1] = *reinterpret_cast<const float4*>(Bt + (long)(k0 + 32 + 2*kp + 1 )*N + bC);
            rb[2] = *reinterpret_cast<const float4*>(Bt + (long)(k0 + 32 + 2*kp + 16)*N + bC);
            rb[3] = *reinterpret_cast<const float4*>(Bt + (long)(k0 + 32 + 2*kp + 17)*N + bC);
        }
        const unsigned* W = smg + cur*BUFW + 64*VP;
        const unsigned aBuf = aLane + cur*BUFW*4;
        #pragma unroll
        for (int kt = 0; kt < 2; kt++) {
            unsigned a[2][4], b[4][2];
            #pragma unroll
            for (int mi = 0; mi < 2; mi++)
                ldsm_x4(a[mi][0], a[mi][1], a[mi][2], a[mi][3],
                        aBuf + mi*16*VP*4 + kt*32);
            #pragma unroll
            for (int nj = 0; nj < 4; nj++) {
                int nb = wc*32 + nj*8 + g;
                b[nj][0] = W[(kt*8 + tg    )*WP + nb];
                b[nj][1] = W[(kt*8 + tg + 4)*WP + nb];
            }
            #pragma unroll
            for (int mi = 0; mi < 2; mi++)
                #pragma unroll
                for (int nj = 0; nj < 4; nj++)
                    mma_f16(acc[mi*4+nj], a[mi][0],a[mi][1],a[mi][2],a[mi][3],
                            b[nj][0], b[nj][1]);
        }
        if (nxt) {
            sts(cur ^ 1);
            __syncthreads();
            cur ^= 1;
        }
    }

    #pragma unroll
    for (int mi = 0; mi < 2; mi++) {
        #pragma unroll
        for (int nj = 0; nj < 4; nj++) {
            float* d = acc[mi*4+nj];
            int r0 = blockIdx.y*64 + wr*32 + mi*16 + g;
            int col = blockIdx.x*128 + wc*32 + nj*8 + tg*2;
            float2 v0 = make_float2(d[0], d[1]);
            float2 v1 = make_float2(d[2], d[3]);
            float2* p0 = reinterpret_cast<float2*>(C + (long)r0*N + col);
            float2* p1 = reinterpret_cast<float2*>(C + (long)(r0+8)*N + col);
            if (ACC) { float2 o0 = *p0, o1 = *p1; v0.x+=o0.x; v0.y+=o0.y; v1.x+=o1.x; v1.y+=o1.y; }
            if (RELU) { v0.x=fmaxf(v0.x,0.f); v0.y=fmaxf(v0.y,0.f); v1.x=fmaxf(v1.x,0.f); v1.y=fmaxf(v1.y,0.f); }
            *p0 = v0; *p1 = v1;
        }
    }
}

// ---------------------------------------------------------------------
// attn_fused (fp16 MMA) — unchanged from R6 (proven).
// ---------------------------------------------------------------------
#define QP 36
#define KP 36
#define VBP 68
#define PP 132

template<int MASK, bool CTX>
__global__ __launch_bounds__(256) void attn_fused(
    const float* __restrict__ Q, const float* __restrict__ Km,
    const float* __restrict__ Vm, float* __restrict__ P,
    float* __restrict__ Cctx,
    int Kdim, int lda, int ldb,
    long strA, long offHA, long strB, long offHB,
    int Hh, float scale, const int* __restrict__ tok, int tokStride)
{
    extern __shared__ unsigned sma[];
    unsigned* Qs = sma;
    unsigned* Ks = sma + 64*QP;
    unsigned* Vs = sma + 64*QP + 256*KP;
    unsigned* Ps = sma;
    __shared__ float red[64*4];

    const int tid = threadIdx.x, warp = tid >> 5, lane = tid & 31;
    const int g = lane >> 2, tg = lane & 3;
    const int wr = warp >> 2, wc = warp & 3;
    const int z = blockIdx.y;
    const int bb = z / Hh, hh = z - bb*Hh;
    const int rowTile = blockIdx.x;
    const int rowBase = rowTile * 64;

    const float* Qb = Q + (long)bb*strA + (long)hh*offHA + (long)rowBase*lda;
    const float* Kb = Km + (long)bb*strB + (long)hh*offHB;

    float acc[16][4];
    #pragma unroll
    for (int i = 0; i < 16; i++) { acc[i][0]=0.f; acc[i][1]=0.f; acc[i][2]=0.f; acc[i][3]=0.f; }

    for (int k0 = 0; k0 < Kdim; k0 += 64) {
        #pragma unroll
        for (int p = 0; p < 4; p++) {
            int idx = tid + p*256;
            int r = idx >> 4, c4 = idx & 15;
            float4 v = *reinterpret_cast<const float4*>(Qb + (long)r*lda + k0 + c4*4);
            uint2 w; w.x = pack_h2(v.x, v.y); w.y = pack_h2(v.z, v.w);
            *reinterpret_cast<uint2*>(&Qs[r*QP + c4*2]) = w;
        }
        #pragma unroll
        for (int p = 0; p < 16; p++) {
            int idx = tid + p*256;
            int r = idx >> 4, c4 = idx & 15;
            float4 v = *reinterpret_cast<const float4*>(Kb + (long)r*ldb + k0 + c4*4);
            uint2 w; w.x = pack_h2(v.x, v.y); w.y = pack_h2(v.z, v.w);
            *reinterpret_cast<uint2*>(&Ks[r*KP + c4*2]) = w;
        }
        if (CTX && k0 == 0) {
            const float* Vb = Vm + (long)bb*strB + (long)hh*offHB;
            #pragma unroll
            for (int p = 0; p < 8; p++) {
                int idx = tid + p*256;
                int r2 = idx >> 4, c4 = idx & 15;
                float4 v0 = *reinterpret_cast<const float4*>(Vb + (long)(2*r2  )*ldb + c4*4);
                float4 v1 = *reinterpret_cast<const float4*>(Vb + (long)(2*r2+1)*ldb + c4*4);
                uint4 w;
                w.x = pack_h2(v0.x, v1.x); w.y = pack_h2(v0.y, v1.y);
                w.z = pack_h2(v0.z, v1.z); w.w = pack_h2(v0.w, v1.w);
                *reinterpret_cast<uint4*>(&Vs[r2*VBP + c4*4]) = w;
            }
        }
        __syncthreads();
        #pragma unroll
        for (int kt = 0; kt < 4; kt++) {
            unsigned a[2][4], b[8][2];
            #pragma unroll
            for (int mi = 0; mi < 2; mi++) {
                int mb = wr*32 + mi*16;
                a[mi][0] = Qs[(mb+g  )*QP + kt*8 + tg];
                a[mi][1] = Qs[(mb+g+8)*QP + kt*8 + tg];
                a[mi][2] = Qs[(mb+g  )*QP + kt*8 + tg + 4];
                a[mi][3] = Qs[(mb+g+8)*QP + kt*8 + tg + 4];
            }
            #pragma unroll
            for (int nj = 0; nj < 8; nj++) {
                int nb = wc*64 + nj*8;
                b[nj][0] = Ks[(nb+g)*KP + kt*8 + tg];
                b[nj][1] = Ks[(nb+g)*KP + kt*8 + tg + 4];
            }
            #pragma unroll
            for (int mi = 0; mi < 2; mi++)
                #pragma unroll
                for (int nj = 0; nj < 8; nj++)
                    mma_f16(acc[mi*8+nj], a[mi][0],a[mi][1],a[mi][2],a[mi][3],
                            b[nj][0], b[nj][1]);
        }
        if (k0 + 64 < Kdim) __syncthreads();
    }

    // ---- scale + mask ----
    #pragma unroll
    for (int mi = 0; mi < 2; mi++) {
        #pragma unroll
        for (int nj = 0; nj < 8; nj++) {
            float* d = acc[mi*8+nj];
            int col = wc*64 + nj*8 + tg*2;
            int lr0 = wr*32 + mi*16 + g;
            #pragma unroll
            for (int c = 0; c < 4; c++) {
                int gcol = col + (c & 1);
                int grow = rowBase + lr0 + ((c >> 1) * 8);
                float v = d[c] * scale;
                if (MASK == 1) {
                    if (tok[bb*tokStride + gcol] == 0 || gcol > grow) v = -1e9f;
                } else if (MASK == 2) {
                    if (tok[bb*tokStride + gcol] == 0) v = -1e9f;
                }
                d[c] = v;
            }
        }
    }

    // ---- softmax (fp32) ----
    float rmax[4];
    #pragma unroll
    for (int mi = 0; mi < 2; mi++) {
        float m0 = -1e30f, m1 = -1e30f;
        #pragma unroll
        for (int nj = 0; nj < 8; nj++) {
            float* d = acc[mi*8+nj];
            m0 = fmaxf(m0, fmaxf(d[0], d[1]));
            m1 = fmaxf(m1, fmaxf(d[2], d[3]));
        }
        rmax[mi*2+0] = m0; rmax[mi*2+1] = m1;
    }
    #pragma unroll
    for (int i = 0; i < 4; i++) {
        rmax[i] = fmaxf(rmax[i], __shfl_xor_sync(0xffffffffu, rmax[i], 1));
        rmax[i] = fmaxf(rmax[i], __shfl_xor_sync(0xffffffffu, rmax[i], 2));
    }
    if (tg == 0) {
        #pragma unroll
        for (int mi = 0; mi < 2; mi++) {
            red[(wr*32 + mi*16 + g    )*4 + wc] = rmax[mi*2+0];
            red[(wr*32 + mi*16 + g + 8)*4 + wc] = rmax[mi*2+1];
        }
    }
    __syncthreads();
    float fmax4[4];
    #pragma unroll
    for (int mi = 0; mi < 2; mi++) {
        int r0 = wr*32 + mi*16 + g, r1 = r0 + 8;
        fmax4[mi*2+0] = fmaxf(fmaxf(red[r0*4+0], red[r0*4+1]), fmaxf(red[r0*4+2], red[r0*4+3]));
        fmax4[mi*2+1] = fmaxf(fmaxf(red[r1*4+0], red[r1*4+1]), fmaxf(red[r1*4+2], red[r1*4+3]));
    }
    __syncthreads();

    float rsum[4] = {0.f, 0.f, 0.f, 0.f};
    #pragma unroll
    for (int mi = 0; mi < 2; mi++) {
        #pragma unroll
        for (int nj = 0; nj < 8; nj++) {
            float* d = acc[mi*8+nj];
            d[0] = __expf(d[0] - fmax4[mi*2+0]);
            d[1] = __expf(d[1] - fmax4[mi*2+0]);
            d[2] = __expf(d[2] - fmax4[mi*2+1]);
            d[3] = __expf(d[3] - fmax4[mi*2+1]);
            rsum[mi*2+0] += d[0] + d[1];
            rsum[mi*2+1] += d[2] + d[3];
        }
    }
    #pragma unroll
    for (int i = 0; i < 4; i++) {
        rsum[i] += __shfl_xor_sync(0xffffffffu, rsum[i], 1);
        rsum[i] += __shfl_xor_sync(0xffffffffu, rsum[i], 2);
    }
    if (tg == 0) {
        #pragma unroll
        for (int mi = 0; mi < 2; mi++) {
            red[(wr*32 + mi*16 + g    )*4 + wc] = rsum[mi*2+0];
            red[(wr*32 + mi*16 + g + 8)*4 + wc] = rsum[mi*2+1];
        }
    }
    __syncthreads();
    float rinv[4];
    #pragma unroll
    for (int mi = 0; mi < 2; mi++) {
        int r0 = wr*32 + mi*16 + g, r1 = r0 + 8;
        rinv[mi*2+0] = 1.f / (red[r0*4+0] + red[r0*4+1] + red[r0*4+2] + red[r0*4+3]);
        rinv[mi*2+1] = 1.f / (red[r1*4+0] + red[r1*4+1] + red[r1*4+2] + red[r1*4+3]);
    }

    float* Pb = P + (long)z * 65536L + (long)rowBase * 256;
    #pragma unroll
    for (int mi = 0; mi < 2; mi++) {
        #pragma unroll
        for (int nj = 0; nj < 8; nj++) {
            float* d = acc[mi*8+nj];
            int col = wc*64 + nj*8 + tg*2;
            int r0 = wr*32 + mi*16 + g;
            float p0 = d[0]*rinv[mi*2+0], p1 = d[1]*rinv[mi*2+0];
            float p2 = d[2]*rinv[mi*2+1], p3 = d[3]*rinv[mi*2+1];
            *reinterpret_cast<float2*>(Pb + (long)r0*256 + col) = make_float2(p0, p1);
            *reinterpret_cast<float2*>(Pb + (long)(r0+8)*256 + col) = make_float2(p2, p3);
            if (CTX) {
                int k2 = wc*32 + nj*4 + tg;
                Ps[r0*PP + k2]     = pack_h2(p0, p1);
                Ps[(r0+8)*PP + k2] = pack_h2(p2, p3);
            }
        }
    }

    if (CTX) {
        __syncthreads();
        float acc2[4][4];
        #pragma unroll
        for (int i = 0; i < 4; i++) { acc2[i][0]=0.f; acc2[i][1]=0.f; acc2[i][2]=0.f; acc2[i][3]=0.f; }
        #pragma unroll
        for (int kt = 0; kt < 16; kt++) {
            unsigned a[2][4], b[2][2];
            #pragma unroll
            for (int mi = 0; mi < 2; mi++) {
                int mb = wr*32 + mi*16;
                a[mi][0] = Ps[(mb+g  )*PP + kt*8 + tg];
                a[mi][1] = Ps[(mb+g+8)*PP + kt*8 + tg];
                a[mi][2] = Ps[(mb+g  )*PP + kt*8 + tg + 4];
                a[mi][3] = Ps[(mb+g+8)*PP + kt*8 + tg + 4];
            }
            #pragma unroll
            for (int nj = 0; nj < 2; nj++) {
                int nb = wc*16 + nj*8 + g;
                b[nj][0] = Vs[(kt*8 + tg    )*VBP + nb];
                b[nj][1] = Vs[(kt*8 + tg + 4)*VBP + nb];
            }
            #pragma unroll
            for (int mi = 0; mi < 2; mi++)
                #pragma unroll
                for (int nj = 0; nj < 2; nj++)
                    mma_f16(acc2[mi*2+nj], a[mi][0],a[mi][1],a[mi][2],a[mi][3],
                            b[nj][0], b[nj][1]);
        }
        float* Cb = Cctx + (long)bb*TT*DD + hh*64;
        #pragma unroll
        for (int mi = 0; mi < 2; mi++) {
            #pragma unroll
            for (int nj = 0; nj < 2; nj++) {
                float* d = acc2[mi*2+nj];
                int r0 = rowBase + wr*32 + mi*16 + g;
                int col = wc*16 + nj*8 + tg*2;
                *reinterpret_cast<float2*>(Cb + (long)r0*DD + col) = make_float2(d[0], d[1]);
                *reinterpret_cast<float2*>(Cb + (long)(r0+8)*DD + col) = make_float2(d[2], d[3]);
            }
        }
    }
}

// ---------------------------------------------------------------------
// bgemm_tf32 (preamble) — unchanged.
// ---------------------------------------------------------------------
template<bool ROWBIAS>
__global__ __launch_bounds__(256) void bgemm_tf32(
    const float* __restrict__ A, const float* __restrict__ B,
    float* __restrict__ C, int M, int N, int K,
    int lda, int ldb, int ldc,
    long strA, long offHA, long strB, long offHB, long strC, long offHC,
    int Hh, const float* __restrict__ bias)
{
    __shared__ unsigned As[128*36];
    __shared__ unsigned Bs[32*72];
    const int tid = threadIdx.x, warp = tid >> 5, lane = tid & 31;
    const int g = lane >> 2, tg = lane & 3;
    const int wr = warp >> 1, wc = warp & 1;
    const int z = blockIdx.z;
    const int bb = z / Hh, hh = z - bb*Hh;

    const float* Ab = A + (long)bb*strA + (long)hh*offHA + (long)blockIdx.y*128*lda;
    const float* Bb = B + (long)bb*strB + (long)hh*offHB + (long)blockIdx.x*64;

    float acc[8][4];
    #pragma unroll
    for (int i = 0; i < 8; i++) { acc[i][0]=0.f; acc[i][1]=0.f; acc[i][2]=0.f; acc[i][3]=0.f; }

    for (int k0 = 0; k0 < K; k0 += 32) {
        if (k0 + 32 <= K && (lda & 3) == 0) {
            #pragma unroll
            for (int p = 0; p < 4; p++) {
                int idx = tid + p*256;
                int r = idx >> 3, c4 = idx & 7;
                float4 v = *reinterpret_cast<const float4*>(Ab + (long)r*lda + k0 + c4*4);
                unsigned* d = &As[r*36 + c4*4];
                d[0]=f2tf(v.x); d[1]=f2tf(v.y); d[2]=f2tf(v.z); d[3]=f2tf(v.w);
            }
        } else {
            #pragma unroll
            for (int p = 0; p < 16; p++) {
                int idx = tid + p*256;
                int r = idx >> 5, c = idx & 31;
                float v = (k0 + c < K) ? Ab[(long)r*lda + k0 + c] : 0.f;
                As[r*36 + c] = f2tf(v);
            }
        }
        #pragma unroll
        for (int p = 0; p < 2; p++) {
            int idx = tid + p*256;
            int r = idx >> 4, c4 = idx & 15;
            float4 v;
            if (k0 + r < K)
                v = *reinterpret_cast<const float4*>(Bb + (long)(k0 + r)*ldb + c4*4);
            else
                v = make_float4(0.f, 0.f, 0.f, 0.f);
            unsigned* d = &Bs[r*72 + c4*4];
            d[0]=f2tf(v.x); d[1]=f2tf(v.y); d[2]=f2tf(v.z); d[3]=f2tf(v.w);
        }
        __syncthreads();
        #pragma unroll
        for (int ks = 0; ks < 4; ks++) {
            const int kk = ks * 8;
            unsigned a[2][4], b[4][2];
            #pragma unroll
            for (int mi = 0; mi < 2; mi++) {
                int mb = wr*32 + mi*16;
                a[mi][0] = As[(mb+g  )*36 + kk + tg];
                a[mi][1] = As[(mb+g+8)*36 + kk + tg];
                a[mi][2] = As[(mb+g  )*36 + kk + tg + 4];
                a[mi][3] = As[(mb+g+8)*36 + kk + tg + 4];
            }
            #pragma unroll
            for (int nj = 0; nj < 4; nj++) {
                int nb = wc*32 + nj*8;
                b[nj][0] = Bs[(kk+tg  )*72 + nb + g];
                b[nj][1] = Bs[(kk+tg+4)*72 + nb + g];
            }
            #pragma unroll
            for (int mi = 0; mi < 2; mi++)
                #pragma unroll
                for (int nj = 0; nj < 4; nj++)
                    mma_tf32(acc[mi*4+nj], a[mi][0],a[mi][1],a[mi][2],a[mi][3],
                             b[nj][0], b[nj][1]);
        }
        __syncthreads();
    }

    float* Cb = C + (long)bb*strC + (long)hh*offHC;
    #pragma unroll
    for (int mi = 0; mi < 2; mi++) {
        #pragma unroll
        for (int nj = 0; nj < 4; nj++) {
            float* d = acc[mi*4+nj];
            int r0 = blockIdx.y*128 + wr*32 + mi*16 + g;
            int col = blockIdx.x*64 + wc*32 + nj*8 + tg*2;
            float b0 = ROWBIAS ? bias[r0] : 0.f;
            float b1 = ROWBIAS ? bias[r0+8] : 0.f;
            *reinterpret_cast<float2*>(Cb + (long)r0*ldc + col) =
                make_float2(d[0]+b0, d[1]+b0);
            *reinterpret_cast<float2*>(Cb + (long)(r0+8)*ldc + col) =
                make_float2(d[2]+b1, d[3]+b1);
        }
    }
}

// ---------------------------------------------------------------------
__global__ __launch_bounds__(256) void add_ln(
    const float* __restrict__ a, const float* __restrict__ b,
    float* __restrict__ out, const float* __restrict__ g,
    const float* __restrict__ beta)
{
    long off = (long)blockIdx.x * DD;
    int t = threadIdx.x;
    int warp = t >> 5, lane = t & 31;
    float v0 = a[off + t] + b[off + t];
    float v1 = a[off + t + 256] + b[off + t + 256];
    __shared__ float ws[8], ws2[8];

    float s = v0 + v1;
    #pragma unroll
    for (int o = 16; o > 0; o >>= 1) s += __shfl_xor_sync(0xffffffffu, s, o);
    if (lane == 0) ws[warp] = s;
    __syncthreads();
    float mu = (ws[0]+ws[1]+ws[2]+ws[3]+ws[4]+ws[5]+ws[6]+ws[7]) * (1.f/DD);

    float d0 = v0 - mu, d1 = v1 - mu;
    float q = d0*d0 + d1*d1;
    #pragma unroll
    for (int o = 16; o > 0; o >>= 1) q += __shfl_xor_sync(0xffffffffu, q, o);
    if (lane == 0) ws2[warp] = q;
    __syncthreads();
    float rstd = rsqrtf((ws2[0]+ws2[1]+ws2[2]+ws2[3]+ws2[4]+ws2[5]+ws2[6]+ws2[7]) * (1.f/DD) + 1e-5f);

    float g0 = g ? g[t] : 1.f,       g1 = g ? g[t+256] : 1.f;
    float b0 = beta ? beta[t] : 0.f, b1 = beta ? beta[t+256] : 0.f;
    out[off + t]       = d0 * rstd * g0 + b0;
    out[off + t + 256] = d1 * rstd * g1 + b1;
}

__global__ void embed_pe(const int* __restrict__ dec,
                         const float* __restrict__ emb,
                         float* __restrict__ x)
{
    long idx = (long)blockIdx.x * blockDim.x + threadIdx.x;
    if (idx >= (long)BT*DD) return;
    int d  = (int)(idx % DD);
    long bt = idx / DD;
    int t  = (int)(bt % TT);
    int tokidx = dec[bt];
    int d2 = d & ~1;
    float div = expf(-logf(10000.f) * (float)d2 / (float)DD);
    float ang = (float)t * div;
    float pe = (d & 1) ? cosf(ang) : sinf(ang);
    x[idx] = emb[(long)tokidx*DD + d] + pe;
}

__global__ void add3(const float* __restrict__ a, const float* __restrict__ bias,
                     const float* __restrict__ c, float* __restrict__ out, long n)
{
    long i = (long)blockIdx.x * blockDim.x + threadIdx.x;
    if (i >= n) return;
    out[i] = a[i] + bias[i % DD] + c[i];
}

__global__ void copyk(const float* __restrict__ src, float* __restrict__ dst, long n)
{
    long i = (long)blockIdx.x * blockDim.x + threadIdx.x;
    if (i < n) dst[i] = src[i];
}

// ---------------------------------------------------------------------
extern "C" void kernel_launch(void* const* d_in, const int* in_sizes, int n_in,
                              void* d_out, int out_size)
{
    const int*   dec     = (const int*)  d_in[0];
    const int*   enc     = (const int*)  d_in[1];
    const float* enc_out = (const float*)d_in[2];
    const float* ast_out = (const float*)d_in[3];
    const float* src_emb = (const float*)d_in[4];
    const float* ast_emb = (const float*)d_in[5];
    const float* emb     = (const float*)d_in[7];
    const float* attn_W  = (const float*)d_in[8];
    const float* ln_g    = (const float*)d_in[9];
    const float* ln_b    = (const float*)d_in[10];
    const float* W1      = (const float*)d_in[11];
    const float* W2      = (const float*)d_in[12];
    const float* conv_w  = (const float*)d_in[13];
    const float* conv_b  = (const float*)d_in[14];
    const float* mffnW   = (const float*)d_in[15];
    const float* mffnb   = (const float*)d_in[16];
    float* out = (float*)d_out;

    float *x,*t,*qkv,*c,*h,*multi,*ast1,*aste,*mm,*mmctx;
    cudaGetSymbolAddress((void**)&x,     g_x);
    cudaGetSymbolAddress((void**)&t,     g_t);
    cudaGetSymbolAddress((void**)&qkv,   g_qkv);
    cudaGetSymbolAddress((void**)&c,     g_c);
    cudaGetSymbolAddress((void**)&h,     g_h);
    cudaGetSymbolAddress((void**)&multi, g_multi);
    cudaGetSymbolAddress((void**)&ast1,  g_ast1);
    cudaGetSymbolAddress((void**)&aste,  g_aste);
    cudaGetSymbolAddress((void**)&mm,    g_mm);
    cudaGetSymbolAddress((void**)&mmctx, g_mmctx);

    const int GM_SMEM  = 2*BUFW*4;                              // 27648
    const int AT_SMEM  = (64*QP + 256*KP + 128*VBP)*4;          // 80896 (CTX)
    const int MM_SMEM  = (64*QP + 256*KP)*4;                    // 46080 (no CTX)
    cudaFuncSetAttribute(gemm2<false,false>, cudaFuncAttributeMaxDynamicSharedMemorySize, GM_SMEM);
    cudaFuncSetAttribute(gemm2<false,true >, cudaFuncAttributeMaxDynamicSharedMemorySize, GM_SMEM);
    cudaFuncSetAttribute(gemm2<true ,false>, cudaFuncAttributeMaxDynamicSharedMemorySize, GM_SMEM);
    cudaFuncSetAttribute(attn_fused<0,false>, cudaFuncAttributeMaxDynamicSharedMemorySize, MM_SMEM);
    cudaFuncSetAttribute(attn_fused<0,true >, cudaFuncAttributeMaxDynamicSharedMemorySize, AT_SMEM);
    cudaFuncSetAttribute(attn_fused<1,true >, cudaFuncAttributeMaxDynamicSharedMemorySize, AT_SMEM);
    cudaFuncSetAttribute(attn_fused<2,true >, cudaFuncAttributeMaxDynamicSharedMemorySize, AT_SMEM);

    float* q = qkv;
    float* k = qkv + (long)BT*DD;
    float* v = qkv + 2L*BT*DD;

    // ---------------- multi_model preamble ----------------
    {
        dim3 grid(DD/64, SS/128, BB);
        bgemm_tf32<true><<<grid, 256>>>(conv_w, ast_out, ast1,
            SS, DD, NA, NA, DD, DD,
            0L, 0L, (long)NA*DD, 0L, (long)SS*DD, 0L, 1, conv_b);
        bgemm_tf32<true><<<grid, 256>>>(conv_w, ast_emb, aste,
            SS, DD, NA, NA, DD, DD,
            0L, 0L, (long)NA*DD, 0L, (long)SS*DD, 0L, 1, conv_b);
    }
    {
        dim3 gs(SS/64, BB);
        attn_fused<0,false><<<gs, 256, MM_SMEM>>>(ast1, enc_out, nullptr, mm, nullptr,
            DD, DD, DD, (long)SS*DD, 0L, (long)SS*DD, 0L,
            1, 0.125f, nullptr, 0);
        dim3 grid2(DD/64, SS/128, BB);
        bgemm_tf32<false><<<grid2, 256>>>(mm, enc_out, mmctx,
            SS, DD, SS, SS, DD, DD,
            (long)SS*SS, 0L, (long)SS*DD, 0L, (long)SS*DD, 0L, 1, nullptr);
    }
    {
        dim3 grid(DD/128, BT/64, 1);
        gemm2<false,false><<<grid, 256, GM_SMEM>>>(src_emb, src_emb, src_emb,
            mffnW, 0L, t, 0L, BT, DD, DD);
        gemm2<false,true ><<<grid, 256, GM_SMEM>>>(aste, aste, aste,
            mffnW + DD*DD, 0L, t, 0L, BT, DD, DD);
        long n = (long)BB*SS*DD;
        add3<<<(int)((n + 255)/256), 256>>>(t, mffnb, mmctx, multi, n);
    }
    embed_pe<<<(BT*DD + 255)/256, 256>>>(dec, emb, x);

    // ---------------- decoder layers ----------------
    dim3 gQKV(DD/128, BT/64, 3);
    dim3 gProj(DD/128, BT/64, 1);
    dim3 gF1(DFF/128, BT/64, 1);
    dim3 gScore(TT/64, BB*HH);

    for (int l = 0; l < LL; l++) {
        for (int a = 0; a < 3; a++) {
            const float* W = attn_W + ((long)(l*3 + a) * 4) * DD * DD;
            const float* Wo = W + 3L*DD*DD;
            const float* xk = (a == 0) ? x : (a == 1 ? enc_out : multi);

            gemm2<false,false><<<gQKV, 256, GM_SMEM>>>(x, xk, xk,
                W, (long)DD*DD, qkv, (long)BT*DD, BT, DD, DD);

            long attnBase = (a == 0 ? SELF_OFF : (a == 1 ? ENC_OFF : AST_OFF))
                            + (long)l * BHTT;
            float* P = out + attnBase;

            if (a == 0)
                attn_fused<1,true><<<gScore, 256, AT_SMEM>>>(q, k, v, P, c,
                    DKK, DD, DD, (long)TT*DD, 64L, (long)TT*DD, 64L,
                    HH, 0.125f, dec, TT);
            else if (a == 1)
                attn_fused<2,true><<<gScore, 256, AT_SMEM>>>(q, k, v, P, c,
                    DKK, DD, DD, (long)TT*DD, 64L, (long)TT*DD, 64L,
                    HH, 0.125f, enc, SS);
            else
                attn_fused<0,true><<<gScore, 256, AT_SMEM>>>(q, k, v, P, c,
                    DKK, DD, DD, (long)TT*DD, 64L, (long)TT*DD, 64L,
                    HH, 0.125f, nullptr, 0);

            gemm2<false,false><<<gProj, 256, GM_SMEM>>>(c, c, c,
                Wo, 0L, t, 0L, BT, DD, DD);
            add_ln<<<BT, 256>>>(t, x, x,
                ln_g + (long)(l*3 + a)*DD, ln_b + (long)(l*3 + a)*DD);
        }
        gemm2<true ,false><<<gF1, 256, GM_SMEM>>>(x, x, x,
            W1 + (long)l*DD*DFF, 0L, h, 0L, BT, DFF, DD);
        gemm2<false,false><<<gProj, 256, GM_SMEM>>>(h, h, h,
            W2 + (long)l*DFF*DD, 0L, t, 0L, BT, DD, DFF);
        add_ln<<<BT, 256>>>(t, x, x, nullptr, nullptr);
    }

    copyk<<<(BT*DD + 255)/256, 256>>>(x, out, (long)BT*DD);
}

// round 9
// speedup vs baseline: 1.1485x; 1.0123x over previous
#include <cuda_runtime.h>
#include <cuda_fp16.h>
#include <math.h>

// Problem dims
#define BB 16
#define TT 256
#define SS 256
#define NA 300
#define DD 512
#define HH 8
#define DKK 64
#define DFF 2048
#define LL 6

#define BT (BB*TT)                 // 4096
#define BHTT ((long)BB*HH*TT*TT)   // 8388608

// d_out layout (floats): x | self_attns | enc_attns | ast_attns
#define SELF_OFF 2097152L
#define ENC_OFF  (SELF_OFF + (long)LL*BHTT)
#define AST_OFF  (ENC_OFF  + (long)LL*BHTT)

// ------------- scratch -------------
__device__ float g_x[BT*DD];
__device__ float g_t[BT*DD];
__device__ float g_qkv[3*BT*DD];
__device__ float g_c[BT*DD];
__device__ float g_h[BT*DFF];
__device__ float g_multi[BB*SS*DD];
__device__ float g_ast1[BB*SS*DD];
__device__ float g_aste[BB*SS*DD];
__device__ float g_mm[BB*SS*SS];
__device__ float g_mmctx[BB*SS*DD];

// ------------- helpers -------------
__device__ __forceinline__ unsigned f2tf(float x) {
    unsigned u; asm("cvt.rna.tf32.f32 %0, %1;" : "=r"(u) : "f"(x)); return u;
}
__device__ __forceinline__ void mma_tf32(float* d,
    unsigned a0, unsigned a1, unsigned a2, unsigned a3,
    unsigned b0, unsigned b1)
{
    asm volatile(
        "mma.sync.aligned.m16n8k8.row.col.f32.tf32.tf32.f32 "
        "{%0,%1,%2,%3},{%4,%5,%6,%7},{%8,%9},{%0,%1,%2,%3};\n"
        : "+f"(d[0]), "+f"(d[1]), "+f"(d[2]), "+f"(d[3])
        : "r"(a0), "r"(a1), "r"(a2), "r"(a3), "r"(b0), "r"(b1));
}
__device__ __forceinline__ unsigned pack_h2(float x, float y) {
    __half2 h = __floats2half2_rn(x, y);
    return *reinterpret_cast<unsigned*>(&h);
}
__device__ __forceinline__ void mma_f16(float* d,
    unsigned a0, unsigned a1, unsigned a2, unsigned a3,
    unsigned b0, unsigned b1)
{
    asm volatile(
        "mma.sync.aligned.m16n8k16.row.col.f32.f16.f16.f32 "
        "{%0,%1,%2,%3},{%4,%5,%6,%7},{%8,%9},{%0,%1,%2,%3};\n"
        : "+f"(d[0]), "+f"(d[1]), "+f"(d[2]), "+f"(d[3])
        : "r"(a0), "r"(a1), "r"(a2), "r"(a3), "r"(b0), "r"(b1));
}
__device__ __forceinline__ void ldsm_x4(unsigned& r0, unsigned& r1,
                                        unsigned& r2, unsigned& r3, unsigned addr)
{
    asm volatile("ldmatrix.sync.aligned.m8n8.x4.shared.b16 {%0,%1,%2,%3}, [%4];"
        : "=r"(r0), "=r"(r1), "=r"(r2), "=r"(r3) : "r"(addr));
}
__device__ __forceinline__ void ldsm_x4_t(unsigned& r0, unsigned& r1,
                                          unsigned& r2, unsigned& r3, unsigned addr)
{
    asm volatile("ldmatrix.sync.aligned.m8n8.x4.trans.shared.b16 {%0,%1,%2,%3}, [%4];"
        : "=r"(r0), "=r"(r1), "=r"(r2), "=r"(r3) : "r"(addr));
}

// ---------------------------------------------------------------------
// gemm2 (fp16 MMA, fp32 accum): C[M,N] = A[M,K] @ B[K,N], row-major.
// 64x128x32 tiles, double-buffered, 256 threads (warps 2x4, warp 32x32).
// A fragments via ldmatrix.x4 on half2 V[m][k2] (pad 20).
// B fragments via ldmatrix.x4.trans on plain half Wh[k][n] (rows of 128
// halves padded to 68 words -> 4-bank row stride, conflict-free).
// dyn smem = 2*(64*20 + 32*68)*4 = 27648 B (unchanged).
// ---------------------------------------------------------------------
#define VP 20
#define WPB 68
#define BUFW (64*VP + 32*WPB)   // 3456 words

template<bool RELU, bool ACC>
__global__ __launch_bounds__(256, 2) void gemm2(
    const float* __restrict__ A0, const float* __restrict__ A1,
    const float* __restrict__ A2,
    const float* __restrict__ B0, long strB,
    float* __restrict__ C0, long strC,
    int M, int N, int K)
{
    extern __shared__ unsigned smg[];

    const int tid = threadIdx.x, warp = tid >> 5, lane = tid & 31;
    const int g = lane >> 2, tg = lane & 3;
    const int wr = warp >> 2, wc = warp & 3;     // wr 0..1 (32 rows), wc 0..3 (32 cols)
    const int z = blockIdx.z;

    const float* A = (z == 0) ? A0 : (z == 1 ? A1 : A2);
    const float* At = A + (long)blockIdx.y * 64 * K;
    const float* Bt = B0 + (long)z * strB + blockIdx.x * 128;
    float* C = C0 + (long)z * strC;

    const int aR = tid >> 3;
    const int aC = (tid & 7) * 4;
    const int kp = tid >> 5;
    const int bC = (tid & 31) * 4;
    const int bw = (tid & 31) * 2;    // word offset within half row

    // A ldmatrix lane address
    const int laneRow = (lane & 7) + ((lane >> 3) & 1) * 8;
    const int laneSeg = (lane >> 4) * 4;
    const unsigned vbase = (unsigned)__cvta_generic_to_shared(smg);
    const unsigned aLane = vbase + ((wr*32 + laneRow)*VP + laneSeg) * 4;

    // B trans-ldmatrix lane address: lanes 0-15 -> rows k 0..15 (matrices 0,1
    // = nj even), lanes 16-31 -> same rows, nj odd (+4 words).
    const int kRow = lane & 15;
    const int nSel = lane >> 4;
    const unsigned bLane = vbase + (64*VP + kRow*WPB + wc*16 + nSel*4) * 4;

    float4 ra[2], rb[4];
    #pragma unroll
    for (int p = 0; p < 2; p++)
        ra[p] = *reinterpret_cast<const float4*>(At + (long)(aR + p*32)*K + aC);
    rb[0] = *reinterpret_cast<const float4*>(Bt + (long)(2*kp     )*N + bC);
    rb[1] = *reinterpret_cast<const float4*>(Bt + (long)(2*kp + 1 )*N + bC);
    rb[2] = *reinterpret_cast<const float4*>(Bt + (long)(2*kp + 16)*N + bC);
    rb[3] = *reinterpret_cast<const float4*>(Bt + (long)(2*kp + 17)*N + bC);

    auto sts = [&](int buf) {
        unsigned* V = smg + buf*BUFW;
        unsigned* W = V + 64*VP;
        #pragma unroll
        for (int p = 0; p < 2; p++) {
            int m = aR + p*32;
            uint2 w;
            w.x = pack_h2(ra[p].x, ra[p].y);
            w.y = pack_h2(ra[p].z, ra[p].w);
            *reinterpret_cast<uint2*>(&V[m*VP + (aC >> 1)]) = w;
        }
        {
            uint2 w;
            w.x = pack_h2(rb[0].x, rb[0].y); w.y = pack_h2(rb[0].z, rb[0].w);
            *reinterpret_cast<uint2*>(&W[(2*kp     )*WPB + bw]) = w;
            w.x = pack_h2(rb[1].x, rb[1].y); w.y = pack_h2(rb[1].z, rb[1].w);
            *reinterpret_cast<uint2*>(&W[(2*kp + 1 )*WPB + bw]) = w;
            w.x = pack_h2(rb[2].x, rb[2].y); w.y = pack_h2(rb[2].z, rb[2].w);
            *reinterpret_cast<uint2*>(&W[(2*kp + 16)*WPB + bw]) = w;
            w.x = pack_h2(rb[3].x, rb[3].y); w.y = pack_h2(rb[3].z, rb[3].w);
            *reinterpret_cast<uint2*>(&W[(2*kp + 17)*WPB + bw]) = w;
        }
    };
    sts(0);
    __syncthreads();

    float acc[8][4];
    #pragma unroll
    for (int i = 0; i < 8; i++) { acc[i][0]=0.f; acc[i][1]=0.f; acc[i][2]=0.f; acc[i][3]=0.f; }

    int cur = 0;
    for (int k0 = 0; k0 < K; k0 += 32) {
        const bool nxt = (k0 + 32) < K;
        if (nxt) {
            #pragma unroll
            for (int p = 0; p < 2; p++)
                ra[p] = *reinterpret_cast<const float4*>(At + (long)(aR + p*32)*K + k0 + 32 + aC);
            rb[0] = *reinterpret_cast<const float4*>(Bt + (long)(k0 + 32 + 2*kp     )*N + bC);
            rb[1] = *reinterpret_cast<const float4*>(Bt + (long)(k0 + 32 + 2*kp + 1 )*N + bC);
            rb[2] = *reinterpret_cast<const float4*>(Bt + (long)(k0 + 32 + 2*kp + 16)*N + bC);
            rb[3] = *reinterpret_cast<const float4*>(Bt + (long)(k0 + 32 + 2*kp + 17)*N + bC);
        }
        const unsigned aBuf = aLane + cur*BUFW*4;
        const unsigned bBuf = bLane + cur*BUFW*4;
        #pragma unroll
        for (int kt = 0; kt < 2; kt++) {
            unsigned a[2][4], b[4][2];
            #pragma unroll
            for (int mi = 0; mi < 2; mi++)
                ldsm_x4(a[mi][0], a[mi][1], a[mi][2], a[mi][3],
                        aBuf + mi*16*VP*4 + kt*32);
            {
                unsigned r0, r1, r2, r3;
                ldsm_x4_t(r0, r1, r2, r3, bBuf + kt*16*WPB*4);
                b[0][0]=r0; b[0][1]=r1; b[1][0]=r2; b[1][1]=r3;
                ldsm_x4_t(r0, r1, r2, r3, bBuf + kt*16*WPB*4 + 32);
                b[2][0]=r0; b[2][1]=r1; b[3][0]=r2; b[3][1]=r3;
            }
            #pragma unroll
            for (int mi = 0; mi < 2; mi++)
                #pragma unroll
                for (int nj = 0; nj < 4; nj++)
                    mma_f16(acc[mi*4+nj], a[mi][0],a[mi][1],a[mi][2],a[mi][3],
                            b[nj][0], b[nj][1]);
        }
        if (nxt) {
            sts(cur ^ 1);
            __syncthreads();
            cur ^= 1;
        }
    }

    #pragma unroll
    for (int mi = 0; mi < 2; mi++) {
        #pragma unroll
        for (int nj = 0; nj < 4; nj++) {
            float* d = acc[mi*4+nj];
            int r0 = blockIdx.y*64 + wr*32 + mi*16 + g;
            int col = blockIdx.x*128 + wc*32 + nj*8 + tg*2;
            float2 v0 = make_float2(d[0], d[1]);
            float2 v1 = make_float2(d[2], d[3]);
            float2* p0 = reinterpret_cast<float2*>(C + (long)r0*N + col);
            float2* p1 = reinterpret_cast<float2*>(C + (long)(r0+8)*N + col);
            if (ACC) { float2 o0 = *p0, o1 = *p1; v0.x+=o0.x; v0.y+=o0.y; v1.x+=o1.x; v1.y+=o1.y; }
            if (RELU) { v0.x=fmaxf(v0.x,0.f); v0.y=fmaxf(v0.y,0.f); v1.x=fmaxf(v1.x,0.f); v1.y=fmaxf(v1.y,0.f); }
            *p0 = v0; *p1 = v1;
        }
    }
}

// ---------------------------------------------------------------------
// attn_fused (fp16 MMA) — unchanged (proven).
// ---------------------------------------------------------------------
#define QP 36
#define KP 36
#define VBP 68
#define PP 132

template<int MASK, bool CTX>
__global__ __launch_bounds__(256) void attn_fused(
    const float* __restrict__ Q, const float* __restrict__ Km,
    const float* __restrict__ Vm, float* __restrict__ P,
    float* __restrict__ Cctx,
    int Kdim, int lda, int ldb,
    long strA, long offHA, long strB, long offHB,
    int Hh, float scale, const int* __restrict__ tok, int tokStride)
{
    extern __shared__ unsigned sma[];
    unsigned* Qs = sma;
    unsigned* Ks = sma + 64*QP;
    unsigned* Vs = sma + 64*QP + 256*KP;
    unsigned* Ps = sma;
    __shared__ float red[64*4];

    const int tid = threadIdx.x, warp = tid >> 5, lane = tid & 31;
    const int g = lane >> 2, tg = lane & 3;
    const int wr = warp >> 2, wc = warp & 3;
    const int z = blockIdx.y;
    const int bb = z / Hh, hh = z - bb*Hh;
    const int rowTile = blockIdx.x;
    const int rowBase = rowTile * 64;

    const float* Qb = Q + (long)bb*strA + (long)hh*offHA + (long)rowBase*lda;
    const float* Kb = Km + (long)bb*strB + (long)hh*offHB;

    float acc[16][4];
    #pragma unroll
    for (int i = 0; i < 16; i++) { acc[i][0]=0.f; acc[i][1]=0.f; acc[i][2]=0.f; acc[i][3]=0.f; }

    for (int k0 = 0; k0 < Kdim; k0 += 64) {
        #pragma unroll
        for (int p = 0; p < 4; p++) {
            int idx = tid + p*256;
            int r = idx >> 4, c4 = idx & 15;
            float4 v = *reinterpret_cast<const float4*>(Qb + (long)r*lda + k0 + c4*4);
            uint2 w; w.x = pack_h2(v.x, v.y); w.y = pack_h2(v.z, v.w);
            *reinterpret_cast<uint2*>(&Qs[r*QP + c4*2]) = w;
        }
        #pragma unroll
        for (int p = 0; p < 16; p++) {
            int idx = tid + p*256;
            int r = idx >> 4, c4 = idx & 15;
            float4 v = *reinterpret_cast<const float4*>(Kb + (long)r*ldb + k0 + c4*4);
            uint2 w; w.x = pack_h2(v.x, v.y); w.y = pack_h2(v.z, v.w);
            *reinterpret_cast<uint2*>(&Ks[r*KP + c4*2]) = w;
        }
        if (CTX && k0 == 0) {
            const float* Vb = Vm + (long)bb*strB + (long)hh*offHB;
            #pragma unroll
            for (int p = 0; p < 8; p++) {
                int idx = tid + p*256;
                int r2 = idx >> 4, c4 = idx & 15;
                float4 v0 = *reinterpret_cast<const float4*>(Vb + (long)(2*r2  )*ldb + c4*4);
                float4 v1 = *reinterpret_cast<const float4*>(Vb + (long)(2*r2+1)*ldb + c4*4);
                uint4 w;
                w.x = pack_h2(v0.x, v1.x); w.y = pack_h2(v0.y, v1.y);
                w.z = pack_h2(v0.z, v1.z); w.w = pack_h2(v0.w, v1.w);
                *reinterpret_cast<uint4*>(&Vs[r2*VBP + c4*4]) = w;
            }
        }
        __syncthreads();
        #pragma unroll
        for (int kt = 0; kt < 4; kt++) {
            unsigned a[2][4], b[8][2];
            #pragma unroll
            for (int mi = 0; mi < 2; mi++) {
                int mb = wr*32 + mi*16;
                a[mi][0] = Qs[(mb+g  )*QP + kt*8 + tg];
                a[mi][1] = Qs[(mb+g+8)*QP + kt*8 + tg];
                a[mi][2] = Qs[(mb+g  )*QP + kt*8 + tg + 4];
                a[mi][3] = Qs[(mb+g+8)*QP + kt*8 + tg + 4];
            }
            #pragma unroll
            for (int nj = 0; nj < 8; nj++) {
                int nb = wc*64 + nj*8;
                b[nj][0] = Ks[(nb+g)*KP + kt*8 + tg];
                b[nj][1] = Ks[(nb+g)*KP + kt*8 + tg + 4];
            }
            #pragma unroll
            for (int mi = 0; mi < 2; mi++)
                #pragma unroll
                for (int nj = 0; nj < 8; nj++)
                    mma_f16(acc[mi*8+nj], a[mi][0],a[mi][1],a[mi][2],a[mi][3],
                            b[nj][0], b[nj][1]);
        }
        if (k0 + 64 < Kdim) __syncthreads();
    }

    // ---- scale + mask ----
    #pragma unroll
    for (int mi = 0; mi < 2; mi++) {
        #pragma unroll
        for (int nj = 0; nj < 8; nj++) {
            float* d = acc[mi*8+nj];
            int col = wc*64 + nj*8 + tg*2;
            int lr0 = wr*32 + mi*16 + g;
            #pragma unroll
            for (int c = 0; c < 4; c++) {
                int gcol = col + (c & 1);
                int grow = rowBase + lr0 + ((c >> 1) * 8);
                float v = d[c] * scale;
                if (MASK == 1) {
                    if (tok[bb*tokStride + gcol] == 0 || gcol > grow) v = -1e9f;
                } else if (MASK == 2) {
                    if (tok[bb*tokStride + gcol] == 0) v = -1e9f;
                }
                d[c] = v;
            }
        }
    }

    // ---- softmax (fp32) ----
    float rmax[4];
    #pragma unroll
    for (int mi = 0; mi < 2; mi++) {
        float m0 = -1e30f, m1 = -1e30f;
        #pragma unroll
        for (int nj = 0; nj < 8; nj++) {
            float* d = acc[mi*8+nj];
            m0 = fmaxf(m0, fmaxf(d[0], d[1]));
            m1 = fmaxf(m1, fmaxf(d[2], d[3]));
        }
        rmax[mi*2+0] = m0; rmax[mi*2+1] = m1;
    }
    #pragma unroll
    for (int i = 0; i < 4; i++) {
        rmax[i] = fmaxf(rmax[i], __shfl_xor_sync(0xffffffffu, rmax[i], 1));
        rmax[i] = fmaxf(rmax[i], __shfl_xor_sync(0xffffffffu, rmax[i], 2));
    }
    if (tg == 0) {
        #pragma unroll
        for (int mi = 0; mi < 2; mi++) {
            red[(wr*32 + mi*16 + g    )*4 + wc] = rmax[mi*2+0];
            red[(wr*32 + mi*16 + g + 8)*4 + wc] = rmax[mi*2+1];
        }
    }
    __syncthreads();
    float fmax4[4];
    #pragma unroll
    for (int mi = 0; mi < 2; mi++) {
        int r0 = wr*32 + mi*16 + g, r1 = r0 + 8;
        fmax4[mi*2+0] = fmaxf(fmaxf(red[r0*4+0], red[r0*4+1]), fmaxf(red[r0*4+2], red[r0*4+3]));
        fmax4[mi*2+1] = fmaxf(fmaxf(red[r1*4+0], red[r1*4+1]), fmaxf(red[r1*4+2], red[r1*4+3]));
    }
    __syncthreads();

    float rsum[4] = {0.f, 0.f, 0.f, 0.f};
    #pragma unroll
    for (int mi = 0; mi < 2; mi++) {
        #pragma unroll
        for (int nj = 0; nj < 8; nj++) {
            float* d = acc[mi*8+nj];
            d[0] = __expf(d[0] - fmax4[mi*2+0]);
            d[1] = __expf(d[1] - fmax4[mi*2+0]);
            d[2] = __expf(d[2] - fmax4[mi*2+1]);
            d[3] = __expf(d[3] - fmax4[mi*2+1]);
            rsum[mi*2+0] += d[0] + d[1];
            rsum[mi*2+1] += d[2] + d[3];
        }
    }
    #pragma unroll
    for (int i = 0; i < 4; i++) {
        rsum[i] += __shfl_xor_sync(0xffffffffu, rsum[i], 1);
        rsum[i] += __shfl_xor_sync(0xffffffffu, rsum[i], 2);
    }
    if (tg == 0) {
        #pragma unroll
        for (int mi = 0; mi < 2; mi++) {
            red[(wr*32 + mi*16 + g    )*4 + wc] = rsum[mi*2+0];
            red[(wr*32 + mi*16 + g + 8)*4 + wc] = rsum[mi*2+1];
        }
    }
    __syncthreads();
    float rinv[4];
    #pragma unroll
    for (int mi = 0; mi < 2; mi++) {
        int r0 = wr*32 + mi*16 + g, r1 = r0 + 8;
        rinv[mi*2+0] = 1.f / (red[r0*4+0] + red[r0*4+1] + red[r0*4+2] + red[r0*4+3]);
        rinv[mi*2+1] = 1.f / (red[r1*4+0] + red[r1*4+1] + red[r1*4+2] + red[r1*4+3]);
    }

    float* Pb = P + (long)z * 65536L + (long)rowBase * 256;
    #pragma unroll
    for (int mi = 0; mi < 2; mi++) {
        #pragma unroll
        for (int nj = 0; nj < 8; nj++) {
            float* d = acc[mi*8+nj];
            int col = wc*64 + nj*8 + tg*2;
            int r0 = wr*32 + mi*16 + g;
            float p0 = d[0]*rinv[mi*2+0], p1 = d[1]*rinv[mi*2+0];
            float p2 = d[2]*rinv[mi*2+1], p3 = d[3]*rinv[mi*2+1];
            *reinterpret_cast<float2*>(Pb + (long)r0*256 + col) = make_float2(p0, p1);
            *reinterpret_cast<float2*>(Pb + (long)(r0+8)*256 + col) = make_float2(p2, p3);
            if (CTX) {
                int k2 = wc*32 + nj*4 + tg;
                Ps[r0*PP + k2]     = pack_h2(p0, p1);
                Ps[(r0+8)*PP + k2] = pack_h2(p2, p3);
            }
        }
    }

    if (CTX) {
        __syncthreads();
        float acc2[4][4];
        #pragma unroll
        for (int i = 0; i < 4; i++) { acc2[i][0]=0.f; acc2[i][1]=0.f; acc2[i][2]=0.f; acc2[i][3]=0.f; }
        #pragma unroll
        for (int kt = 0; kt < 16; kt++) {
            unsigned a[2][4], b[2][2];
            #pragma unroll
            for (int mi = 0; mi < 2; mi++) {
                int mb = wr*32 + mi*16;
                a[mi][0] = Ps[(mb+g  )*PP + kt*8 + tg];
                a[mi][1] = Ps[(mb+g+8)*PP + kt*8 + tg];
                a[mi][2] = Ps[(mb+g  )*PP + kt*8 + tg + 4];
                a[mi][3] = Ps[(mb+g+8)*PP + kt*8 + tg + 4];
            }
            #pragma unroll
            for (int nj = 0; nj < 2; nj++) {
                int nb = wc*16 + nj*8 + g;
                b[nj][0] = Vs[(kt*8 + tg    )*VBP + nb];
                b[nj][1] = Vs[(kt*8 + tg + 4)*VBP + nb];
            }
            #pragma unroll
            for (int mi = 0; mi < 2; mi++)
                #pragma unroll
                for (int nj = 0; nj < 2; nj++)
                    mma_f16(acc2[mi*2+nj], a[mi][0],a[mi][1],a[mi][2],a[mi][3],
                            b[nj][0], b[nj][1]);
        }
        float* Cb = Cctx + (long)bb*TT*DD + hh*64;
        #pragma unroll
        for (int mi = 0; mi < 2; mi++) {
            #pragma unroll
            for (int nj = 0; nj < 2; nj++) {
                float* d = acc2[mi*2+nj];
                int r0 = rowBase + wr*32 + mi*16 + g;
                int col = wc*16 + nj*8 + tg*2;
                *reinterpret_cast<float2*>(Cb + (long)r0*DD + col) = make_float2(d[0], d[1]);
                *reinterpret_cast<float2*>(Cb + (long)(r0+8)*DD + col) = make_float2(d[2], d[3]);
            }
        }
    }
}

// ---------------------------------------------------------------------
// bgemm_tf32 (preamble) — unchanged.
// ---------------------------------------------------------------------
template<bool ROWBIAS>
__global__ __launch_bounds__(256) void bgemm_tf32(
    const float* __restrict__ A, const float* __restrict__ B,
    float* __restrict__ C, int M, int N, int K,
    int lda, int ldb, int ldc,
    long strA, long offHA, long strB, long offHB, long strC, long offHC,
    int Hh, const float* __restrict__ bias)
{
    __shared__ unsigned As[128*36];
    __shared__ unsigned Bs[32*72];
    const int tid = threadIdx.x, warp = tid >> 5, lane = tid & 31;
    const int g = lane >> 2, tg = lane & 3;
    const int wr = warp >> 1, wc = warp & 1;
    const int z = blockIdx.z;
    const int bb = z / Hh, hh = z - bb*Hh;

    const float* Ab = A + (long)bb*strA + (long)hh*offHA + (long)blockIdx.y*128*lda;
    const float* Bb = B + (long)bb*strB + (long)hh*offHB + (long)blockIdx.x*64;

    float acc[8][4];
    #pragma unroll
    for (int i = 0; i < 8; i++) { acc[i][0]=0.f; acc[i][1]=0.f; acc[i][2]=0.f; acc[i][3]=0.f; }

    for (int k0 = 0; k0 < K; k0 += 32) {
        if (k0 + 32 <= K && (lda & 3) == 0) {
            #pragma unroll
            for (int p = 0; p < 4; p++) {
                int idx = tid + p*256;
                int r = idx >> 3, c4 = idx & 7;
                float4 v = *reinterpret_cast<const float4*>(Ab + (long)r*lda + k0 + c4*4);
                unsigned* d = &As[r*36 + c4*4];
                d[0]=f2tf(v.x); d[1]=f2tf(v.y); d[2]=f2tf(v.z); d[3]=f2tf(v.w);
            }
        } else {
            #pragma unroll
            for (int p = 0; p < 16; p++) {
                int idx = tid + p*256;
                int r = idx >> 5, c = idx & 31;
                float v = (k0 + c < K) ? Ab[(long)r*lda + k0 + c] : 0.f;
                As[r*36 + c] = f2tf(v);
            }
        }
        #pragma unroll
        for (int p = 0; p < 2; p++) {
            int idx = tid + p*256;
            int r = idx >> 4, c4 = idx & 15;
            float4 v;
            if (k0 + r < K)
                v = *reinterpret_cast<const float4*>(Bb + (long)(k0 + r)*ldb + c4*4);
            else
                v = make_float4(0.f, 0.f, 0.f, 0.f);
            unsigned* d = &Bs[r*72 + c4*4];
            d[0]=f2tf(v.x); d[1]=f2tf(v.y); d[2]=f2tf(v.z); d[3]=f2tf(v.w);
        }
        __syncthreads();
        #pragma unroll
        for (int ks = 0; ks < 4; ks++) {
            const int kk = ks * 8;
            unsigned a[2][4], b[4][2];
            #pragma unroll
            for (int mi = 0; mi < 2; mi++) {
                int mb = wr*32 + mi*16;
                a[mi][0] = As[(mb+g  )*36 + kk + tg];
                a[mi][1] = As[(mb+g+8)*36 + kk + tg];
                a[mi][2] = As[(mb+g  )*36 + kk + tg + 4];
                a[mi][3] = As[(mb+g+8)*36 + kk + tg + 4];
            }
            #pragma unroll
            for (int nj = 0; nj < 4; nj++) {
                int nb = wc*32 + nj*8;
                b[nj][0] = Bs[(kk+tg  )*72 + nb + g];
                b[nj][1] = Bs[(kk+tg+4)*72 + nb + g];
            }
            #pragma unroll
            for (int mi = 0; mi < 2; mi++)
                #pragma unroll
                for (int nj = 0; nj < 4; nj++)
                    mma_tf32(acc[mi*4+nj], a[mi][0],a[mi][1],a[mi][2],a[mi][3],
                             b[nj][0], b[nj][1]);
        }
        __syncthreads();
    }

    float* Cb = C + (long)bb*strC + (long)hh*offHC;
    #pragma unroll
    for (int mi = 0; mi < 2; mi++) {
        #pragma unroll
        for (int nj = 0; nj < 4; nj++) {
            float* d = acc[mi*4+nj];
            int r0 = blockIdx.y*128 + wr*32 + mi*16 + g;
            int col = blockIdx.x*64 + wc*32 + nj*8 + tg*2;
            float b0 = ROWBIAS ? bias[r0] : 0.f;
            float b1 = ROWBIAS ? bias[r0+8] : 0.f;
            *reinterpret_cast<float2*>(Cb + (long)r0*ldc + col) =
                make_float2(d[0]+b0, d[1]+b0);
            *reinterpret_cast<float2*>(Cb + (long)(r0+8)*ldc + col) =
                make_float2(d[2]+b1, d[3]+b1);
        }
    }
}

// ---------------------------------------------------------------------
__global__ __launch_bounds__(256) void add_ln(
    const float* __restrict__ a, const float* __restrict__ b,
    float* __restrict__ out, const float* __restrict__ g,
    const float* __restrict__ beta)
{
    long off = (long)blockIdx.x * DD;
    int t = threadIdx.x;
    int warp = t >> 5, lane = t & 31;
    float v0 = a[off + t] + b[off + t];
    float v1 = a[off + t + 256] + b[off + t + 256];
    __shared__ float ws[8], ws2[8];

    float s = v0 + v1;
    #pragma unroll
    for (int o = 16; o > 0; o >>= 1) s += __shfl_xor_sync(0xffffffffu, s, o);
    if (lane == 0) ws[warp] = s;
    __syncthreads();
    float mu = (ws[0]+ws[1]+ws[2]+ws[3]+ws[4]+ws[5]+ws[6]+ws[7]) * (1.f/DD);

    float d0 = v0 - mu, d1 = v1 - mu;
    float q = d0*d0 + d1*d1;
    #pragma unroll
    for (int o = 16; o > 0; o >>= 1) q += __shfl_xor_sync(0xffffffffu, q, o);
    if (lane == 0) ws2[warp] = q;
    __syncthreads();
    float rstd = rsqrtf((ws2[0]+ws2[1]+ws2[2]+ws2[3]+ws2[4]+ws2[5]+ws2[6]+ws2[7]) * (1.f/DD) + 1e-5f);

    float g0 = g ? g[t] : 1.f,       g1 = g ? g[t+256] : 1.f;
    float b0 = beta ? beta[t] : 0.f, b1 = beta ? beta[t+256] : 0.f;
    out[off + t]       = d0 * rstd * g0 + b0;
    out[off + t + 256] = d1 * rstd * g1 + b1;
}

__global__ void embed_pe(const int* __restrict__ dec,
                         const float* __restrict__ emb,
                         float* __restrict__ x)
{
    long idx = (long)blockIdx.x * blockDim.x + threadIdx.x;
    if (idx >= (long)BT*DD) return;
    int d  = (int)(idx % DD);
    long bt = idx / DD;
    int t  = (int)(bt % TT);
    int tokidx = dec[bt];
    int d2 = d & ~1;
    float div = expf(-logf(10000.f) * (float)d2 / (float)DD);
    float ang = (float)t * div;
    float pe = (d & 1) ? cosf(ang) : sinf(ang);
    x[idx] = emb[(long)tokidx*DD + d] + pe;
}

__global__ void add3(const float* __restrict__ a, const float* __restrict__ bias,
                     const float* __restrict__ c, float* __restrict__ out, long n)
{
    long i = (long)blockIdx.x * blockDim.x + threadIdx.x;
    if (i >= n) return;
    out[i] = a[i] + bias[i % DD] + c[i];
}

__global__ void copyk(const float* __restrict__ src, float* __restrict__ dst, long n)
{
    long i = (long)blockIdx.x * blockDim.x + threadIdx.x;
    if (i < n) dst[i] = src[i];
}

// ---------------------------------------------------------------------
extern "C" void kernel_launch(void* const* d_in, const int* in_sizes, int n_in,
                              void* d_out, int out_size)
{
    const int*   dec     = (const int*)  d_in[0];
    const int*   enc     = (const int*)  d_in[1];
    const float* enc_out = (const float*)d_in[2];
    const float* ast_out = (const float*)d_in[3];
    const float* src_emb = (const float*)d_in[4];
    const float* ast_emb = (const float*)d_in[5];
    const float* emb     = (const float*)d_in[7];
    const float* attn_W  = (const float*)d_in[8];
    const float* ln_g    = (const float*)d_in[9];
    const float* ln_b    = (const float*)d_in[10];
    const float* W1      = (const float*)d_in[11];
    const float* W2      = (const float*)d_in[12];
    const float* conv_w  = (const float*)d_in[13];
    const float* conv_b  = (const float*)d_in[14];
    const float* mffnW   = (const float*)d_in[15];
    const float* mffnb   = (const float*)d_in[16];
    float* out = (float*)d_out;

    float *x,*t,*qkv,*c,*h,*multi,*ast1,*aste,*mm,*mmctx;
    cudaGetSymbolAddress((void**)&x,     g_x);
    cudaGetSymbolAddress((void**)&t,     g_t);
    cudaGetSymbolAddress((void**)&qkv,   g_qkv);
    cudaGetSymbolAddress((void**)&c,     g_c);
    cudaGetSymbolAddress((void**)&h,     g_h);
    cudaGetSymbolAddress((void**)&multi, g_multi);
    cudaGetSymbolAddress((void**)&ast1,  g_ast1);
    cudaGetSymbolAddress((void**)&aste,  g_aste);
    cudaGetSymbolAddress((void**)&mm,    g_mm);
    cudaGetSymbolAddress((void**)&mmctx, g_mmctx);

    const int GM_SMEM  = 2*BUFW*4;                              // 27648
    const int AT_SMEM  = (64*QP + 256*KP + 128*VBP)*4;          // 80896 (CTX)
    const int MM_SMEM  = (64*QP + 256*KP)*4;                    // 46080 (no CTX)
    cudaFuncSetAttribute(gemm2<false,false>, cudaFuncAttributeMaxDynamicSharedMemorySize, GM_SMEM);
    cudaFuncSetAttribute(gemm2<false,true >, cudaFuncAttributeMaxDynamicSharedMemorySize, GM_SMEM);
    cudaFuncSetAttribute(gemm2<true ,false>, cudaFuncAttributeMaxDynamicSharedMemorySize, GM_SMEM);
    cudaFuncSetAttribute(attn_fused<0,false>, cudaFuncAttributeMaxDynamicSharedMemorySize, MM_SMEM);
    cudaFuncSetAttribute(attn_fused<0,true >, cudaFuncAttributeMaxDynamicSharedMemorySize, AT_SMEM);
    cudaFuncSetAttribute(attn_fused<1,true >, cudaFuncAttributeMaxDynamicSharedMemorySize, AT_SMEM);
    cudaFuncSetAttribute(attn_fused<2,true >, cudaFuncAttributeMaxDynamicSharedMemorySize, AT_SMEM);

    float* q = qkv;
    float* k = qkv + (long)BT*DD;
    float* v = qkv + 2L*BT*DD;

    // ---------------- multi_model preamble ----------------
    {
        dim3 grid(DD/64, SS/128, BB);
        bgemm_tf32<true><<<grid, 256>>>(conv_w, ast_out, ast1,
            SS, DD, NA, NA, DD, DD,
            0L, 0L, (long)NA*DD, 0L, (long)SS*DD, 0L, 1, conv_b);
        bgemm_tf32<true><<<grid, 256>>>(conv_w, ast_emb, aste,
            SS, DD, NA, NA, DD, DD,
            0L, 0L, (long)NA*DD, 0L, (long)SS*DD, 0L, 1, conv_b);
    }
    {
        dim3 gs(SS/64, BB);
        attn_fused<0,false><<<gs, 256, MM_SMEM>>>(ast1, enc_out, nullptr, mm, nullptr,
            DD, DD, DD, (long)SS*DD, 0L, (long)SS*DD, 0L,
            1, 0.125f, nullptr, 0);
        dim3 grid2(DD/64, SS/128, BB);
        bgemm_tf32<false><<<grid2, 256>>>(mm, enc_out, mmctx,
            SS, DD, SS, SS, DD, DD,
            (long)SS*SS, 0L, (long)SS*DD, 0L, (long)SS*DD, 0L, 1, nullptr);
    }
    {
        dim3 grid(DD/128, BT/64, 1);
        gemm2<false,false><<<grid, 256, GM_SMEM>>>(src_emb, src_emb, src_emb,
            mffnW, 0L, t, 0L, BT, DD, DD);
        gemm2<false,true ><<<grid, 256, GM_SMEM>>>(aste, aste, aste,
            mffnW + DD*DD, 0L, t, 0L, BT, DD, DD);
        long n = (long)BB*SS*DD;
        add3<<<(int)((n + 255)/256), 256>>>(t, mffnb, mmctx, multi, n);
    }
    embed_pe<<<(BT*DD + 255)/256, 256>>>(dec, emb, x);

    // ---------------- decoder layers ----------------
    dim3 gQKV(DD/128, BT/64, 3);
    dim3 gProj(DD/128, BT/64, 1);
    dim3 gF1(DFF/128, BT/64, 1);
    dim3 gScore(TT/64, BB*HH);

    for (int l = 0; l < LL; l++) {
        for (int a = 0; a < 3; a++) {
            const float* W = attn_W + ((long)(l*3 + a) * 4) * DD * DD;
            const float* Wo = W + 3L*DD*DD;
            const float* xk = (a == 0) ? x : (a == 1 ? enc_out : multi);

            gemm2<false,false><<<gQKV, 256, GM_SMEM>>>(x, xk, xk,
                W, (long)DD*DD, qkv, (long)BT*DD, BT, DD, DD);

            long attnBase = (a == 0 ? SELF_OFF : (a == 1 ? ENC_OFF : AST_OFF))
                            + (long)l * BHTT;
            float* P = out + attnBase;

            if (a == 0)
                attn_fused<1,true><<<gScore, 256, AT_SMEM>>>(q, k, v, P, c,
                    DKK, DD, DD, (long)TT*DD, 64L, (long)TT*DD, 64L,
                    HH, 0.125f, dec, TT);
            else if (a == 1)
                attn_fused<2,true><<<gScore, 256, AT_SMEM>>>(q, k, v, P, c,
                    DKK, DD, DD, (long)TT*DD, 64L, (long)TT*DD, 64L,
                    HH, 0.125f, enc, SS);
            else
                attn_fused<0,true><<<gScore, 256, AT_SMEM>>>(q, k, v, P, c,
                    DKK, DD, DD, (long)TT*DD, 64L, (long)TT*DD, 64L,
                    HH, 0.125f, nullptr, 0);

            gemm2<false,false><<<gProj, 256, GM_SMEM>>>(c, c, c,
                Wo, 0L, t, 0L, BT, DD, DD);
            add_ln<<<BT, 256>>>(t, x, x,
                ln_g + (long)(l*3 + a)*DD, ln_b + (long)(l*3 + a)*DD);
        }
        gemm2<true ,false><<<gF1, 256, GM_SMEM>>>(x, x, x,
            W1 + (long)l*DD*DFF, 0L, h, 0L, BT, DFF, DD);
        gemm2<false,false><<<gProj, 256, GM_SMEM>>>(h, h, h,
            W2 + (long)l*DFF*DD, 0L, t, 0L, BT, DD, DFF);
        add_ln<<<BT, 256>>>(t, x, x, nullptr, nullptr);
    }

    copyk<<<(BT*DD + 255)/256, 256>>>(x, out, (long)BT*DD);
}

// round 10
// speedup vs baseline: 1.2161x; 1.0589x over previous
#include <cuda_runtime.h>
#include <cuda_fp16.h>
#include <math.h>

// Problem dims
#define BB 16
#define TT 256
#define SS 256
#define NA 300
#define DD 512
#define HH 8
#define DKK 64
#define DFF 2048
#define LL 6

#define BT (BB*TT)                 // 4096
#define BHTT ((long)BB*HH*TT*TT)   // 8388608

// d_out layout (floats): x | self_attns | enc_attns | ast_attns
#define SELF_OFF 2097152L
#define ENC_OFF  (SELF_OFF + (long)LL*BHTT)
#define AST_OFF  (ENC_OFF  + (long)LL*BHTT)

// ------------- scratch -------------
__device__ float g_x[BT*DD];
__device__ float g_t[BT*DD];
__device__ float g_qkv[3*BT*DD];
__device__ float g_c[BT*DD];
__device__ float g_h[BT*DFF];
__device__ float g_multi[BB*SS*DD];
__device__ float g_ast1[BB*SS*DD];
__device__ float g_aste[BB*SS*DD];
__device__ float g_mm[BB*SS*SS];
__device__ float g_mmctx[BB*SS*DD];

// ------------- helpers -------------
__device__ __forceinline__ unsigned pack_h2(float x, float y) {
    __half2 h = __floats2half2_rn(x, y);
    return *reinterpret_cast<unsigned*>(&h);
}
__device__ __forceinline__ void mma_f16(float* d,
    unsigned a0, unsigned a1, unsigned a2, unsigned a3,
    unsigned b0, unsigned b1)
{
    asm volatile(
        "mma.sync.aligned.m16n8k16.row.col.f32.f16.f16.f32 "
        "{%0,%1,%2,%3},{%4,%5,%6,%7},{%8,%9},{%0,%1,%2,%3};\n"
        : "+f"(d[0]), "+f"(d[1]), "+f"(d[2]), "+f"(d[3])
        : "r"(a0), "r"(a1), "r"(a2), "r"(a3), "r"(b0), "r"(b1));
}
__device__ __forceinline__ void ldsm_x4(unsigned& r0, unsigned& r1,
                                        unsigned& r2, unsigned& r3, unsigned addr)
{
    asm volatile("ldmatrix.sync.aligned.m8n8.x4.shared.b16 {%0,%1,%2,%3}, [%4];"
        : "=r"(r0), "=r"(r1), "=r"(r2), "=r"(r3) : "r"(addr));
}
__device__ __forceinline__ void ldsm_x4_t(unsigned& r0, unsigned& r1,
                                          unsigned& r2, unsigned& r3, unsigned addr)
{
    asm volatile("ldmatrix.sync.aligned.m8n8.x4.trans.shared.b16 {%0,%1,%2,%3}, [%4];"
        : "=r"(r0), "=r"(r1), "=r"(r2), "=r"(r3) : "r"(addr));
}

// ---------------------------------------------------------------------
// gemm2 (fp16 MMA, fp32 accum): C[M,N] = A[M,K] @ B[K,N], row-major.
// 64x128x32 tiles, double-buffered, 256 threads (warps 2x4, warp 32x32).
// A = (z-selected pointer) + z*strA; B = B0 + z*strB; C = C0 + z*strC.
// KG: guard K not multiple of 32 (requires K%4==0 for alignment).
// RBIAS: add bias[row]. A via ldmatrix, B via ldmatrix.trans.
// dyn smem = 2*(64*20 + 32*68)*4 = 27648 B.
// ---------------------------------------------------------------------
#define VP 20
#define WPB 68
#define BUFW (64*VP + 32*WPB)   // 3456 words

template<bool RELU, bool ACC, bool RBIAS, bool KG>
__global__ __launch_bounds__(256, 2) void gemm2(
    const float* __restrict__ A0, const float* __restrict__ A1,
    const float* __restrict__ A2, long strA,
    const float* __restrict__ B0, long strB,
    float* __restrict__ C0, long strC,
    const float* __restrict__ bias,
    int M, int N, int K)
{
    extern __shared__ unsigned smg[];

    const int tid = threadIdx.x, warp = tid >> 5, lane = tid & 31;
    const int g = lane >> 2, tg = lane & 3;
    const int wr = warp >> 2, wc = warp & 3;
    const int z = blockIdx.z;

    const float* A = ((z == 0) ? A0 : (z == 1 ? A1 : A2)) + (long)z * strA;
    const float* At = A + (long)blockIdx.y * 64 * K;
    const float* Bt = B0 + (long)z * strB + blockIdx.x * 128;
    float* C = C0 + (long)z * strC;

    const int aR = tid >> 3;
    const int aC = (tid & 7) * 4;
    const int kp = tid >> 5;
    const int bC = (tid & 31) * 4;
    const int bw = (tid & 31) * 2;

    const int laneRow = (lane & 7) + ((lane >> 3) & 1) * 8;
    const int laneSeg = (lane >> 4) * 4;
    const unsigned vbase = (unsigned)__cvta_generic_to_shared(smg);
    const unsigned aLane = vbase + ((wr*32 + laneRow)*VP + laneSeg) * 4;
    const int kRow = lane & 15;
    const int nSel = lane >> 4;
    const unsigned bLane = vbase + (64*VP + kRow*WPB + wc*16 + nSel*4) * 4;

    float4 ra[2], rb[4];
    auto ldA = [&](int p, int k0) -> float4 {
        long row = aR + p*32;
        if (!KG || (k0 + aC + 4 <= K))
            return *reinterpret_cast<const float4*>(At + row*K + k0 + aC);
        float4 v = make_float4(0.f, 0.f, 0.f, 0.f);
        if (k0 + aC     < K) v.x = At[row*K + k0 + aC];
        if (k0 + aC + 1 < K) v.y = At[row*K + k0 + aC + 1];
        if (k0 + aC + 2 < K) v.z = At[row*K + k0 + aC + 2];
        if (k0 + aC + 3 < K) v.w = At[row*K + k0 + aC + 3];
        return v;
    };
    auto ldB = [&](int r, int k0) -> float4 {
        int row = k0 + r;
        if (!KG || row < K)
            return *reinterpret_cast<const float4*>(Bt + (long)row*N + bC);
        return make_float4(0.f, 0.f, 0.f, 0.f);
    };

    #pragma unroll
    for (int p = 0; p < 2; p++) ra[p] = ldA(p, 0);
    rb[0] = ldB(2*kp,      0);
    rb[1] = ldB(2*kp + 1,  0);
    rb[2] = ldB(2*kp + 16, 0);
    rb[3] = ldB(2*kp + 17, 0);

    auto sts = [&](int buf) {
        unsigned* V = smg + buf*BUFW;
        unsigned* W = V + 64*VP;
        #pragma unroll
        for (int p = 0; p < 2; p++) {
            int m = aR + p*32;
            uint2 w;
            w.x = pack_h2(ra[p].x, ra[p].y);
            w.y = pack_h2(ra[p].z, ra[p].w);
            *reinterpret_cast<uint2*>(&V[m*VP + (aC >> 1)]) = w;
        }
        {
            uint2 w;
            w.x = pack_h2(rb[0].x, rb[0].y); w.y = pack_h2(rb[0].z, rb[0].w);
            *reinterpret_cast<uint2*>(&W[(2*kp     )*WPB + bw]) = w;
            w.x = pack_h2(rb[1].x, rb[1].y); w.y = pack_h2(rb[1].z, rb[1].w);
            *reinterpret_cast<uint2*>(&W[(2*kp + 1 )*WPB + bw]) = w;
            w.x = pack_h2(rb[2].x, rb[2].y); w.y = pack_h2(rb[2].z, rb[2].w);
            *reinterpret_cast<uint2*>(&W[(2*kp + 16)*WPB + bw]) = w;
            w.x = pack_h2(rb[3].x, rb[3].y); w.y = pack_h2(rb[3].z, rb[3].w);
            *reinterpret_cast<uint2*>(&W[(2*kp + 17)*WPB + bw]) = w;
        }
    };
    sts(0);
    __syncthreads();

    float acc[8][4];
    #pragma unroll
    for (int i = 0; i < 8; i++) { acc[i][0]=0.f; acc[i][1]=0.f; acc[i][2]=0.f; acc[i][3]=0.f; }

    int cur = 0;
    for (int k0 = 0; k0 < K; k0 += 32) {
        const bool nxt = (k0 + 32) < K;
        if (nxt) {
            #pragma unroll
            for (int p = 0; p < 2; p++) ra[p] = ldA(p, k0 + 32);
            rb[0] = ldB(2*kp,      k0 + 32);
            rb[1] = ldB(2*kp + 1,  k0 + 32);
            rb[2] = ldB(2*kp + 16, k0 + 32);
            rb[3] = ldB(2*kp + 17, k0 + 32);
        }
        const unsigned aBuf = aLane + cur*BUFW*4;
        const unsigned bBuf = bLane + cur*BUFW*4;
        #pragma unroll
        for (int kt = 0; kt < 2; kt++) {
            unsigned a[2][4], b[4][2];
            #pragma unroll
            for (int mi = 0; mi < 2; mi++)
                ldsm_x4(a[mi][0], a[mi][1], a[mi][2], a[mi][3],
                        aBuf + mi*16*VP*4 + kt*32);
            {
                unsigned r0, r1, r2, r3;
                ldsm_x4_t(r0, r1, r2, r3, bBuf + kt*16*WPB*4);
                b[0][0]=r0; b[0][1]=r1; b[1][0]=r2; b[1][1]=r3;
                ldsm_x4_t(r0, r1, r2, r3, bBuf + kt*16*WPB*4 + 32);
                b[2][0]=r0; b[2][1]=r1; b[3][0]=r2; b[3][1]=r3;
            }
            #pragma unroll
            for (int mi = 0; mi < 2; mi++)
                #pragma unroll
                for (int nj = 0; nj < 4; nj++)
                    mma_f16(acc[mi*4+nj], a[mi][0],a[mi][1],a[mi][2],a[mi][3],
                            b[nj][0], b[nj][1]);
        }
        if (nxt) {
            sts(cur ^ 1);
            __syncthreads();
            cur ^= 1;
        }
    }

    #pragma unroll
    for (int mi = 0; mi < 2; mi++) {
        #pragma unroll
        for (int nj = 0; nj < 4; nj++) {
            float* d = acc[mi*4+nj];
            int r0 = blockIdx.y*64 + wr*32 + mi*16 + g;
            int col = blockIdx.x*128 + wc*32 + nj*8 + tg*2;
            float b0 = RBIAS ? bias[r0] : 0.f;
            float b1 = RBIAS ? bias[r0+8] : 0.f;
            float2 v0 = make_float2(d[0]+b0, d[1]+b0);
            float2 v1 = make_float2(d[2]+b1, d[3]+b1);
            float2* p0 = reinterpret_cast<float2*>(C + (long)r0*N + col);
            float2* p1 = reinterpret_cast<float2*>(C + (long)(r0+8)*N + col);
            if (ACC) { float2 o0 = *p0, o1 = *p1; v0.x+=o0.x; v0.y+=o0.y; v1.x+=o1.x; v1.y+=o1.y; }
            if (RELU) { v0.x=fmaxf(v0.x,0.f); v0.y=fmaxf(v0.y,0.f); v1.x=fmaxf(v1.x,0.f); v1.y=fmaxf(v1.y,0.f); }
            *p0 = v0; *p1 = v1;
        }
    }
}

// ---------------------------------------------------------------------
// attn_fused (fp16 MMA) — unchanged (proven).
// ---------------------------------------------------------------------
#define QP 36
#define KP 36
#define VBP 68
#define PP 132

template<int MASK, bool CTX>
__global__ __launch_bounds__(256) void attn_fused(
    const float* __restrict__ Q, const float* __restrict__ Km,
    const float* __restrict__ Vm, float* __restrict__ P,
    float* __restrict__ Cctx,
    int Kdim, int lda, int ldb,
    long strA, long offHA, long strB, long offHB,
    int Hh, float scale, const int* __restrict__ tok, int tokStride)
{
    extern __shared__ unsigned sma[];
    unsigned* Qs = sma;
    unsigned* Ks = sma + 64*QP;
    unsigned* Vs = sma + 64*QP + 256*KP;
    unsigned* Ps = sma;
    __shared__ float red[64*4];

    const int tid = threadIdx.x, warp = tid >> 5, lane = tid & 31;
    const int g = lane >> 2, tg = lane & 3;
    const int wr = warp >> 2, wc = warp & 3;
    const int z = blockIdx.y;
    const int bb = z / Hh, hh = z - bb*Hh;
    const int rowTile = blockIdx.x;
    const int rowBase = rowTile * 64;

    const float* Qb = Q + (long)bb*strA + (long)hh*offHA + (long)rowBase*lda;
    const float* Kb = Km + (long)bb*strB + (long)hh*offHB;

    float acc[16][4];
    #pragma unroll
    for (int i = 0; i < 16; i++) { acc[i][0]=0.f; acc[i][1]=0.f; acc[i][2]=0.f; acc[i][3]=0.f; }

    for (int k0 = 0; k0 < Kdim; k0 += 64) {
        #pragma unroll
        for (int p = 0; p < 4; p++) {
            int idx = tid + p*256;
            int r = idx >> 4, c4 = idx & 15;
            float4 v = *reinterpret_cast<const float4*>(Qb + (long)r*lda + k0 + c4*4);
            uint2 w; w.x = pack_h2(v.x, v.y); w.y = pack_h2(v.z, v.w);
            *reinterpret_cast<uint2*>(&Qs[r*QP + c4*2]) = w;
        }
        #pragma unroll
        for (int p = 0; p < 16; p++) {
            int idx = tid + p*256;
            int r = idx >> 4, c4 = idx & 15;
            float4 v = *reinterpret_cast<const float4*>(Kb + (long)r*ldb + k0 + c4*4);
            uint2 w; w.x = pack_h2(v.x, v.y); w.y = pack_h2(v.z, v.w);
            *reinterpret_cast<uint2*>(&Ks[r*KP + c4*2]) = w;
        }
        if (CTX && k0 == 0) {
            const float* Vb = Vm + (long)bb*strB + (long)hh*offHB;
            #pragma unroll
            for (int p = 0; p < 8; p++) {
                int idx = tid + p*256;
                int r2 = idx >> 4, c4 = idx & 15;
                float4 v0 = *reinterpret_cast<const float4*>(Vb + (long)(2*r2  )*ldb + c4*4);
                float4 v1 = *reinterpret_cast<const float4*>(Vb + (long)(2*r2+1)*ldb + c4*4);
                uint4 w;
                w.x = pack_h2(v0.x, v1.x); w.y = pack_h2(v0.y, v1.y);
                w.z = pack_h2(v0.z, v1.z); w.w = pack_h2(v0.w, v1.w);
                *reinterpret_cast<uint4*>(&Vs[r2*VBP + c4*4]) = w;
            }
        }
        __syncthreads();
        #pragma unroll
        for (int kt = 0; kt < 4; kt++) {
            unsigned a[2][4], b[8][2];
            #pragma unroll
            for (int mi = 0; mi < 2; mi++) {
                int mb = wr*32 + mi*16;
                a[mi][0] = Qs[(mb+g  )*QP + kt*8 + tg];
                a[mi][1] = Qs[(mb+g+8)*QP + kt*8 + tg];
                a[mi][2] = Qs[(mb+g  )*QP + kt*8 + tg + 4];
                a[mi][3] = Qs[(mb+g+8)*QP + kt*8 + tg + 4];
            }
            #pragma unroll
            for (int nj = 0; nj < 8; nj++) {
                int nb = wc*64 + nj*8;
                b[nj][0] = Ks[(nb+g)*KP + kt*8 + tg];
                b[nj][1] = Ks[(nb+g)*KP + kt*8 + tg + 4];
            }
            #pragma unroll
            for (int mi = 0; mi < 2; mi++)
                #pragma unroll
                for (int nj = 0; nj < 8; nj++)
                    mma_f16(acc[mi*8+nj], a[mi][0],a[mi][1],a[mi][2],a[mi][3],
                            b[nj][0], b[nj][1]);
        }
        if (k0 + 64 < Kdim) __syncthreads();
    }

    // ---- scale + mask ----
    #pragma unroll
    for (int mi = 0; mi < 2; mi++) {
        #pragma unroll
        for (int nj = 0; nj < 8; nj++) {
            float* d = acc[mi*8+nj];
            int col = wc*64 + nj*8 + tg*2;
            int lr0 = wr*32 + mi*16 + g;
            #pragma unroll
            for (int c = 0; c < 4; c++) {
                int gcol = col + (c & 1);
                int grow = rowBase + lr0 + ((c >> 1) * 8);
                float v = d[c] * scale;
                if (MASK == 1) {
                    if (tok[bb*tokStride + gcol] == 0 || gcol > grow) v = -1e9f;
                } else if (MASK == 2) {
                    if (tok[bb*tokStride + gcol] == 0) v = -1e9f;
                }
                d[c] = v;
            }
        }
    }

    // ---- softmax (fp32) ----
    float rmax[4];
    #pragma unroll
    for (int mi = 0; mi < 2; mi++) {
        float m0 = -1e30f, m1 = -1e30f;
        #pragma unroll
        for (int nj = 0; nj < 8; nj++) {
            float* d = acc[mi*8+nj];
            m0 = fmaxf(m0, fmaxf(d[0], d[1]));
            m1 = fmaxf(m1, fmaxf(d[2], d[3]));
        }
        rmax[mi*2+0] = m0; rmax[mi*2+1] = m1;
    }
    #pragma unroll
    for (int i = 0; i < 4; i++) {
        rmax[i] = fmaxf(rmax[i], __shfl_xor_sync(0xffffffffu, rmax[i], 1));
        rmax[i] = fmaxf(rmax[i], __shfl_xor_sync(0xffffffffu, rmax[i], 2));
    }
    if (tg == 0) {
        #pragma unroll
        for (int mi = 0; mi < 2; mi++) {
            red[(wr*32 + mi*16 + g    )*4 + wc] = rmax[mi*2+0];
            red[(wr*32 + mi*16 + g + 8)*4 + wc] = rmax[mi*2+1];
        }
    }
    __syncthreads();
    float fmax4[4];
    #pragma unroll
    for (int mi = 0; mi < 2; mi++) {
        int r0 = wr*32 + mi*16 + g, r1 = r0 + 8;
        fmax4[mi*2+0] = fmaxf(fmaxf(red[r0*4+0], red[r0*4+1]), fmaxf(red[r0*4+2], red[r0*4+3]));
        fmax4[mi*2+1] = fmaxf(fmaxf(red[r1*4+0], red[r1*4+1]), fmaxf(red[r1*4+2], red[r1*4+3]));
    }
    __syncthreads();

    float rsum[4] = {0.f, 0.f, 0.f, 0.f};
    #pragma unroll
    for (int mi = 0; mi < 2; mi++) {
        #pragma unroll
        for (int nj = 0; nj < 8; nj++) {
            float* d = acc[mi*8+nj];
            d[0] = __expf(d[0] - fmax4[mi*2+0]);
            d[1] = __expf(d[1] - fmax4[mi*2+0]);
            d[2] = __expf(d[2] - fmax4[mi*2+1]);
            d[3] = __expf(d[3] - fmax4[mi*2+1]);
            rsum[mi*2+0] += d[0] + d[1];
            rsum[mi*2+1] += d[2] + d[3];
        }
    }
    #pragma unroll
    for (int i = 0; i < 4; i++) {
        rsum[i] += __shfl_xor_sync(0xffffffffu, rsum[i], 1);
        rsum[i] += __shfl_xor_sync(0xffffffffu, rsum[i], 2);
    }
    if (tg == 0) {
        #pragma unroll
        for (int mi = 0; mi < 2; mi++) {
            red[(wr*32 + mi*16 + g    )*4 + wc] = rsum[mi*2+0];
            red[(wr*32 + mi*16 + g + 8)*4 + wc] = rsum[mi*2+1];
        }
    }
    __syncthreads();
    float rinv[4];
    #pragma unroll
    for (int mi = 0; mi < 2; mi++) {
        int r0 = wr*32 + mi*16 + g, r1 = r0 + 8;
        rinv[mi*2+0] = 1.f / (red[r0*4+0] + red[r0*4+1] + red[r0*4+2] + red[r0*4+3]);
        rinv[mi*2+1] = 1.f / (red[r1*4+0] + red[r1*4+1] + red[r1*4+2] + red[r1*4+3]);
    }

    float* Pb = P + (long)z * 65536L + (long)rowBase * 256;
    #pragma unroll
    for (int mi = 0; mi < 2; mi++) {
        #pragma unroll
        for (int nj = 0; nj < 8; nj++) {
            float* d = acc[mi*8+nj];
            int col = wc*64 + nj*8 + tg*2;
            int r0 = wr*32 + mi*16 + g;
            float p0 = d[0]*rinv[mi*2+0], p1 = d[1]*rinv[mi*2+0];
            float p2 = d[2]*rinv[mi*2+1], p3 = d[3]*rinv[mi*2+1];
            *reinterpret_cast<float2*>(Pb + (long)r0*256 + col) = make_float2(p0, p1);
            *reinterpret_cast<float2*>(Pb + (long)(r0+8)*256 + col) = make_float2(p2, p3);
            if (CTX) {
                int k2 = wc*32 + nj*4 + tg;
                Ps[r0*PP + k2]     = pack_h2(p0, p1);
                Ps[(r0+8)*PP + k2] = pack_h2(p2, p3);
            }
        }
    }

    if (CTX) {
        __syncthreads();
        float acc2[4][4];
        #pragma unroll
        for (int i = 0; i < 4; i++) { acc2[i][0]=0.f; acc2[i][1]=0.f; acc2[i][2]=0.f; acc2[i][3]=0.f; }
        #pragma unroll
        for (int kt = 0; kt < 16; kt++) {
            unsigned a[2][4], b[2][2];
            #pragma unroll
            for (int mi = 0; mi < 2; mi++) {
                int mb = wr*32 + mi*16;
                a[mi][0] = Ps[(mb+g  )*PP + kt*8 + tg];
                a[mi][1] = Ps[(mb+g+8)*PP + kt*8 + tg];
                a[mi][2] = Ps[(mb+g  )*PP + kt*8 + tg + 4];
                a[mi][3] = Ps[(mb+g+8)*PP + kt*8 + tg + 4];
            }
            #pragma unroll
            for (int nj = 0; nj < 2; nj++) {
                int nb = wc*16 + nj*8 + g;
                b[nj][0] = Vs[(kt*8 + tg    )*VBP + nb];
                b[nj][1] = Vs[(kt*8 + tg + 4)*VBP + nb];
            }
            #pragma unroll
            for (int mi = 0; mi < 2; mi++)
                #pragma unroll
                for (int nj = 0; nj < 2; nj++)
                    mma_f16(acc2[mi*2+nj], a[mi][0],a[mi][1],a[mi][2],a[mi][3],
                            b[nj][0], b[nj][1]);
        }
        float* Cb = Cctx + (long)bb*TT*DD + hh*64;
        #pragma unroll
        for (int mi = 0; mi < 2; mi++) {
            #pragma unroll
            for (int nj = 0; nj < 2; nj++) {
                float* d = acc2[mi*2+nj];
                int r0 = rowBase + wr*32 + mi*16 + g;
                int col = wc*16 + nj*8 + tg*2;
                *reinterpret_cast<float2*>(Cb + (long)r0*DD + col) = make_float2(d[0], d[1]);
                *reinterpret_cast<float2*>(Cb + (long)(r0+8)*DD + col) = make_float2(d[2], d[3]);
            }
        }
    }
}

// ---------------------------------------------------------------------
__global__ __launch_bounds__(256) void add_ln(
    const float* __restrict__ a, const float* __restrict__ b,
    float* __restrict__ out, const float* __restrict__ g,
    const float* __restrict__ beta)
{
    long off = (long)blockIdx.x * DD;
    int t = threadIdx.x;
    int warp = t >> 5, lane = t & 31;
    float v0 = a[off + t] + b[off + t];
    float v1 = a[off + t + 256] + b[off + t + 256];
    __shared__ float ws[8], ws2[8];

    float s = v0 + v1;
    #pragma unroll
    for (int o = 16; o > 0; o >>= 1) s += __shfl_xor_sync(0xffffffffu, s, o);
    if (lane == 0) ws[warp] = s;
    __syncthreads();
    float mu = (ws[0]+ws[1]+ws[2]+ws[3]+ws[4]+ws[5]+ws[6]+ws[7]) * (1.f/DD);

    float d0 = v0 - mu, d1 = v1 - mu;
    float q = d0*d0 + d1*d1;
    #pragma unroll
    for (int o = 16; o > 0; o >>= 1) q += __shfl_xor_sync(0xffffffffu, q, o);
    if (lane == 0) ws2[warp] = q;
    __syncthreads();
    float rstd = rsqrtf((ws2[0]+ws2[1]+ws2[2]+ws2[3]+ws2[4]+ws2[5]+ws2[6]+ws2[7]) * (1.f/DD) + 1e-5f);

    float g0 = g ? g[t] : 1.f,       g1 = g ? g[t+256] : 1.f;
    float b0 = beta ? beta[t] : 0.f, b1 = beta ? beta[t+256] : 0.f;
    out[off + t]       = d0 * rstd * g0 + b0;
    out[off + t + 256] = d1 * rstd * g1 + b1;
}

__global__ void embed_pe(const int* __restrict__ dec,
                         const float* __restrict__ emb,
                         float* __restrict__ x)
{
    long idx = (long)blockIdx.x * blockDim.x + threadIdx.x;
    if (idx >= (long)BT*DD) return;
    int d  = (int)(idx % DD);
    long bt = idx / DD;
    int t  = (int)(bt % TT);
    int tokidx = dec[bt];
    int d2 = d & ~1;
    float div = expf(-logf(10000.f) * (float)d2 / (float)DD);
    float ang = (float)t * div;
    float pe = (d & 1) ? cosf(ang) : sinf(ang);
    x[idx] = emb[(long)tokidx*DD + d] + pe;
}

__global__ void add3(const float* __restrict__ a, const float* __restrict__ bias,
                     const float* __restrict__ c, float* __restrict__ out, long n)
{
    long i = (long)blockIdx.x * blockDim.x + threadIdx.x;
    if (i >= n) return;
    out[i] = a[i] + bias[i % DD] + c[i];
}

__global__ void copyk(const float* __restrict__ src, float* __restrict__ dst, long n)
{
    long i = (long)blockIdx.x * blockDim.x + threadIdx.x;
    if (i < n) dst[i] = src[i];
}

// ---------------------------------------------------------------------
extern "C" void kernel_launch(void* const* d_in, const int* in_sizes, int n_in,
                              void* d_out, int out_size)
{
    const int*   dec     = (const int*)  d_in[0];
    const int*   enc     = (const int*)  d_in[1];
    const float* enc_out = (const float*)d_in[2];
    const float* ast_out = (const float*)d_in[3];
    const float* src_emb = (const float*)d_in[4];
    const float* ast_emb = (const float*)d_in[5];
    const float* emb     = (const float*)d_in[7];
    const float* attn_W  = (const float*)d_in[8];
    const float* ln_g    = (const float*)d_in[9];
    const float* ln_b    = (const float*)d_in[10];
    const float* W1      = (const float*)d_in[11];
    const float* W2      = (const float*)d_in[12];
    const float* conv_w  = (const float*)d_in[13];
    const float* conv_b  = (const float*)d_in[14];
    const float* mffnW   = (const float*)d_in[15];
    const float* mffnb   = (const float*)d_in[16];
    float* out = (float*)d_out;

    float *x,*t,*qkv,*c,*h,*multi,*ast1,*aste,*mm,*mmctx;
    cudaGetSymbolAddress((void**)&x,     g_x);
    cudaGetSymbolAddress((void**)&t,     g_t);
    cudaGetSymbolAddress((void**)&qkv,   g_qkv);
    cudaGetSymbolAddress((void**)&c,     g_c);
    cudaGetSymbolAddress((void**)&h,     g_h);
    cudaGetSymbolAddress((void**)&multi, g_multi);
    cudaGetSymbolAddress((void**)&ast1,  g_ast1);
    cudaGetSymbolAddress((void**)&aste,  g_aste);
    cudaGetSymbolAddress((void**)&mm,    g_mm);
    cudaGetSymbolAddress((void**)&mmctx, g_mmctx);

    const int GM_SMEM  = 2*BUFW*4;                              // 27648
    const int AT_SMEM  = (64*QP + 256*KP + 128*VBP)*4;          // 80896 (CTX)
    const int MM_SMEM  = (64*QP + 256*KP)*4;                    // 46080 (no CTX)
    cudaFuncSetAttribute((const void*)gemm2<false,false,false,false>, cudaFuncAttributeMaxDynamicSharedMemorySize, GM_SMEM);
    cudaFuncSetAttribute((const void*)gemm2<false,true ,false,false>, cudaFuncAttributeMaxDynamicSharedMemorySize, GM_SMEM);
    cudaFuncSetAttribute((const void*)gemm2<true ,false,false,false>, cudaFuncAttributeMaxDynamicSharedMemorySize, GM_SMEM);
    cudaFuncSetAttribute((const void*)gemm2<false,false,true ,true >, cudaFuncAttributeMaxDynamicSharedMemorySize, GM_SMEM);
    cudaFuncSetAttribute((const void*)attn_fused<0,false>, cudaFuncAttributeMaxDynamicSharedMemorySize, MM_SMEM);
    cudaFuncSetAttribute((const void*)attn_fused<0,true >, cudaFuncAttributeMaxDynamicSharedMemorySize, AT_SMEM);
    cudaFuncSetAttribute((const void*)attn_fused<1,true >, cudaFuncAttributeMaxDynamicSharedMemorySize, AT_SMEM);
    cudaFuncSetAttribute((const void*)attn_fused<2,true >, cudaFuncAttributeMaxDynamicSharedMemorySize, AT_SMEM);

    float* q = qkv;
    float* k = qkv + (long)BT*DD;
    float* v = qkv + 2L*BT*DD;

    // ---- fork: preamble runs on s2, main path on default stream ----
    cudaStream_t s2;
    cudaStreamCreate(&s2);
    cudaEvent_t evF, evJ;
    cudaEventCreateWithFlags(&evF, cudaEventDisableTiming);
    cudaEventCreateWithFlags(&evJ, cudaEventDisableTiming);
    cudaEventRecord(evF, 0);
    cudaStreamWaitEvent(s2, evF, 0);

    // ---------------- multi_model preamble (stream s2) ----------------
    {
        // ast1 = conv_w @ ast_out[b] + conv_b; aste likewise. K=300 (guarded).
        dim3 gc(DD/128, SS/64, BB);
        gemm2<false,false,true,true><<<gc, 256, GM_SMEM, s2>>>(
            conv_w, conv_w, conv_w, 0L, ast_out, (long)NA*DD,
            ast1, (long)SS*DD, conv_b, SS, DD, NA);
        gemm2<false,false,true,true><<<gc, 256, GM_SMEM, s2>>>(
            conv_w, conv_w, conv_w, 0L, ast_emb, (long)NA*DD,
            aste, (long)SS*DD, conv_b, SS, DD, NA);
        // mm = softmax(ast1 @ enc_out^T / 8)
        dim3 gs(SS/64, BB);
        attn_fused<0,false><<<gs, 256, MM_SMEM, s2>>>(ast1, enc_out, nullptr, mm, nullptr,
            DD, DD, DD, (long)SS*DD, 0L, (long)SS*DD, 0L,
            1, 0.125f, nullptr, 0);
        // mmctx = mm @ enc_out
        dim3 gm(DD/128, SS/64, BB);
        gemm2<false,false,false,false><<<gm, 256, GM_SMEM, s2>>>(
            mm, mm, mm, (long)SS*SS, enc_out, (long)SS*DD,
            mmctx, (long)SS*DD, nullptr, SS, DD, SS);
        // h(tmp) = src_emb @ Wtop; += aste @ Wbot; multi = h + b + mmctx
        dim3 gp(DD/128, BT/64, 1);
        gemm2<false,false,false,false><<<gp, 256, GM_SMEM, s2>>>(
            src_emb, src_emb, src_emb, 0L, mffnW, 0L, h, 0L, nullptr, BT, DD, DD);
        gemm2<false,true ,false,false><<<gp, 256, GM_SMEM, s2>>>(
            aste, aste, aste, 0L, mffnW + DD*DD, 0L, h, 0L, nullptr, BT, DD, DD);
        long n = (long)BB*SS*DD;
        add3<<<(int)((n + 255)/256), 256, 0, s2>>>(h, mffnb, mmctx, multi, n);
    }
    cudaEventRecord(evJ, s2);

    // ---------------- main path ----------------
    embed_pe<<<(BT*DD + 255)/256, 256>>>(dec, emb, x);

    dim3 gQKV(DD/128, BT/64, 3);
    dim3 gProj(DD/128, BT/64, 1);
    dim3 gF1(DFF/128, BT/64, 1);
    dim3 gScore(TT/64, BB*HH);

    for (int l = 0; l < LL; l++) {
        for (int a = 0; a < 3; a++) {
            const float* W = attn_W + ((long)(l*3 + a) * 4) * DD * DD;
            const float* Wo = W + 3L*DD*DD;
            const float* xk = (a == 0) ? x : (a == 1 ? enc_out : multi);

            if (l == 0 && a == 2) cudaStreamWaitEvent(0, evJ, 0);  // join: multi ready

            gemm2<false,false,false,false><<<gQKV, 256, GM_SMEM>>>(
                x, xk, xk, 0L, W, (long)DD*DD, qkv, (long)BT*DD, nullptr, BT, DD, DD);

            long attnBase = (a == 0 ? SELF_OFF : (a == 1 ? ENC_OFF : AST_OFF))
                            + (long)l * BHTT;
            float* P = out + attnBase;

            if (a == 0)
                attn_fused<1,true><<<gScore, 256, AT_SMEM>>>(q, k, v, P, c,
                    DKK, DD, DD, (long)TT*DD, 64L, (long)TT*DD, 64L,
                    HH, 0.125f, dec, TT);
            else if (a == 1)
                attn_fused<2,true><<<gScore, 256, AT_SMEM>>>(q, k, v, P, c,
                    DKK, DD, DD, (long)TT*DD, 64L, (long)TT*DD, 64L,
                    HH, 0.125f, enc, SS);
            else
                attn_fused<0,true><<<gScore, 256, AT_SMEM>>>(q, k, v, P, c,
                    DKK, DD, DD, (long)TT*DD, 64L, (long)TT*DD, 64L,
                    HH, 0.125f, nullptr, 0);

            gemm2<false,false,false,false><<<gProj, 256, GM_SMEM>>>(
                c, c, c, 0L, Wo, 0L, t, 0L, nullptr, BT, DD, DD);
            add_ln<<<BT, 256>>>(t, x, x,
                ln_g + (long)(l*3 + a)*DD, ln_b + (long)(l*3 + a)*DD);
        }
        gemm2<true,false,false,false><<<gF1, 256, GM_SMEM>>>(
            x, x, x, 0L, W1 + (long)l*DD*DFF, 0L, h, 0L, nullptr, BT, DFF, DD);
        gemm2<false,false,false,false><<<gProj, 256, GM_SMEM>>>(
            h, h, h, 0L, W2 + (long)l*DFF*DD, 0L, t, 0L, nullptr, BT, DD, DFF);
        add_ln<<<BT, 256>>>(t, x, x, nullptr, nullptr);
    }

    copyk<<<(BT*DD + 255)/256, 256>>>(x, out, (long)BT*DD);

    cudaStreamDestroy(s2);
    cudaEventDestroy(evF);
    cudaEventDestroy(evJ);
}

// round 12
// speedup vs baseline: 1.2314x; 1.0125x over previous
#include <cuda_runtime.h>
#include <cuda_fp16.h>
#include <math.h>

// Problem dims
#define BB 16
#define TT 256
#define SS 256
#define NA 300
#define DD 512
#define HH 8
#define DKK 64
#define DFF 2048
#define LL 6

#define BT (BB*TT)                 // 4096
#define BHTT ((long)BB*HH*TT*TT)   // 8388608

#define SELF_OFF 2097152L
#define ENC_OFF  (SELF_OFF + (long)LL*BHTT)
#define AST_OFF  (ENC_OFF  + (long)LL*BHTT)

// ------------- scratch -------------
__device__ float g_x[BT*DD];
__device__ float g_t[BT*DD];
__device__ float g_qkv[3*BT*DD];
__device__ float g_c[BT*DD];
__device__ float g_h[BT*DFF];
__device__ float g_multi[BB*SS*DD];
__device__ float g_ast1[BB*SS*DD];
__device__ float g_aste[BB*SS*DD];
__device__ float g_mm[BB*SS*SS];
__device__ float g_mmctx[BB*SS*DD];

// ------------- helpers -------------
__device__ __forceinline__ unsigned pack_h2(float x, float y) {
    __half2 h = __floats2half2_rn(x, y);
    return *reinterpret_cast<unsigned*>(&h);
}
__device__ __forceinline__ void mma_f16(float* d,
    unsigned a0, unsigned a1, unsigned a2, unsigned a3,
    unsigned b0, unsigned b1)
{
    asm volatile(
        "mma.sync.aligned.m16n8k16.row.col.f32.f16.f16.f32 "
        "{%0,%1,%2,%3},{%4,%5,%6,%7},{%8,%9},{%0,%1,%2,%3};\n"
        : "+f"(d[0]), "+f"(d[1]), "+f"(d[2]), "+f"(d[3])
        : "r"(a0), "r"(a1), "r"(a2), "r"(a3), "r"(b0), "r"(b1));
}
__device__ __forceinline__ void ldsm_x4(unsigned& r0, unsigned& r1,
                                        unsigned& r2, unsigned& r3, unsigned addr)
{
    asm volatile("ldmatrix.sync.aligned.m8n8.x4.shared.b16 {%0,%1,%2,%3}, [%4];"
        : "=r"(r0), "=r"(r1), "=r"(r2), "=r"(r3) : "r"(addr));
}
__device__ __forceinline__ void ldsm_x4_t(unsigned& r0, unsigned& r1,
                                          unsigned& r2, unsigned& r3, unsigned addr)
{
    asm volatile("ldmatrix.sync.aligned.m8n8.x4.trans.shared.b16 {%0,%1,%2,%3}, [%4];"
        : "=r"(r0), "=r"(r1), "=r"(r2), "=r"(r3) : "r"(addr));
}

// ---------------------------------------------------------------------
// gemm2 (fp16 MMA, fp32 accum): C[M,N] = A[M,K] @ B[K,N], row-major.
// 64x128x32 tiles, double-buffered, 256 threads (warps 2x4, warp 32x32).
// A = (z-selected pointer) + z*strA; B = B0 + z*strB; C = C0 + z*strC.
// KG: guard K not multiple of 32. RBIAS: add bias[row].
// A via ldmatrix, B via ldmatrix.trans.
// dyn smem = 2*(64*20 + 32*68)*4 = 27648 B.
// ---------------------------------------------------------------------
#define VP 20
#define WPB 68
#define BUFW (64*VP + 32*WPB)   // 3456 words

template<bool RELU, bool ACC, bool RBIAS, bool KG>
__global__ __launch_bounds__(256, 2) void gemm2(
    const float* __restrict__ A0, const float* __restrict__ A1,
    const float* __restrict__ A2, long strA,
    const float* __restrict__ B0, long strB,
    float* __restrict__ C0, long strC,
    const float* __restrict__ bias,
    int M, int N, int K)
{
    extern __shared__ unsigned smg[];

    const int tid = threadIdx.x, warp = tid >> 5, lane = tid & 31;
    const int g = lane >> 2, tg = lane & 3;
    const int wr = warp >> 2, wc = warp & 3;
    const int z = blockIdx.z;

    const float* A = ((z == 0) ? A0 : (z == 1 ? A1 : A2)) + (long)z * strA;
    const float* At = A + (long)blockIdx.y * 64 * K;
    const float* Bt = B0 + (long)z * strB + blockIdx.x * 128;
    float* C = C0 + (long)z * strC;

    const int aR = tid >> 3;
    const int aC = (tid & 7) * 4;
    const int kp = tid >> 5;
    const int bC = (tid & 31) * 4;
    const int bw = (tid & 31) * 2;

    const int laneRow = (lane & 7) + ((lane >> 3) & 1) * 8;
    const int laneSeg = (lane >> 4) * 4;
    const unsigned vbase = (unsigned)__cvta_generic_to_shared(smg);
    const unsigned aLane = vbase + ((wr*32 + laneRow)*VP + laneSeg) * 4;
    const int kRow = lane & 15;
    const int nSel = lane >> 4;
    const unsigned bLane = vbase + (64*VP + kRow*WPB + wc*16 + nSel*4) * 4;

    float4 ra[2], rb[4];
    auto ldA = [&](int p, int k0) -> float4 {
        long row = aR + p*32;
        if (!KG || (k0 + aC + 4 <= K))
            return *reinterpret_cast<const float4*>(At + row*K + k0 + aC);
        float4 v = make_float4(0.f, 0.f, 0.f, 0.f);
        if (k0 + aC     < K) v.x = At[row*K + k0 + aC];
        if (k0 + aC + 1 < K) v.y = At[row*K + k0 + aC + 1];
        if (k0 + aC + 2 < K) v.z = At[row*K + k0 + aC + 2];
        if (k0 + aC + 3 < K) v.w = At[row*K + k0 + aC + 3];
        return v;
    };
    auto ldB = [&](int r, int k0) -> float4 {
        int row = k0 + r;
        if (!KG || row < K)
            return *reinterpret_cast<const float4*>(Bt + (long)row*N + bC);
        return make_float4(0.f, 0.f, 0.f, 0.f);
    };

    #pragma unroll
    for (int p = 0; p < 2; p++) ra[p] = ldA(p, 0);
    rb[0] = ldB(2*kp,      0);
    rb[1] = ldB(2*kp + 1,  0);
    rb[2] = ldB(2*kp + 16, 0);
    rb[3] = ldB(2*kp + 17, 0);

    auto sts = [&](int buf) {
        unsigned* V = smg + buf*BUFW;
        unsigned* W = V + 64*VP;
        #pragma unroll
        for (int p = 0; p < 2; p++) {
            int m = aR + p*32;
            uint2 w;
            w.x = pack_h2(ra[p].x, ra[p].y);
            w.y = pack_h2(ra[p].z, ra[p].w);
            *reinterpret_cast<uint2*>(&V[m*VP + (aC >> 1)]) = w;
        }
        {
            uint2 w;
            w.x = pack_h2(rb[0].x, rb[0].y); w.y = pack_h2(rb[0].z, rb[0].w);
            *reinterpret_cast<uint2*>(&W[(2*kp     )*WPB + bw]) = w;
            w.x = pack_h2(rb[1].x, rb[1].y); w.y = pack_h2(rb[1].z, rb[1].w);
            *reinterpret_cast<uint2*>(&W[(2*kp + 1 )*WPB + bw]) = w;
            w.x = pack_h2(rb[2].x, rb[2].y); w.y = pack_h2(rb[2].z, rb[2].w);
            *reinterpret_cast<uint2*>(&W[(2*kp + 16)*WPB + bw]) = w;
            w.x = pack_h2(rb[3].x, rb[3].y); w.y = pack_h2(rb[3].z, rb[3].w);
            *reinterpret_cast<uint2*>(&W[(2*kp + 17)*WPB + bw]) = w;
        }
    };
    sts(0);
    __syncthreads();

    float acc[8][4];
    #pragma unroll
    for (int i = 0; i < 8; i++) { acc[i][0]=0.f; acc[i][1]=0.f; acc[i][2]=0.f; acc[i][3]=0.f; }

    int cur = 0;
    for (int k0 = 0; k0 < K; k0 += 32) {
        const bool nxt = (k0 + 32) < K;
        if (nxt) {
            #pragma unroll
            for (int p = 0; p < 2; p++) ra[p] = ldA(p, k0 + 32);
            rb[0] = ldB(2*kp,      k0 + 32);
            rb[1] = ldB(2*kp + 1,  k0 + 32);
            rb[2] = ldB(2*kp + 16, k0 + 32);
            rb[3] = ldB(2*kp + 17, k0 + 32);
        }
        const unsigned aBuf = aLane + cur*BUFW*4;
        const unsigned bBuf = bLane + cur*BUFW*4;
        #pragma unroll
        for (int kt = 0; kt < 2; kt++) {
            unsigned a[2][4], b[4][2];
            #pragma unroll
            for (int mi = 0; mi < 2; mi++)
                ldsm_x4(a[mi][0], a[mi][1], a[mi][2], a[mi][3],
                        aBuf + mi*16*VP*4 + kt*32);
            {
                unsigned r0, r1, r2, r3;
                ldsm_x4_t(r0, r1, r2, r3, bBuf + kt*16*WPB*4);
                b[0][0]=r0; b[0][1]=r1; b[1][0]=r2; b[1][1]=r3;
                ldsm_x4_t(r0, r1, r2, r3, bBuf + kt*16*WPB*4 + 32);
                b[2][0]=r0; b[2][1]=r1; b[3][0]=r2; b[3][1]=r3;
            }
            #pragma unroll
            for (int mi = 0; mi < 2; mi++)
                #pragma unroll
                for (int nj = 0; nj < 4; nj++)
                    mma_f16(acc[mi*4+nj], a[mi][0],a[mi][1],a[mi][2],a[mi][3],
                            b[nj][0], b[nj][1]);
        }
        if (nxt) {
            sts(cur ^ 1);
            __syncthreads();
            cur ^= 1;
        }
    }

    #pragma unroll
    for (int mi = 0; mi < 2; mi++) {
        #pragma unroll
        for (int nj = 0; nj < 4; nj++) {
            float* d = acc[mi*4+nj];
            int r0 = blockIdx.y*64 + wr*32 + mi*16 + g;
            int col = blockIdx.x*128 + wc*32 + nj*8 + tg*2;
            float b0 = RBIAS ? bias[r0] : 0.f;
            float b1 = RBIAS ? bias[r0+8] : 0.f;
            float2 v0 = make_float2(d[0]+b0, d[1]+b0);
            float2 v1 = make_float2(d[2]+b1, d[3]+b1);
            float2* p0 = reinterpret_cast<float2*>(C + (long)r0*N + col);
            float2* p1 = reinterpret_cast<float2*>(C + (long)(r0+8)*N + col);
            if (ACC) { float2 o0 = *p0, o1 = *p1; v0.x+=o0.x; v0.y+=o0.y; v1.x+=o1.x; v1.y+=o1.y; }
            if (RELU) { v0.x=fmaxf(v0.x,0.f); v0.y=fmaxf(v0.y,0.f); v1.x=fmaxf(v1.x,0.f); v1.y=fmaxf(v1.y,0.f); }
            *p0 = v0; *p1 = v1;
        }
    }
}

// ---------------------------------------------------------------------
// attn_fused (fp16 MMA) — unchanged (proven).
// ---------------------------------------------------------------------
#define QP 36
#define KP 36
#define VBP 68
#define PP 132

template<int MASK, bool CTX>
__global__ __launch_bounds__(256) void attn_fused(
    const float* __restrict__ Q, const float* __restrict__ Km,
    const float* __restrict__ Vm, float* __restrict__ P,
    float* __restrict__ Cctx,
    int Kdim, int lda, int ldb,
    long strA, long offHA, long strB, long offHB,
    int Hh, float scale, const int* __restrict__ tok, int tokStride)
{
    extern __shared__ unsigned sma[];
    unsigned* Qs = sma;
    unsigned* Ks = sma + 64*QP;
    unsigned* Vs = sma + 64*QP + 256*KP;
    unsigned* Ps = sma;
    __shared__ float red[64*4];

    const int tid = threadIdx.x, warp = tid >> 5, lane = tid & 31;
    const int g = lane >> 2, tg = lane & 3;
    const int wr = warp >> 2, wc = warp & 3;
    const int z = blockIdx.y;
    const int bb = z / Hh, hh = z - bb*Hh;
    const int rowTile = blockIdx.x;
    const int rowBase = rowTile * 64;

    const float* Qb = Q + (long)bb*strA + (long)hh*offHA + (long)rowBase*lda;
    const float* Kb = Km + (long)bb*strB + (long)hh*offHB;

    float acc[16][4];
    #pragma unroll
    for (int i = 0; i < 16; i++) { acc[i][0]=0.f; acc[i][1]=0.f; acc[i][2]=0.f; acc[i][3]=0.f; }

    for (int k0 = 0; k0 < Kdim; k0 += 64) {
        #pragma unroll
        for (int p = 0; p < 4; p++) {
            int idx = tid + p*256;
            int r = idx >> 4, c4 = idx & 15;
            float4 v = *reinterpret_cast<const float4*>(Qb + (long)r*lda + k0 + c4*4);
            uint2 w; w.x = pack_h2(v.x, v.y); w.y = pack_h2(v.z, v.w);
            *reinterpret_cast<uint2*>(&Qs[r*QP + c4*2]) = w;
        }
        #pragma unroll
        for (int p = 0; p < 16; p++) {
            int idx = tid + p*256;
            int r = idx >> 4, c4 = idx & 15;
            float4 v = *reinterpret_cast<const float4*>(Kb + (long)r*ldb + k0 + c4*4);
            uint2 w; w.x = pack_h2(v.x, v.y); w.y = pack_h2(v.z, v.w);
            *reinterpret_cast<uint2*>(&Ks[r*KP + c4*2]) = w;
        }
        if (CTX && k0 == 0) {
            const float* Vb = Vm + (long)bb*strB + (long)hh*offHB;
            #pragma unroll
            for (int p = 0; p < 8; p++) {
                int idx = tid + p*256;
                int r2 = idx >> 4, c4 = idx & 15;
                float4 v0 = *reinterpret_cast<const float4*>(Vb + (long)(2*r2  )*ldb + c4*4);
                float4 v1 = *reinterpret_cast<const float4*>(Vb + (long)(2*r2+1)*ldb + c4*4);
                uint4 w;
                w.x = pack_h2(v0.x, v1.x); w.y = pack_h2(v0.y, v1.y);
                w.z = pack_h2(v0.z, v1.z); w.w = pack_h2(v0.w, v1.w);
                *reinterpret_cast<uint4*>(&Vs[r2*VBP + c4*4]) = w;
            }
        }
        __syncthreads();
        #pragma unroll
        for (int kt = 0; kt < 4; kt++) {
            unsigned a[2][4], b[8][2];
            #pragma unroll
            for (int mi = 0; mi < 2; mi++) {
                int mb = wr*32 + mi*16;
                a[mi][0] = Qs[(mb+g  )*QP + kt*8 + tg];
                a[mi][1] = Qs[(mb+g+8)*QP + kt*8 + tg];
                a[mi][2] = Qs[(mb+g  )*QP + kt*8 + tg + 4];
                a[mi][3] = Qs[(mb+g+8)*QP + kt*8 + tg + 4];
            }
            #pragma unroll
            for (int nj = 0; nj < 8; nj++) {
                int nb = wc*64 + nj*8;
                b[nj][0] = Ks[(nb+g)*KP + kt*8 + tg];
                b[nj][1] = Ks[(nb+g)*KP + kt*8 + tg + 4];
            }
            #pragma unroll
            for (int mi = 0; mi < 2; mi++)
                #pragma unroll
                for (int nj = 0; nj < 8; nj++)
                    mma_f16(acc[mi*8+nj], a[mi][0],a[mi][1],a[mi][2],a[mi][3],
                            b[nj][0], b[nj][1]);
        }
        if (k0 + 64 < Kdim) __syncthreads();
    }

    #pragma unroll
    for (int mi = 0; mi < 2; mi++) {
        #pragma unroll
        for (int nj = 0; nj < 8; nj++) {
            float* d = acc[mi*8+nj];
            int col = wc*64 + nj*8 + tg*2;
            int lr0 = wr*32 + mi*16 + g;
            #pragma unroll
            for (int c = 0; c < 4; c++) {
                int gcol = col + (c & 1);
                int grow = rowBase + lr0 + ((c >> 1) * 8);
                float v = d[c] * scale;
                if (MASK == 1) {
                    if (tok[bb*tokStride + gcol] == 0 || gcol > grow) v = -1e9f;
                } else if (MASK == 2) {
                    if (tok[bb*tokStride + gcol] == 0) v = -1e9f;
                }
                d[c] = v;
            }
        }
    }

    float rmax[4];
    #pragma unroll
    for (int mi = 0; mi < 2; mi++) {
        float m0 = -1e30f, m1 = -1e30f;
        #pragma unroll
        for (int nj = 0; nj < 8; nj++) {
            float* d = acc[mi*8+nj];
            m0 = fmaxf(m0, fmaxf(d[0], d[1]));
            m1 = fmaxf(m1, fmaxf(d[2], d[3]));
        }
        rmax[mi*2+0] = m0; rmax[mi*2+1] = m1;
    }
    #pragma unroll
    for (int i = 0; i < 4; i++) {
        rmax[i] = fmaxf(rmax[i], __shfl_xor_sync(0xffffffffu, rmax[i], 1));
        rmax[i] = fmaxf(rmax[i], __shfl_xor_sync(0xffffffffu, rmax[i], 2));
    }
    if (tg == 0) {
        #pragma unroll
        for (int mi = 0; mi < 2; mi++) {
            red[(wr*32 + mi*16 + g    )*4 + wc] = rmax[mi*2+0];
            red[(wr*32 + mi*16 + g + 8)*4 + wc] = rmax[mi*2+1];
        }
    }
    __syncthreads();
    float fmax4[4];
    #pragma unroll
    for (int mi = 0; mi < 2; mi++) {
        int r0 = wr*32 + mi*16 + g, r1 = r0 + 8;
        fmax4[mi*2+0] = fmaxf(fmaxf(red[r0*4+0], red[r0*4+1]), fmaxf(red[r0*4+2], red[r0*4+3]));
        fmax4[mi*2+1] = fmaxf(fmaxf(red[r1*4+0], red[r1*4+1]), fmaxf(red[r1*4+2], red[r1*4+3]));
    }
    __syncthreads();

    float rsum[4] = {0.f, 0.f, 0.f, 0.f};
    #pragma unroll
    for (int mi = 0; mi < 2; mi++) {
        #pragma unroll
        for (int nj = 0; nj < 8; nj++) {
            float* d = acc[mi*8+nj];
            d[0] = __expf(d[0] - fmax4[mi*2+0]);
            d[1] = __expf(d[1] - fmax4[mi*2+0]);
            d[2] = __expf(d[2] - fmax4[mi*2+1]);
            d[3] = __expf(d[3] - fmax4[mi*2+1]);
            rsum[mi*2+0] += d[0] + d[1];
            rsum[mi*2+1] += d[2] + d[3];
        }
    }
    #pragma unroll
    for (int i = 0; i < 4; i++) {
        rsum[i] += __shfl_xor_sync(0xffffffffu, rsum[i], 1);
        rsum[i] += __shfl_xor_sync(0xffffffffu, rsum[i], 2);
    }
    if (tg == 0) {
        #pragma unroll
        for (int mi = 0; mi < 2; mi++) {
            red[(wr*32 + mi*16 + g    )*4 + wc] = rsum[mi*2+0];
            red[(wr*32 + mi*16 + g + 8)*4 + wc] = rsum[mi*2+1];
        }
    }
    __syncthreads();
    float rinv[4];
    #pragma unroll
    for (int mi = 0; mi < 2; mi++) {
        int r0 = wr*32 + mi*16 + g, r1 = r0 + 8;
        rinv[mi*2+0] = 1.f / (red[r0*4+0] + red[r0*4+1] + red[r0*4+2] + red[r0*4+3]);
        rinv[mi*2+1] = 1.f / (red[r1*4+0] + red[r1*4+1] + red[r1*4+2] + red[r1*4+3]);
    }

    float* Pb = P + (long)z * 65536L + (long)rowBase * 256;
    #pragma unroll
    for (int mi = 0; mi < 2; mi++) {
        #pragma unroll
        for (int nj = 0; nj < 8; nj++) {
            float* d = acc[mi*8+nj];
            int col = wc*64 + nj*8 + tg*2;
            int r0 = wr*32 + mi*16 + g;
            float p0 = d[0]*rinv[mi*2+0], p1 = d[1]*rinv[mi*2+0];
            float p2 = d[2]*rinv[mi*2+1], p3 = d[3]*rinv[mi*2+1];
            *reinterpret_cast<float2*>(Pb + (long)r0*256 + col) = make_float2(p0, p1);
            *reinterpret_cast<float2*>(Pb + (long)(r0+8)*256 + col) = make_float2(p2, p3);
            if (CTX) {
                int k2 = wc*32 + nj*4 + tg;
                Ps[r0*PP + k2]     = pack_h2(p0, p1);
                Ps[(r0+8)*PP + k2] = pack_h2(p2, p3);
            }
        }
    }

    if (CTX) {
        __syncthreads();
        float acc2[4][4];
        #pragma unroll
        for (int i = 0; i < 4; i++) { acc2[i][0]=0.f; acc2[i][1]=0.f; acc2[i][2]=0.f; acc2[i][3]=0.f; }
        #pragma unroll
        for (int kt = 0; kt < 16; kt++) {
            unsigned a[2][4], b[2][2];
            #pragma unroll
            for (int mi = 0; mi < 2; mi++) {
                int mb = wr*32 + mi*16;
                a[mi][0] = Ps[(mb+g  )*PP + kt*8 + tg];
                a[mi][1] = Ps[(mb+g+8)*PP + kt*8 + tg];
                a[mi][2] = Ps[(mb+g  )*PP + kt*8 + tg + 4];
                a[mi][3] = Ps[(mb+g+8)*PP + kt*8 + tg + 4];
            }
            #pragma unroll
            for (int nj = 0; nj < 2; nj++) {
                int nb = wc*16 + nj*8 + g;
                b[nj][0] = Vs[(kt*8 + tg    )*VBP + nb];
                b[nj][1] = Vs[(kt*8 + tg + 4)*VBP + nb];
            }
            #pragma unroll
            for (int mi = 0; mi < 2; mi++)
                #pragma unroll
                for (int nj = 0; nj < 2; nj++)
                    mma_f16(acc2[mi*2+nj], a[mi][0],a[mi][1],a[mi][2],a[mi][3],
                            b[nj][0], b[nj][1]);
        }
        float* Cb = Cctx + (long)bb*TT*DD + hh*64;
        #pragma unroll
        for (int mi = 0; mi < 2; mi++) {
            #pragma unroll
            for (int nj = 0; nj < 2; nj++) {
                float* d = acc2[mi*2+nj];
                int r0 = rowBase + wr*32 + mi*16 + g;
                int col = wc*16 + nj*8 + tg*2;
                *reinterpret_cast<float2*>(Cb + (long)r0*DD + col) = make_float2(d[0], d[1]);
                *reinterpret_cast<float2*>(Cb + (long)(r0+8)*DD + col) = make_float2(d[2], d[3]);
            }
        }
    }
}

// ---------------------------------------------------------------------
// add_ln: 128 threads/row, float4 loads. out = LN(a+b)*g + beta.
// ---------------------------------------------------------------------
__global__ __launch_bounds__(128) void add_ln(
    const float* __restrict__ a, const float* __restrict__ b,
    float* __restrict__ out, const float* __restrict__ g,
    const float* __restrict__ beta)
{
    long off = (long)blockIdx.x * DD;
    int t = threadIdx.x;
    int warp = t >> 5, lane = t & 31;
    float4 va = *reinterpret_cast<const float4*>(a + off + t*4);
    float4 vb = *reinterpret_cast<const float4*>(b + off + t*4);
    float4 v;
    v.x = va.x + vb.x; v.y = va.y + vb.y; v.z = va.z + vb.z; v.w = va.w + vb.w;
    __shared__ float ws[4], ws2[4];

    float s = v.x + v.y + v.z + v.w;
    #pragma unroll
    for (int o = 16; o > 0; o >>= 1) s += __shfl_xor_sync(0xffffffffu, s, o);
    if (lane == 0) ws[warp] = s;
    __syncthreads();
    float mu = (ws[0]+ws[1]+ws[2]+ws[3]) * (1.f/DD);

    float4 d;
    d.x = v.x - mu; d.y = v.y - mu; d.z = v.z - mu; d.w = v.w - mu;
    float q = d.x*d.x + d.y*d.y + d.z*d.z + d.w*d.w;
    #pragma unroll
    for (int o = 16; o > 0; o >>= 1) q += __shfl_xor_sync(0xffffffffu, q, o);
    if (lane == 0) ws2[warp] = q;
    __syncthreads();
    float rstd = rsqrtf((ws2[0]+ws2[1]+ws2[2]+ws2[3]) * (1.f/DD) + 1e-5f);

    float4 gg = g ? *reinterpret_cast<const float4*>(g + t*4)
                  : make_float4(1.f, 1.f, 1.f, 1.f);
    float4 bb = beta ? *reinterpret_cast<const float4*>(beta + t*4)
                     : make_float4(0.f, 0.f, 0.f, 0.f);
    float4 o;
    o.x = d.x * rstd * gg.x + bb.x;
    o.y = d.y * rstd * gg.y + bb.y;
    o.z = d.z * rstd * gg.z + bb.z;
    o.w = d.w * rstd * gg.w + bb.w;
    *reinterpret_cast<float4*>(out + off + t*4) = o;
}

__global__ void embed_pe(const int* __restrict__ dec,
                         const float* __restrict__ emb,
                         float* __restrict__ x)
{
    long idx = (long)blockIdx.x * blockDim.x + threadIdx.x;
    if (idx >= (long)BT*DD) return;
    int d  = (int)(idx % DD);
    long bt = idx / DD;
    int t  = (int)(bt % TT);
    int tokidx = dec[bt];
    int d2 = d & ~1;
    float div = expf(-logf(10000.f) * (float)d2 / (float)DD);
    float ang = (float)t * div;
    float pe = (d & 1) ? cosf(ang) : sinf(ang);
    x[idx] = emb[(long)tokidx*DD + d] + pe;
}

__global__ void add3(const float* __restrict__ a, const float* __restrict__ bias,
                     const float* __restrict__ c, float* __restrict__ out, long n)
{
    long i = (long)blockIdx.x * blockDim.x + threadIdx.x;
    if (i >= n) return;
    out[i] = a[i] + bias[i % DD] + c[i];
}

__global__ void copyk4(const float4* __restrict__ src, float4* __restrict__ dst, long n4)
{
    long i = (long)blockIdx.x * blockDim.x + threadIdx.x;
    if (i < n4) dst[i] = src[i];
}

// ---------------------------------------------------------------------
extern "C" void kernel_launch(void* const* d_in, const int* in_sizes, int n_in,
                              void* d_out, int out_size)
{
    const int*   dec     = (const int*)  d_in[0];
    const int*   enc     = (const int*)  d_in[1];
    const float* enc_out = (const float*)d_in[2];
    const float* ast_out = (const float*)d_in[3];
    const float* src_emb = (const float*)d_in[4];
    const float* ast_emb = (const float*)d_in[5];
    const float* emb     = (const float*)d_in[7];
    const float* attn_W  = (const float*)d_in[8];
    const float* ln_g    = (const float*)d_in[9];
    const float* ln_b    = (const float*)d_in[10];
    const float* W1      = (const float*)d_in[11];
    const float* W2      = (const float*)d_in[12];
    const float* conv_w  = (const float*)d_in[13];
    const float* conv_b  = (const float*)d_in[14];
    const float* mffnW   = (const float*)d_in[15];
    const float* mffnb   = (const float*)d_in[16];
    float* out = (float*)d_out;

    float *x,*t,*qkv,*c,*h,*multi,*ast1,*aste,*mm,*mmctx;
    cudaGetSymbolAddress((void**)&x,     g_x);
    cudaGetSymbolAddress((void**)&t,     g_t);
    cudaGetSymbolAddress((void**)&qkv,   g_qkv);
    cudaGetSymbolAddress((void**)&c,     g_c);
    cudaGetSymbolAddress((void**)&h,     g_h);
    cudaGetSymbolAddress((void**)&multi, g_multi);
    cudaGetSymbolAddress((void**)&ast1,  g_ast1);
    cudaGetSymbolAddress((void**)&aste,  g_aste);
    cudaGetSymbolAddress((void**)&mm,    g_mm);
    cudaGetSymbolAddress((void**)&mmctx, g_mmctx);

    const int GM_SMEM  = 2*BUFW*4;
    const int AT_SMEM  = (64*QP + 256*KP + 128*VBP)*4;
    const int MM_SMEM  = (64*QP + 256*KP)*4;
    cudaFuncSetAttribute((const void*)gemm2<false,false,false,false>, cudaFuncAttributeMaxDynamicSharedMemorySize, GM_SMEM);
    cudaFuncSetAttribute((const void*)gemm2<false,true ,false,false>, cudaFuncAttributeMaxDynamicSharedMemorySize, GM_SMEM);
    cudaFuncSetAttribute((const void*)gemm2<true ,false,false,false>, cudaFuncAttributeMaxDynamicSharedMemorySize, GM_SMEM);
    cudaFuncSetAttribute((const void*)gemm2<false,false,true ,true >, cudaFuncAttributeMaxDynamicSharedMemorySize, GM_SMEM);
    cudaFuncSetAttribute((const void*)attn_fused<0,false>, cudaFuncAttributeMaxDynamicSharedMemorySize, MM_SMEM);
    cudaFuncSetAttribute((const void*)attn_fused<0,true >, cudaFuncAttributeMaxDynamicSharedMemorySize, AT_SMEM);
    cudaFuncSetAttribute((const void*)attn_fused<1,true >, cudaFuncAttributeMaxDynamicSharedMemorySize, AT_SMEM);
    cudaFuncSetAttribute((const void*)attn_fused<2,true >, cudaFuncAttributeMaxDynamicSharedMemorySize, AT_SMEM);

    float* q = qkv;
    float* k = qkv + (long)BT*DD;
    float* v = qkv + 2L*BT*DD;

    // ---- fork: preamble on s2 ----
    cudaStream_t s2;
    cudaStreamCreate(&s2);
    cudaEvent_t evF, evJ;
    cudaEventCreateWithFlags(&evF, cudaEventDisableTiming);
    cudaEventCreateWithFlags(&evJ, cudaEventDisableTiming);
    cudaEventRecord(evF, 0);
    cudaStreamWaitEvent(s2, evF, 0);

    {
        dim3 gc(DD/128, SS/64, BB);
        gemm2<false,false,true,true><<<gc, 256, GM_SMEM, s2>>>(
            conv_w, conv_w, conv_w, 0L, ast_out, (long)NA*DD,
            ast1, (long)SS*DD, conv_b, SS, DD, NA);
        gemm2<false,false,true,true><<<gc, 256, GM_SMEM, s2>>>(
            conv_w, conv_w, conv_w, 0L, ast_emb, (long)NA*DD,
            aste, (long)SS*DD, conv_b, SS, DD, NA);
        dim3 gs(SS/64, BB);
        attn_fused<0,false><<<gs, 256, MM_SMEM, s2>>>(ast1, enc_out, nullptr, mm, nullptr,
            DD, DD, DD, (long)SS*DD, 0L, (long)SS*DD, 0L,
            1, 0.125f, nullptr, 0);
        dim3 gm(DD/128, SS/64, BB);
        gemm2<false,false,false,false><<<gm, 256, GM_SMEM, s2>>>(
            mm, mm, mm, (long)SS*SS, enc_out, (long)SS*DD,
            mmctx, (long)SS*DD, nullptr, SS, DD, SS);
        dim3 gp(DD/128, BT/64, 1);
        gemm2<false,false,false,false><<<gp, 256, GM_SMEM, s2>>>(
            src_emb, src_emb, src_emb, 0L, mffnW, 0L, h, 0L, nullptr, BT, DD, DD);
        gemm2<false,true ,false,false><<<gp, 256, GM_SMEM, s2>>>(
            aste, aste, aste, 0L, mffnW + DD*DD, 0L, h, 0L, nullptr, BT, DD, DD);
        long n = (long)BB*SS*DD;
        add3<<<(int)((n + 255)/256), 256, 0, s2>>>(h, mffnb, mmctx, multi, n);
    }
    cudaEventRecord(evJ, s2);

    // ---------------- main path ----------------
    embed_pe<<<(BT*DD + 255)/256, 256>>>(dec, emb, x);

    dim3 gQKV(DD/128, BT/64, 3);
    dim3 gProj(DD/128, BT/64, 1);
    dim3 gF1(DFF/128, BT/64, 1);
    dim3 gScore(TT/64, BB*HH);

    for (int l = 0; l < LL; l++) {
        for (int a = 0; a < 3; a++) {
            const float* W = attn_W + ((long)(l*3 + a) * 4) * DD * DD;
            const float* Wo = W + 3L*DD*DD;
            const float* xk = (a == 0) ? x : (a == 1 ? enc_out : multi);

            if (l == 0 && a == 2) cudaStreamWaitEvent(0, evJ, 0);

            gemm2<false,false,false,false><<<gQKV, 256, GM_SMEM>>>(
                x, xk, xk, 0L, W, (long)DD*DD, qkv, (long)BT*DD, nullptr, BT, DD, DD);

            long attnBase = (a == 0 ? SELF_OFF : (a == 1 ? ENC_OFF : AST_OFF))
                            + (long)l * BHTT;
            float* P = out + attnBase;

            if (a == 0)
                attn_fused<1,true><<<gScore, 256, AT_SMEM>>>(q, k, v, P, c,
                    DKK, DD, DD, (long)TT*DD, 64L, (long)TT*DD, 64L,
                    HH, 0.125f, dec, TT);
            else if (a == 1)
                attn_fused<2,true><<<gScore, 256, AT_SMEM>>>(q, k, v, P, c,
                    DKK, DD, DD, (long)TT*DD, 64L, (long)TT*DD, 64L,
                    HH, 0.125f, enc, SS);
            else
                attn_fused<0,true><<<gScore, 256, AT_SMEM>>>(q, k, v, P, c,
                    DKK, DD, DD, (long)TT*DD, 64L, (long)TT*DD, 64L,
                    HH, 0.125f, nullptr, 0);

            gemm2<false,false,false,false><<<gProj, 256, GM_SMEM>>>(
                c, c, c, 0L, Wo, 0L, t, 0L, nullptr, BT, DD, DD);
            add_ln<<<BT, 128>>>(t, x, x,
                ln_g + (long)(l*3 + a)*DD, ln_b + (long)(l*3 + a)*DD);
        }
        gemm2<true,false,false,false><<<gF1, 256, GM_SMEM>>>(
            x, x, x, 0L, W1 + (long)l*DD*DFF, 0L, h, 0L, nullptr, BT, DFF, DD);
        gemm2<false,false,false,false><<<gProj, 256, GM_SMEM>>>(
            h, h, h, 0L, W2 + (long)l*DFF*DD, 0L, t, 0L, nullptr, BT, DD, DFF);
        add_ln<<<BT, 128>>>(t, x, x, nullptr, nullptr);
    }

    copyk4<<<(BT*DD/4 + 255)/256, 256>>>(
        reinterpret_cast<const float4*>(x), reinterpret_cast<float4*>(out),
        (long)BT*DD/4);

    cudaStreamDestroy(s2);
    cudaEventDestroy(evF);
    cudaEventDestroy(evJ);
}

// round 13
// speedup vs baseline: 1.2354x; 1.0032x over previous
#include <cuda_runtime.h>
#include <cuda_fp16.h>
#include <math.h>

// Problem dims
#define BB 16
#define TT 256
#define SS 256
#define NA 300
#define DD 512
#define HH 8
#define DKK 64
#define DFF 2048
#define LL 6

#define BT (BB*TT)                 // 4096
#define BHTT ((long)BB*HH*TT*TT)   // 8388608

#define SELF_OFF 2097152L
#define ENC_OFF  (SELF_OFF + (long)LL*BHTT)
#define AST_OFF  (ENC_OFF  + (long)LL*BHTT)

// ------------- scratch -------------
__device__ float g_x[BT*DD];
__device__ float g_t[BT*DD];
__device__ float g_qkv[3*BT*DD];
__device__ float g_c[BT*DD];
__device__ float g_h[BT*DFF];
__device__ float g_multi[BB*SS*DD];
__device__ float g_ast1[BB*SS*DD];
__device__ float g_aste[BB*SS*DD];
__device__ float g_mm[BB*SS*SS];
__device__ float g_mmctx[BB*SS*DD];

// fp16 weights: attn (72 x 512x512) | W1 (6 x 512x2048) | W2 (6 x 2048x512)
#define WB_ATTN 0L
#define WB_W1   18874368L
#define WB_W2   25165824L
__device__ __half g_wb[31457280];

// ------------- helpers -------------
__device__ __forceinline__ unsigned pack_h2(float x, float y) {
    __half2 h = __floats2half2_rn(x, y);
    return *reinterpret_cast<unsigned*>(&h);
}
__device__ __forceinline__ void mma_f16(float* d,
    unsigned a0, unsigned a1, unsigned a2, unsigned a3,
    unsigned b0, unsigned b1)
{
    asm volatile(
        "mma.sync.aligned.m16n8k16.row.col.f32.f16.f16.f32 "
        "{%0,%1,%2,%3},{%4,%5,%6,%7},{%8,%9},{%0,%1,%2,%3};\n"
        : "+f"(d[0]), "+f"(d[1]), "+f"(d[2]), "+f"(d[3])
        : "r"(a0), "r"(a1), "r"(a2), "r"(a3), "r"(b0), "r"(b1));
}
__device__ __forceinline__ void ldsm_x4(unsigned& r0, unsigned& r1,
                                        unsigned& r2, unsigned& r3, unsigned addr)
{
    asm volatile("ldmatrix.sync.aligned.m8n8.x4.shared.b16 {%0,%1,%2,%3}, [%4];"
        : "=r"(r0), "=r"(r1), "=r"(r2), "=r"(r3) : "r"(addr));
}
__device__ __forceinline__ void ldsm_x4_t(unsigned& r0, unsigned& r1,
                                          unsigned& r2, unsigned& r3, unsigned addr)
{
    asm volatile("ldmatrix.sync.aligned.m8n8.x4.trans.shared.b16 {%0,%1,%2,%3}, [%4];"
        : "=r"(r0), "=r"(r1), "=r"(r2), "=r"(r3) : "r"(addr));
}

// f32 -> f16 elementwise (vectorized by 4)
__global__ void w2h(const float* __restrict__ in, __half* __restrict__ outp, long n4)
{
    long i = (long)blockIdx.x * blockDim.x + threadIdx.x;
    if (i >= n4) return;
    float4 v = reinterpret_cast<const float4*>(in)[i];
    uint2 w; w.x = pack_h2(v.x, v.y); w.y = pack_h2(v.z, v.w);
    *reinterpret_cast<uint2*>(outp + i*4) = w;
}

#define VP 20
#define WPB 68
#define BUFW (64*VP + 32*WPB)   // 3456 words

// ---------------------------------------------------------------------
// gemm2h (fp16 weights): C[M,N] = A[M,K](f32) @ B[K,N](f16), row-major.
// 64x128x32 tiles, double-buffered, 256 threads (warps 2x4, warp 32x32).
// A z-select + strA; B = B0 + z*strB; C = C0 + z*strC. K%32==0.
// ---------------------------------------------------------------------
template<bool RELU>
__global__ __launch_bounds__(256, 2) void gemm2h(
    const float* __restrict__ A0, const float* __restrict__ A1,
    const float* __restrict__ A2, long strA,
    const __half* __restrict__ B0, long strB,
    float* __restrict__ C0, long strC,
    int M, int N, int K)
{
    extern __shared__ unsigned smg[];

    const int tid = threadIdx.x, warp = tid >> 5, lane = tid & 31;
    const int g = lane >> 2, tg = lane & 3;
    const int wr = warp >> 2, wc = warp & 3;
    const int z = blockIdx.z;

    const float* A = ((z == 0) ? A0 : (z == 1 ? A1 : A2)) + (long)z * strA;
    const float* At = A + (long)blockIdx.y * 64 * K;
    const __half* Bt = B0 + (long)z * strB + blockIdx.x * 128;
    float* C = C0 + (long)z * strC;

    const int aR = tid >> 3;
    const int aC = (tid & 7) * 4;
    const int bR = tid >> 4;          // 0..15 (+16)
    const int bC8 = (tid & 15) * 8;   // half offset in row

    const int laneRow = (lane & 7) + ((lane >> 3) & 1) * 8;
    const int laneSeg = (lane >> 4) * 4;
    const unsigned vbase = (unsigned)__cvta_generic_to_shared(smg);
    const unsigned aLane = vbase + ((wr*32 + laneRow)*VP + laneSeg) * 4;
    const int kRow = lane & 15;
    const int nSel = lane >> 4;
    const unsigned bLane = vbase + (64*VP + kRow*WPB + wc*16 + nSel*4) * 4;

    float4 ra[2];
    uint4 rbh[2];
    #pragma unroll
    for (int p = 0; p < 2; p++)
        ra[p] = *reinterpret_cast<const float4*>(At + (long)(aR + p*32)*K + aC);
    #pragma unroll
    for (int p = 0; p < 2; p++)
        rbh[p] = *reinterpret_cast<const uint4*>(Bt + (long)(bR + p*16)*N + bC8);

    auto sts = [&](int buf) {
        unsigned* V = smg + buf*BUFW;
        unsigned* W = V + 64*VP;
        #pragma unroll
        for (int p = 0; p < 2; p++) {
            int m = aR + p*32;
            uint2 w;
            w.x = pack_h2(ra[p].x, ra[p].y);
            w.y = pack_h2(ra[p].z, ra[p].w);
            *reinterpret_cast<uint2*>(&V[m*VP + (aC >> 1)]) = w;
        }
        #pragma unroll
        for (int p = 0; p < 2; p++)
            *reinterpret_cast<uint4*>(&W[(bR + p*16)*WPB + (bC8 >> 1)]) = rbh[p];
    };
    sts(0);
    __syncthreads();

    float acc[8][4];
    #pragma unroll
    for (int i = 0; i < 8; i++) { acc[i][0]=0.f; acc[i][1]=0.f; acc[i][2]=0.f; acc[i][3]=0.f; }

    int cur = 0;
    for (int k0 = 0; k0 < K; k0 += 32) {
        const bool nxt = (k0 + 32) < K;
        if (nxt) {
            #pragma unroll
            for (int p = 0; p < 2; p++)
                ra[p] = *reinterpret_cast<const float4*>(At + (long)(aR + p*32)*K + k0 + 32 + aC);
            #pragma unroll
            for (int p = 0; p < 2; p++)
                rbh[p] = *reinterpret_cast<const uint4*>(Bt + (long)(k0 + 32 + bR + p*16)*N + bC8);
        }
        const unsigned aBuf = aLane + cur*BUFW*4;
        const unsigned bBuf = bLane + cur*BUFW*4;
        #pragma unroll
        for (int kt = 0; kt < 2; kt++) {
            unsigned a[2][4], b[4][2];
            #pragma unroll
            for (int mi = 0; mi < 2; mi++)
                ldsm_x4(a[mi][0], a[mi][1], a[mi][2], a[mi][3],
                        aBuf + mi*16*VP*4 + kt*32);
            {
                unsigned r0, r1, r2, r3;
                ldsm_x4_t(r0, r1, r2, r3, bBuf + kt*16*WPB*4);
                b[0][0]=r0; b[0][1]=r1; b[1][0]=r2; b[1][1]=r3;
                ldsm_x4_t(r0, r1, r2, r3, bBuf + kt*16*WPB*4 + 32);
                b[2][0]=r0; b[2][1]=r1; b[3][0]=r2; b[3][1]=r3;
            }
            #pragma unroll
            for (int mi = 0; mi < 2; mi++)
                #pragma unroll
                for (int nj = 0; nj < 4; nj++)
                    mma_f16(acc[mi*4+nj], a[mi][0],a[mi][1],a[mi][2],a[mi][3],
                            b[nj][0], b[nj][1]);
        }
        if (nxt) {
            sts(cur ^ 1);
            __syncthreads();
            cur ^= 1;
        }
    }

    #pragma unroll
    for (int mi = 0; mi < 2; mi++) {
        #pragma unroll
        for (int nj = 0; nj < 4; nj++) {
            float* d = acc[mi*4+nj];
            int r0 = blockIdx.y*64 + wr*32 + mi*16 + g;
            int col = blockIdx.x*128 + wc*32 + nj*8 + tg*2;
            float2 v0 = make_float2(d[0], d[1]);
            float2 v1 = make_float2(d[2], d[3]);
            if (RELU) {
                v0.x=fmaxf(v0.x,0.f); v0.y=fmaxf(v0.y,0.f);
                v1.x=fmaxf(v1.x,0.f); v1.y=fmaxf(v1.y,0.f);
            }
            *reinterpret_cast<float2*>(C + (long)r0*N + col) = v0;
            *reinterpret_cast<float2*>(C + (long)(r0+8)*N + col) = v1;
        }
    }
}

// ---------------------------------------------------------------------
// gemm2 (fp32 B) — preamble only (K=300 guard, bias, acc). Unchanged.
// ---------------------------------------------------------------------
template<bool RELU, bool ACC, bool RBIAS, bool KG>
__global__ __launch_bounds__(256, 2) void gemm2(
    const float* __restrict__ A0, const float* __restrict__ A1,
    const float* __restrict__ A2, long strA,
    const float* __restrict__ B0, long strB,
    float* __restrict__ C0, long strC,
    const float* __restrict__ bias,
    int M, int N, int K)
{
    extern __shared__ unsigned smg[];

    const int tid = threadIdx.x, warp = tid >> 5, lane = tid & 31;
    const int g = lane >> 2, tg = lane & 3;
    const int wr = warp >> 2, wc = warp & 3;
    const int z = blockIdx.z;

    const float* A = ((z == 0) ? A0 : (z == 1 ? A1 : A2)) + (long)z * strA;
    const float* At = A + (long)blockIdx.y * 64 * K;
    const float* Bt = B0 + (long)z * strB + blockIdx.x * 128;
    float* C = C0 + (long)z * strC;

    const int aR = tid >> 3;
    const int aC = (tid & 7) * 4;
    const int kp = tid >> 5;
    const int bC = (tid & 31) * 4;
    const int bw = (tid & 31) * 2;

    const int laneRow = (lane & 7) + ((lane >> 3) & 1) * 8;
    const int laneSeg = (lane >> 4) * 4;
    const unsigned vbase = (unsigned)__cvta_generic_to_shared(smg);
    const unsigned aLane = vbase + ((wr*32 + laneRow)*VP + laneSeg) * 4;
    const int kRow = lane & 15;
    const int nSel = lane >> 4;
    const unsigned bLane = vbase + (64*VP + kRow*WPB + wc*16 + nSel*4) * 4;

    float4 ra[2], rb[4];
    auto ldA = [&](int p, int k0) -> float4 {
        long row = aR + p*32;
        if (!KG || (k0 + aC + 4 <= K))
            return *reinterpret_cast<const float4*>(At + row*K + k0 + aC);
        float4 v = make_float4(0.f, 0.f, 0.f, 0.f);
        if (k0 + aC     < K) v.x = At[row*K + k0 + aC];
        if (k0 + aC + 1 < K) v.y = At[row*K + k0 + aC + 1];
        if (k0 + aC + 2 < K) v.z = At[row*K + k0 + aC + 2];
        if (k0 + aC + 3 < K) v.w = At[row*K + k0 + aC + 3];
        return v;
    };
    auto ldB = [&](int r, int k0) -> float4 {
        int row = k0 + r;
        if (!KG || row < K)
            return *reinterpret_cast<const float4*>(Bt + (long)row*N + bC);
        return make_float4(0.f, 0.f, 0.f, 0.f);
    };

    #pragma unroll
    for (int p = 0; p < 2; p++) ra[p] = ldA(p, 0);
    rb[0] = ldB(2*kp,      0);
    rb[1] = ldB(2*kp + 1,  0);
    rb[2] = ldB(2*kp + 16, 0);
    rb[3] = ldB(2*kp + 17, 0);

    auto sts = [&](int buf) {
        unsigned* V = smg + buf*BUFW;
        unsigned* W = V + 64*VP;
        #pragma unroll
        for (int p = 0; p < 2; p++) {
            int m = aR + p*32;
            uint2 w;
            w.x = pack_h2(ra[p].x, ra[p].y);
            w.y = pack_h2(ra[p].z, ra[p].w);
            *reinterpret_cast<uint2*>(&V[m*VP + (aC >> 1)]) = w;
        }
        {
            uint2 w;
            w.x = pack_h2(rb[0].x, rb[0].y); w.y = pack_h2(rb[0].z, rb[0].w);
            *reinterpret_cast<uint2*>(&W[(2*kp     )*WPB + bw]) = w;
            w.x = pack_h2(rb[1].x, rb[1].y); w.y = pack_h2(rb[1].z, rb[1].w);
            *reinterpret_cast<uint2*>(&W[(2*kp + 1 )*WPB + bw]) = w;
            w.x = pack_h2(rb[2].x, rb[2].y); w.y = pack_h2(rb[2].z, rb[2].w);
            *reinterpret_cast<uint2*>(&W[(2*kp + 16)*WPB + bw]) = w;
            w.x = pack_h2(rb[3].x, rb[3].y); w.y = pack_h2(rb[3].z, rb[3].w);
            *reinterpret_cast<uint2*>(&W[(2*kp + 17)*WPB + bw]) = w;
        }
    };
    sts(0);
    __syncthreads();

    float acc[8][4];
    #pragma unroll
    for (int i = 0; i < 8; i++) { acc[i][0]=0.f; acc[i][1]=0.f; acc[i][2]=0.f; acc[i][3]=0.f; }

    int cur = 0;
    for (int k0 = 0; k0 < K; k0 += 32) {
        const bool nxt = (k0 + 32) < K;
        if (nxt) {
            #pragma unroll
            for (int p = 0; p < 2; p++) ra[p] = ldA(p, k0 + 32);
            rb[0] = ldB(2*kp,      k0 + 32);
            rb[1] = ldB(2*kp + 1,  k0 + 32);
            rb[2] = ldB(2*kp + 16, k0 + 32);
            rb[3] = ldB(2*kp + 17, k0 + 32);
        }
        const unsigned aBuf = aLane + cur*BUFW*4;
        const unsigned bBuf = bLane + cur*BUFW*4;
        #pragma unroll
        for (int kt = 0; kt < 2; kt++) {
            unsigned a[2][4], b[4][2];
            #pragma unroll
            for (int mi = 0; mi < 2; mi++)
                ldsm_x4(a[mi][0], a[mi][1], a[mi][2], a[mi][3],
                        aBuf + mi*16*VP*4 + kt*32);
            {
                unsigned r0, r1, r2, r3;
                ldsm_x4_t(r0, r1, r2, r3, bBuf + kt*16*WPB*4);
                b[0][0]=r0; b[0][1]=r1; b[1][0]=r2; b[1][1]=r3;
                ldsm_x4_t(r0, r1, r2, r3, bBuf + kt*16*WPB*4 + 32);
                b[2][0]=r0; b[2][1]=r1; b[3][0]=r2; b[3][1]=r3;
            }
            #pragma unroll
            for (int mi = 0; mi < 2; mi++)
                #pragma unroll
                for (int nj = 0; nj < 4; nj++)
                    mma_f16(acc[mi*4+nj], a[mi][0],a[mi][1],a[mi][2],a[mi][3],
                            b[nj][0], b[nj][1]);
        }
        if (nxt) {
            sts(cur ^ 1);
            __syncthreads();
            cur ^= 1;
        }
    }

    #pragma unroll
    for (int mi = 0; mi < 2; mi++) {
        #pragma unroll
        for (int nj = 0; nj < 4; nj++) {
            float* d = acc[mi*4+nj];
            int r0 = blockIdx.y*64 + wr*32 + mi*16 + g;
            int col = blockIdx.x*128 + wc*32 + nj*8 + tg*2;
            float b0 = RBIAS ? bias[r0] : 0.f;
            float b1 = RBIAS ? bias[r0+8] : 0.f;
            float2 v0 = make_float2(d[0]+b0, d[1]+b0);
            float2 v1 = make_float2(d[2]+b1, d[3]+b1);
            float2* p0 = reinterpret_cast<float2*>(C + (long)r0*N + col);
            float2* p1 = reinterpret_cast<float2*>(C + (long)(r0+8)*N + col);
            if (ACC) { float2 o0 = *p0, o1 = *p1; v0.x+=o0.x; v0.y+=o0.y; v1.x+=o1.x; v1.y+=o1.y; }
            if (RELU) { v0.x=fmaxf(v0.x,0.f); v0.y=fmaxf(v0.y,0.f); v1.x=fmaxf(v1.x,0.f); v1.y=fmaxf(v1.y,0.f); }
            *p0 = v0; *p1 = v1;
        }
    }
}

// ---------------------------------------------------------------------
// attn_fused (fp16 MMA) — unchanged (proven).
// ---------------------------------------------------------------------
#define QP 36
#define KP 36
#define VBP 68
#define PP 132

template<int MASK, bool CTX>
__global__ __launch_bounds__(256) void attn_fused(
    const float* __restrict__ Q, const float* __restrict__ Km,
    const float* __restrict__ Vm, float* __restrict__ P,
    float* __restrict__ Cctx,
    int Kdim, int lda, int ldb,
    long strA, long offHA, long strB, long offHB,
    int Hh, float scale, const int* __restrict__ tok, int tokStride)
{
    extern __shared__ unsigned sma[];
    unsigned* Qs = sma;
    unsigned* Ks = sma + 64*QP;
    unsigned* Vs = sma + 64*QP + 256*KP;
    unsigned* Ps = sma;
    __shared__ float red[64*4];

    const int tid = threadIdx.x, warp = tid >> 5, lane = tid & 31;
    const int g = lane >> 2, tg = lane & 3;
    const int wr = warp >> 2, wc = warp & 3;
    const int z = blockIdx.y;
    const int bb = z / Hh, hh = z - bb*Hh;
    const int rowTile = blockIdx.x;
    const int rowBase = rowTile * 64;

    const float* Qb = Q + (long)bb*strA + (long)hh*offHA + (long)rowBase*lda;
    const float* Kb = Km + (long)bb*strB + (long)hh*offHB;

    float acc[16][4];
    #pragma unroll
    for (int i = 0; i < 16; i++) { acc[i][0]=0.f; acc[i][1]=0.f; acc[i][2]=0.f; acc[i][3]=0.f; }

    for (int k0 = 0; k0 < Kdim; k0 += 64) {
        #pragma unroll
        for (int p = 0; p < 4; p++) {
            int idx = tid + p*256;
            int r = idx >> 4, c4 = idx & 15;
            float4 v = *reinterpret_cast<const float4*>(Qb + (long)r*lda + k0 + c4*4);
            uint2 w; w.x = pack_h2(v.x, v.y); w.y = pack_h2(v.z, v.w);
            *reinterpret_cast<uint2*>(&Qs[r*QP + c4*2]) = w;
        }
        #pragma unroll
        for (int p = 0; p < 16; p++) {
            int idx = tid + p*256;
            int r = idx >> 4, c4 = idx & 15;
            float4 v = *reinterpret_cast<const float4*>(Kb + (long)r*ldb + k0 + c4*4);
            uint2 w; w.x = pack_h2(v.x, v.y); w.y = pack_h2(v.z, v.w);
            *reinterpret_cast<uint2*>(&Ks[r*KP + c4*2]) = w;
        }
        if (CTX && k0 == 0) {
            const float* Vb = Vm + (long)bb*strB + (long)hh*offHB;
            #pragma unroll
            for (int p = 0; p < 8; p++) {
                int idx = tid + p*256;
                int r2 = idx >> 4, c4 = idx & 15;
                float4 v0 = *reinterpret_cast<const float4*>(Vb + (long)(2*r2  )*ldb + c4*4);
                float4 v1 = *reinterpret_cast<const float4*>(Vb + (long)(2*r2+1)*ldb + c4*4);
                uint4 w;
                w.x = pack_h2(v0.x, v1.x); w.y = pack_h2(v0.y, v1.y);
                w.z = pack_h2(v0.z, v1.z); w.w = pack_h2(v0.w, v1.w);
                *reinterpret_cast<uint4*>(&Vs[r2*VBP + c4*4]) = w;
            }
        }
        __syncthreads();
        #pragma unroll
        for (int kt = 0; kt < 4; kt++) {
            unsigned a[2][4], b[8][2];
            #pragma unroll
            for (int mi = 0; mi < 2; mi++) {
                int mb = wr*32 + mi*16;
                a[mi][0] = Qs[(mb+g  )*QP + kt*8 + tg];
                a[mi][1] = Qs[(mb+g+8)*QP + kt*8 + tg];
                a[mi][2] = Qs[(mb+g  )*QP + kt*8 + tg + 4];
                a[mi][3] = Qs[(mb+g+8)*QP + kt*8 + tg + 4];
            }
            #pragma unroll
            for (int nj = 0; nj < 8; nj++) {
                int nb = wc*64 + nj*8;
                b[nj][0] = Ks[(nb+g)*KP + kt*8 + tg];
                b[nj][1] = Ks[(nb+g)*KP + kt*8 + tg + 4];
            }
            #pragma unroll
            for (int mi = 0; mi < 2; mi++)
                #pragma unroll
                for (int nj = 0; nj < 8; nj++)
                    mma_f16(acc[mi*8+nj], a[mi][0],a[mi][1],a[mi][2],a[mi][3],
                            b[nj][0], b[nj][1]);
        }
        if (k0 + 64 < Kdim) __syncthreads();
    }

    #pragma unroll
    for (int mi = 0; mi < 2; mi++) {
        #pragma unroll
        for (int nj = 0; nj < 8; nj++) {
            float* d = acc[mi*8+nj];
            int col = wc*64 + nj*8 + tg*2;
            int lr0 = wr*32 + mi*16 + g;
            #pragma unroll
            for (int c = 0; c < 4; c++) {
                int gcol = col + (c & 1);
                int grow = rowBase + lr0 + ((c >> 1) * 8);
                float v = d[c] * scale;
                if (MASK == 1) {
                    if (tok[bb*tokStride + gcol] == 0 || gcol > grow) v = -1e9f;
                } else if (MASK == 2) {
                    if (tok[bb*tokStride + gcol] == 0) v = -1e9f;
                }
                d[c] = v;
            }
        }
    }

    float rmax[4];
    #pragma unroll
    for (int mi = 0; mi < 2; mi++) {
        float m0 = -1e30f, m1 = -1e30f;
        #pragma unroll
        for (int nj = 0; nj < 8; nj++) {
            float* d = acc[mi*8+nj];
            m0 = fmaxf(m0, fmaxf(d[0], d[1]));
            m1 = fmaxf(m1, fmaxf(d[2], d[3]));
        }
        rmax[mi*2+0] = m0; rmax[mi*2+1] = m1;
    }
    #pragma unroll
    for (int i = 0; i < 4; i++) {
        rmax[i] = fmaxf(rmax[i], __shfl_xor_sync(0xffffffffu, rmax[i], 1));
        rmax[i] = fmaxf(rmax[i], __shfl_xor_sync(0xffffffffu, rmax[i], 2));
    }
    if (tg == 0) {
        #pragma unroll
        for (int mi = 0; mi < 2; mi++) {
            red[(wr*32 + mi*16 + g    )*4 + wc] = rmax[mi*2+0];
            red[(wr*32 + mi*16 + g + 8)*4 + wc] = rmax[mi*2+1];
        }
    }
    __syncthreads();
    float fmax4[4];
    #pragma unroll
    for (int mi = 0; mi < 2; mi++) {
        int r0 = wr*32 + mi*16 + g, r1 = r0 + 8;
        fmax4[mi*2+0] = fmaxf(fmaxf(red[r0*4+0], red[r0*4+1]), fmaxf(red[r0*4+2], red[r0*4+3]));
        fmax4[mi*2+1] = fmaxf(fmaxf(red[r1*4+0], red[r1*4+1]), fmaxf(red[r1*4+2], red[r1*4+3]));
    }
    __syncthreads();

    float rsum[4] = {0.f, 0.f, 0.f, 0.f};
    #pragma unroll
    for (int mi = 0; mi < 2; mi++) {
        #pragma unroll
        for (int nj = 0; nj < 8; nj++) {
            float* d = acc[mi*8+nj];
            d[0] = __expf(d[0] - fmax4[mi*2+0]);
            d[1] = __expf(d[1] - fmax4[mi*2+0]);
            d[2] = __expf(d[2] - fmax4[mi*2+1]);
            d[3] = __expf(d[3] - fmax4[mi*2+1]);
            rsum[mi*2+0] += d[0] + d[1];
            rsum[mi*2+1] += d[2] + d[3];
        }
    }
    #pragma unroll
    for (int i = 0; i < 4; i++) {
        rsum[i] += __shfl_xor_sync(0xffffffffu, rsum[i], 1);
        rsum[i] += __shfl_xor_sync(0xffffffffu, rsum[i], 2);
    }
    if (tg == 0) {
        #pragma unroll
        for (int mi = 0; mi < 2; mi++) {
            red[(wr*32 + mi*16 + g    )*4 + wc] = rsum[mi*2+0];
            red[(wr*32 + mi*16 + g + 8)*4 + wc] = rsum[mi*2+1];
        }
    }
    __syncthreads();
    float rinv[4];
    #pragma unroll
    for (int mi = 0; mi < 2; mi++) {
        int r0 = wr*32 + mi*16 + g, r1 = r0 + 8;
        rinv[mi*2+0] = 1.f / (red[r0*4+0] + red[r0*4+1] + red[r0*4+2] + red[r0*4+3]);
        rinv[mi*2+1] = 1.f / (red[r1*4+0] + red[r1*4+1] + red[r1*4+2] + red[r1*4+3]);
    }

    float* Pb = P + (long)z * 65536L + (long)rowBase * 256;
    #pragma unroll
    for (int mi = 0; mi < 2; mi++) {
        #pragma unroll
        for (int nj = 0; nj < 8; nj++) {
            float* d = acc[mi*8+nj];
            int col = wc*64 + nj*8 + tg*2;
            int r0 = wr*32 + mi*16 + g;
            float p0 = d[0]*rinv[mi*2+0], p1 = d[1]*rinv[mi*2+0];
            float p2 = d[2]*rinv[mi*2+1], p3 = d[3]*rinv[mi*2+1];
            *reinterpret_cast<float2*>(Pb + (long)r0*256 + col) = make_float2(p0, p1);
            *reinterpret_cast<float2*>(Pb + (long)(r0+8)*256 + col) = make_float2(p2, p3);
            if (CTX) {
                int k2 = wc*32 + nj*4 + tg;
                Ps[r0*PP + k2]     = pack_h2(p0, p1);
                Ps[(r0+8)*PP + k2] = pack_h2(p2, p3);
            }
        }
    }

    if (CTX) {
        __syncthreads();
        float acc2[4][4];
        #pragma unroll
        for (int i = 0; i < 4; i++) { acc2[i][0]=0.f; acc2[i][1]=0.f; acc2[i][2]=0.f; acc2[i][3]=0.f; }
        #pragma unroll
        for (int kt = 0; kt < 16; kt++) {
            unsigned a[2][4], b[2][2];
            #pragma unroll
            for (int mi = 0; mi < 2; mi++) {
                int mb = wr*32 + mi*16;
                a[mi][0] = Ps[(mb+g  )*PP + kt*8 + tg];
                a[mi][1] = Ps[(mb+g+8)*PP + kt*8 + tg];
                a[mi][2] = Ps[(mb+g  )*PP + kt*8 + tg + 4];
                a[mi][3] = Ps[(mb+g+8)*PP + kt*8 + tg + 4];
            }
            #pragma unroll
            for (int nj = 0; nj < 2; nj++) {
                int nb = wc*16 + nj*8 + g;
                b[nj][0] = Vs[(kt*8 + tg    )*VBP + nb];
                b[nj][1] = Vs[(kt*8 + tg + 4)*VBP + nb];
            }
            #pragma unroll
            for (int mi = 0; mi < 2; mi++)
                #pragma unroll
                for (int nj = 0; nj < 2; nj++)
                    mma_f16(acc2[mi*2+nj], a[mi][0],a[mi][1],a[mi][2],a[mi][3],
                            b[nj][0], b[nj][1]);
        }
        float* Cb = Cctx + (long)bb*TT*DD + hh*64;
        #pragma unroll
        for (int mi = 0; mi < 2; mi++) {
            #pragma unroll
            for (int nj = 0; nj < 2; nj++) {
                float* d = acc2[mi*2+nj];
                int r0 = rowBase + wr*32 + mi*16 + g;
                int col = wc*16 + nj*8 + tg*2;
                *reinterpret_cast<float2*>(Cb + (long)r0*DD + col) = make_float2(d[0], d[1]);
                *reinterpret_cast<float2*>(Cb + (long)(r0+8)*DD + col) = make_float2(d[2], d[3]);
            }
        }
    }
}

// ---------------------------------------------------------------------
__global__ __launch_bounds__(128) void add_ln(
    const float* __restrict__ a, const float* __restrict__ b,
    float* __restrict__ out, const float* __restrict__ g,
    const float* __restrict__ beta)
{
    long off = (long)blockIdx.x * DD;
    int t = threadIdx.x;
    int warp = t >> 5, lane = t & 31;
    float4 va = *reinterpret_cast<const float4*>(a + off + t*4);
    float4 vb = *reinterpret_cast<const float4*>(b + off + t*4);
    float4 v;
    v.x = va.x + vb.x; v.y = va.y + vb.y; v.z = va.z + vb.z; v.w = va.w + vb.w;
    __shared__ float ws[4], ws2[4];

    float s = v.x + v.y + v.z + v.w;
    #pragma unroll
    for (int o = 16; o > 0; o >>= 1) s += __shfl_xor_sync(0xffffffffu, s, o);
    if (lane == 0) ws[warp] = s;
    __syncthreads();
    float mu = (ws[0]+ws[1]+ws[2]+ws[3]) * (1.f/DD);

    float4 d;
    d.x = v.x - mu; d.y = v.y - mu; d.z = v.z - mu; d.w = v.w - mu;
    float q = d.x*d.x + d.y*d.y + d.z*d.z + d.w*d.w;
    #pragma unroll
    for (int o = 16; o > 0; o >>= 1) q += __shfl_xor_sync(0xffffffffu, q, o);
    if (lane == 0) ws2[warp] = q;
    __syncthreads();
    float rstd = rsqrtf((ws2[0]+ws2[1]+ws2[2]+ws2[3]) * (1.f/DD) + 1e-5f);

    float4 gg = g ? *reinterpret_cast<const float4*>(g + t*4)
                  : make_float4(1.f, 1.f, 1.f, 1.f);
    float4 bb = beta ? *reinterpret_cast<const float4*>(beta + t*4)
                     : make_float4(0.f, 0.f, 0.f, 0.f);
    float4 o;
    o.x = d.x * rstd * gg.x + bb.x;
    o.y = d.y * rstd * gg.y + bb.y;
    o.z = d.z * rstd * gg.z + bb.z;
    o.w = d.w * rstd * gg.w + bb.w;
    *reinterpret_cast<float4*>(out + off + t*4) = o;
}

__global__ void embed_pe(const int* __restrict__ dec,
                         const float* __restrict__ emb,
                         float* __restrict__ x)
{
    long idx = (long)blockIdx.x * blockDim.x + threadIdx.x;
    if (idx >= (long)BT*DD) return;
    int d  = (int)(idx % DD);
    long bt = idx / DD;
    int t  = (int)(bt % TT);
    int tokidx = dec[bt];
    int d2 = d & ~1;
    float div = expf(-logf(10000.f) * (float)d2 / (float)DD);
    float ang = (float)t * div;
    float pe = (d & 1) ? cosf(ang) : sinf(ang);
    x[idx] = emb[(long)tokidx*DD + d] + pe;
}

__global__ void add3(const float* __restrict__ a, const float* __restrict__ bias,
                     const float* __restrict__ c, float* __restrict__ out, long n)
{
    long i = (long)blockIdx.x * blockDim.x + threadIdx.x;
    if (i >= n) return;
    out[i] = a[i] + bias[i % DD] + c[i];
}

__global__ void copyk4(const float4* __restrict__ src, float4* __restrict__ dst, long n4)
{
    long i = (long)blockIdx.x * blockDim.x + threadIdx.x;
    if (i < n4) dst[i] = src[i];
}

// ---------------------------------------------------------------------
extern "C" void kernel_launch(void* const* d_in, const int* in_sizes, int n_in,
                              void* d_out, int out_size)
{
    const int*   dec     = (const int*)  d_in[0];
    const int*   enc     = (const int*)  d_in[1];
    const float* enc_out = (const float*)d_in[2];
    const float* ast_out = (const float*)d_in[3];
    const float* src_emb = (const float*)d_in[4];
    const float* ast_emb = (const float*)d_in[5];
    const float* emb     = (const float*)d_in[7];
    const float* attn_W  = (const float*)d_in[8];
    const float* ln_g    = (const float*)d_in[9];
    const float* ln_b    = (const float*)d_in[10];
    const float* W1      = (const float*)d_in[11];
    const float* W2      = (const float*)d_in[12];
    const float* conv_w  = (const float*)d_in[13];
    const float* conv_b  = (const float*)d_in[14];
    const float* mffnW   = (const float*)d_in[15];
    const float* mffnb   = (const float*)d_in[16];
    float* out = (float*)d_out;

    float *x,*t,*qkv,*c,*h,*multi,*ast1,*aste,*mm,*mmctx;
    __half* wb;
    cudaGetSymbolAddress((void**)&x,     g_x);
    cudaGetSymbolAddress((void**)&t,     g_t);
    cudaGetSymbolAddress((void**)&qkv,   g_qkv);
    cudaGetSymbolAddress((void**)&c,     g_c);
    cudaGetSymbolAddress((void**)&h,     g_h);
    cudaGetSymbolAddress((void**)&multi, g_multi);
    cudaGetSymbolAddress((void**)&ast1,  g_ast1);
    cudaGetSymbolAddress((void**)&aste,  g_aste);
    cudaGetSymbolAddress((void**)&mm,    g_mm);
    cudaGetSymbolAddress((void**)&mmctx, g_mmctx);
    cudaGetSymbolAddress((void**)&wb,    g_wb);

    const int GM_SMEM  = 2*BUFW*4;
    const int AT_SMEM  = (64*QP + 256*KP + 128*VBP)*4;
    const int MM_SMEM  = (64*QP + 256*KP)*4;
    cudaFuncSetAttribute((const void*)gemm2<false,false,false,false>, cudaFuncAttributeMaxDynamicSharedMemorySize, GM_SMEM);
    cudaFuncSetAttribute((const void*)gemm2<false,true ,false,false>, cudaFuncAttributeMaxDynamicSharedMemorySize, GM_SMEM);
    cudaFuncSetAttribute((const void*)gemm2<false,false,true ,true >, cudaFuncAttributeMaxDynamicSharedMemorySize, GM_SMEM);
    cudaFuncSetAttribute((const void*)gemm2h<false>, cudaFuncAttributeMaxDynamicSharedMemorySize, GM_SMEM);
    cudaFuncSetAttribute((const void*)gemm2h<true >, cudaFuncAttributeMaxDynamicSharedMemorySize, GM_SMEM);
    cudaFuncSetAttribute((const void*)attn_fused<0,false>, cudaFuncAttributeMaxDynamicSharedMemorySize, MM_SMEM);
    cudaFuncSetAttribute((const void*)attn_fused<0,true >, cudaFuncAttributeMaxDynamicSharedMemorySize, AT_SMEM);
    cudaFuncSetAttribute((const void*)attn_fused<1,true >, cudaFuncAttributeMaxDynamicSharedMemorySize, AT_SMEM);
    cudaFuncSetAttribute((const void*)attn_fused<2,true >, cudaFuncAttributeMaxDynamicSharedMemorySize, AT_SMEM);

    float* q = qkv;
    float* k = qkv + (long)BT*DD;
    float* v = qkv + 2L*BT*DD;

    // ---- weight conversion to fp16 (main stream; feeds layer 0) ----
    w2h<<<(int)((18874368/4 + 255)/256), 256>>>(attn_W, wb + WB_ATTN, 18874368/4);
    w2h<<<(int)((6291456/4  + 255)/256), 256>>>(W1,     wb + WB_W1,   6291456/4);
    w2h<<<(int)((6291456/4  + 255)/256), 256>>>(W2,     wb + WB_W2,   6291456/4);

    // ---- fork: preamble on s2 ----
    cudaStream_t s2;
    cudaStreamCreate(&s2);
    cudaEvent_t evF, evJ;
    cudaEventCreateWithFlags(&evF, cudaEventDisableTiming);
    cudaEventCreateWithFlags(&evJ, cudaEventDisableTiming);
    cudaEventRecord(evF, 0);
    cudaStreamWaitEvent(s2, evF, 0);

    {
        dim3 gc(DD/128, SS/64, BB);
        gemm2<false,false,true,true><<<gc, 256, GM_SMEM, s2>>>(
            conv_w, conv_w, conv_w, 0L, ast_out, (long)NA*DD,
            ast1, (long)SS*DD, conv_b, SS, DD, NA);
        gemm2<false,false,true,true><<<gc, 256, GM_SMEM, s2>>>(
            conv_w, conv_w, conv_w, 0L, ast_emb, (long)NA*DD,
            aste, (long)SS*DD, conv_b, SS, DD, NA);
        dim3 gs(SS/64, BB);
        attn_fused<0,false><<<gs, 256, MM_SMEM, s2>>>(ast1, enc_out, nullptr, mm, nullptr,
            DD, DD, DD, (long)SS*DD, 0L, (long)SS*DD, 0L,
            1, 0.125f, nullptr, 0);
        dim3 gm(DD/128, SS/64, BB);
        gemm2<false,false,false,false><<<gm, 256, GM_SMEM, s2>>>(
            mm, mm, mm, (long)SS*SS, enc_out, (long)SS*DD,
            mmctx, (long)SS*DD, nullptr, SS, DD, SS);
        dim3 gp(DD/128, BT/64, 1);
        gemm2<false,false,false,false><<<gp, 256, GM_SMEM, s2>>>(
            src_emb, src_emb, src_emb, 0L, mffnW, 0L, h, 0L, nullptr, BT, DD, DD);
        gemm2<false,true ,false,false><<<gp, 256, GM_SMEM, s2>>>(
            aste, aste, aste, 0L, mffnW + DD*DD, 0L, h, 0L, nullptr, BT, DD, DD);
        long n = (long)BB*SS*DD;
        add3<<<(int)((n + 255)/256), 256, 0, s2>>>(h, mffnb, mmctx, multi, n);
    }
    cudaEventRecord(evJ, s2);

    // ---------------- main path ----------------
    embed_pe<<<(BT*DD + 255)/256, 256>>>(dec, emb, x);

    dim3 gQKV(DD/128, BT/64, 3);
    dim3 gProj(DD/128, BT/64, 1);
    dim3 gF1(DFF/128, BT/64, 1);
    dim3 gScore(TT/64, BB*HH);

    for (int l = 0; l < LL; l++) {
        for (int a = 0; a < 3; a++) {
            const __half* wqkv = wb + WB_ATTN + (long)((l*3 + a)*4) * 262144;
            const __half* wo   = wb + WB_ATTN + (long)((l*3 + a)*4 + 3) * 262144;
            const float* xk = (a == 0) ? x : (a == 1 ? enc_out : multi);

            if (l == 0 && a == 2) cudaStreamWaitEvent(0, evJ, 0);

            gemm2h<false><<<gQKV, 256, GM_SMEM>>>(
                x, xk, xk, 0L, wqkv, 262144L, qkv, (long)BT*DD, BT, DD, DD);

            long attnBase = (a == 0 ? SELF_OFF : (a == 1 ? ENC_OFF : AST_OFF))
                            + (long)l * BHTT;
            float* P = out + attnBase;

            if (a == 0)
                attn_fused<1,true><<<gScore, 256, AT_SMEM>>>(q, k, v, P, c,
                    DKK, DD, DD, (long)TT*DD, 64L, (long)TT*DD, 64L,
                    HH, 0.125f, dec, TT);
            else if (a == 1)
                attn_fused<2,true><<<gScore, 256, AT_SMEM>>>(q, k, v, P, c,
                    DKK, DD, DD, (long)TT*DD, 64L, (long)TT*DD, 64L,
                    HH, 0.125f, enc, SS);
            else
                attn_fused<0,true><<<gScore, 256, AT_SMEM>>>(q, k, v, P, c,
                    DKK, DD, DD, (long)TT*DD, 64L, (long)TT*DD, 64L,
                    HH, 0.125f, nullptr, 0);

            gemm2h<false><<<gProj, 256, GM_SMEM>>>(
                c, c, c, 0L, wo, 0L, t, 0L, BT, DD, DD);
            add_ln<<<BT, 128>>>(t, x, x,
                ln_g + (long)(l*3 + a)*DD, ln_b + (long)(l*3 + a)*DD);
        }
        gemm2h<true><<<gF1, 256, GM_SMEM>>>(
            x, x, x, 0L, wb + WB_W1 + (long)l*1048576, 0L, h, 0L, BT, DFF, DD);
        gemm2h<false><<<gProj, 256, GM_SMEM>>>(
            h, h, h, 0L, wb + WB_W2 + (long)l*1048576, 0L, t, 0L, BT, DD, DFF);
        add_ln<<<BT, 128>>>(t, x, x, nullptr, nullptr);
    }

    copyk4<<<(BT*DD/4 + 255)/256, 256>>>(
        reinterpret_cast<const float4*>(x), reinterpret_cast<float4*>(out),
        (long)BT*DD/4);

    cudaStreamDestroy(s2);
    cudaEventDestroy(evF);
    cudaEventDestroy(evJ);
}

// round 15
// speedup vs baseline: 1.3108x; 1.0611x over previous
#include <cuda_runtime.h>
#include <cuda_fp16.h>
#include <math.h>

// Problem dims
#define BB 16
#define TT 256
#define SS 256
#define NA 300
#define DD 512
#define HH 8
#define DKK 64
#define DFF 2048
#define LL 6

#define BT (BB*TT)                 // 4096
#define BHTT ((long)BB*HH*TT*TT)   // 8388608

#define SELF_OFF 2097152L
#define ENC_OFF  (SELF_OFF + (long)LL*BHTT)
#define AST_OFF  (ENC_OFF  + (long)LL*BHTT)

// ------------- scratch -------------
__device__ float g_x[BT*DD];
__device__ float g_t[BT*DD];
__device__ float g_pt[BT*DD];          // preamble-only temp (avoids s2 race)
__device__ __half g_qkvh[3*BT*DD];
__device__ __half g_ch[BT*DD];
__device__ __half g_hh[BT*DFF];
__device__ float g_multi[BB*SS*DD];
__device__ float g_ast1[BB*SS*DD];
__device__ float g_aste[BB*SS*DD];
__device__ float g_mm[BB*SS*SS];
__device__ float g_mmctx[BB*SS*DD];

// fp16 weights: attn (72 x 512x512) | W1 (6 x 512x2048) | W2 (6 x 2048x512)
#define WB_ATTN 0L
#define WB_W1   18874368L
#define WB_W2   25165824L
__device__ __half g_wb[31457280];

// ------------- helpers -------------
__device__ __forceinline__ unsigned pack_h2(float x, float y) {
    __half2 h = __floats2half2_rn(x, y);
    return *reinterpret_cast<unsigned*>(&h);
}
__device__ __forceinline__ void mma_f16(float* d,
    unsigned a0, unsigned a1, unsigned a2, unsigned a3,
    unsigned b0, unsigned b1)
{
    asm volatile(
        "mma.sync.aligned.m16n8k16.row.col.f32.f16.f16.f32 "
        "{%0,%1,%2,%3},{%4,%5,%6,%7},{%8,%9},{%0,%1,%2,%3};\n"
        : "+f"(d[0]), "+f"(d[1]), "+f"(d[2]), "+f"(d[3])
        : "r"(a0), "r"(a1), "r"(a2), "r"(a3), "r"(b0), "r"(b1));
}
__device__ __forceinline__ void ldsm_x4(unsigned& r0, unsigned& r1,
                                        unsigned& r2, unsigned& r3, unsigned addr)
{
    asm volatile("ldmatrix.sync.aligned.m8n8.x4.shared.b16 {%0,%1,%2,%3}, [%4];"
        : "=r"(r0), "=r"(r1), "=r"(r2), "=r"(r3) : "r"(addr));
}
__device__ __forceinline__ void ldsm_x4_t(unsigned& r0, unsigned& r1,
                                          unsigned& r2, unsigned& r3, unsigned addr)
{
    asm volatile("ldmatrix.sync.aligned.m8n8.x4.trans.shared.b16 {%0,%1,%2,%3}, [%4];"
        : "=r"(r0), "=r"(r1), "=r"(r2), "=r"(r3) : "r"(addr));
}

// f32 -> f16 elementwise (vectorized by 4)
__global__ void w2h(const float* __restrict__ in, __half* __restrict__ outp, long n4)
{
    long i = (long)blockIdx.x * blockDim.x + threadIdx.x;
    if (i >= n4) return;
    float4 v = reinterpret_cast<const float4*>(in)[i];
    uint2 w; w.x = pack_h2(v.x, v.y); w.y = pack_h2(v.z, v.w);
    *reinterpret_cast<uint2*>(outp + i*4) = w;
}

#define VP 20
#define WPB 68
#define BUFW (64*VP + 32*WPB)   // 3456 words

// ---------------------------------------------------------------------
// gemm2h: C[M,N] = A[M,K] @ B[K,N](f16). AH: A is f16; OUTH: C is f16.
// ---------------------------------------------------------------------
template<bool RELU, bool AH, bool OUTH>
__global__ __launch_bounds__(256, 2) void gemm2h(
    const void* __restrict__ A0, const void* __restrict__ A1,
    const void* __restrict__ A2, long strA,
    const __half* __restrict__ B0, long strB,
    void* __restrict__ C0, long strC,
    int M, int N, int K)
{
    extern __shared__ unsigned smg[];

    const int tid = threadIdx.x, warp = tid >> 5, lane = tid & 31;
    const int g = lane >> 2, tg = lane & 3;
    const int wr = warp >> 2, wc = warp & 3;
    const int z = blockIdx.z;

    const void* Ap = (z == 0) ? A0 : (z == 1 ? A1 : A2);
    const float*  Atf = AH ? nullptr : ((const float*)Ap + (long)z*strA + (long)blockIdx.y*64*K);
    const __half* Ath = AH ? ((const __half*)Ap + (long)z*strA + (long)blockIdx.y*64*K) : nullptr;
    const __half* Bt = B0 + (long)z * strB + blockIdx.x * 128;

    const int aR = tid >> 3;
    const int aC = (tid & 7) * 4;
    const int bR = tid >> 4;
    const int bC8 = (tid & 15) * 8;

    const int laneRow = (lane & 7) + ((lane >> 3) & 1) * 8;
    const int laneSeg = (lane >> 4) * 4;
    const unsigned vbase = (unsigned)__cvta_generic_to_shared(smg);
    const unsigned aLane = vbase + ((wr*32 + laneRow)*VP + laneSeg) * 4;
    const int kRow = lane & 15;
    const int nSel = lane >> 4;
    const unsigned bLane = vbase + (64*VP + kRow*WPB + wc*16 + nSel*4) * 4;

    float4 raf[2];
    uint2  rah[2];
    uint4  rbh[2];

    auto ldA = [&](int p, int k0) {
        long row = aR + p*32;
        if (AH) rah[p] = *reinterpret_cast<const uint2*>(Ath + row*K + k0 + aC);
        else    raf[p] = *reinterpret_cast<const float4*>(Atf + row*K + k0 + aC);
    };
    auto ldB = [&](int p, int k0) {
        rbh[p] = *reinterpret_cast<const uint4*>(Bt + (long)(k0 + bR + p*16)*N + bC8);
    };

    #pragma unroll
    for (int p = 0; p < 2; p++) { ldA(p, 0); ldB(p, 0); }

    auto sts = [&](int buf) {
        unsigned* V = smg + buf*BUFW;
        unsigned* W = V + 64*VP;
        #pragma unroll
        for (int p = 0; p < 2; p++) {
            int m = aR + p*32;
            uint2 w;
            if (AH) w = rah[p];
            else { w.x = pack_h2(raf[p].x, raf[p].y); w.y = pack_h2(raf[p].z, raf[p].w); }
            *reinterpret_cast<uint2*>(&V[m*VP + (aC >> 1)]) = w;
        }
        #pragma unroll
        for (int p = 0; p < 2; p++)
            *reinterpret_cast<uint4*>(&W[(bR + p*16)*WPB + (bC8 >> 1)]) = rbh[p];
    };
    sts(0);
    __syncthreads();

    float acc[8][4];
    #pragma unroll
    for (int i = 0; i < 8; i++) { acc[i][0]=0.f; acc[i][1]=0.f; acc[i][2]=0.f; acc[i][3]=0.f; }

    int cur = 0;
    for (int k0 = 0; k0 < K; k0 += 32) {
        const bool nxt = (k0 + 32) < K;
        if (nxt) {
            #pragma unroll
            for (int p = 0; p < 2; p++) { ldA(p, k0 + 32); ldB(p, k0 + 32); }
        }
        const unsigned aBuf = aLane + cur*BUFW*4;
        const unsigned bBuf = bLane + cur*BUFW*4;
        #pragma unroll
        for (int kt = 0; kt < 2; kt++) {
            unsigned a[2][4], b[4][2];
            #pragma unroll
            for (int mi = 0; mi < 2; mi++)
                ldsm_x4(a[mi][0], a[mi][1], a[mi][2], a[mi][3],
                        aBuf + mi*16*VP*4 + kt*32);
            {
                unsigned r0, r1, r2, r3;
                ldsm_x4_t(r0, r1, r2, r3, bBuf + kt*16*WPB*4);
                b[0][0]=r0; b[0][1]=r1; b[1][0]=r2; b[1][1]=r3;
                ldsm_x4_t(r0, r1, r2, r3, bBuf + kt*16*WPB*4 + 32);
                b[2][0]=r0; b[2][1]=r1; b[3][0]=r2; b[3][1]=r3;
            }
            #pragma unroll
            for (int mi = 0; mi < 2; mi++)
                #pragma unroll
                for (int nj = 0; nj < 4; nj++)
                    mma_f16(acc[mi*4+nj], a[mi][0],a[mi][1],a[mi][2],a[mi][3],
                            b[nj][0], b[nj][1]);
        }
        if (nxt) {
            sts(cur ^ 1);
            __syncthreads();
            cur ^= 1;
        }
    }

    #pragma unroll
    for (int mi = 0; mi < 2; mi++) {
        #pragma unroll
        for (int nj = 0; nj < 4; nj++) {
            float* d = acc[mi*4+nj];
            int r0 = blockIdx.y*64 + wr*32 + mi*16 + g;
            int col = blockIdx.x*128 + wc*32 + nj*8 + tg*2;
            float v0 = d[0], v1 = d[1], v2 = d[2], v3 = d[3];
            if (RELU) {
                v0=fmaxf(v0,0.f); v1=fmaxf(v1,0.f); v2=fmaxf(v2,0.f); v3=fmaxf(v3,0.f);
            }
            if (OUTH) {
                __half* C = (__half*)C0 + (long)z * strC;
                *reinterpret_cast<unsigned*>(C + (long)r0*N + col) = pack_h2(v0, v1);
                *reinterpret_cast<unsigned*>(C + (long)(r0+8)*N + col) = pack_h2(v2, v3);
            } else {
                float* C = (float*)C0 + (long)z * strC;
                *reinterpret_cast<float2*>(C + (long)r0*N + col) = make_float2(v0, v1);
                *reinterpret_cast<float2*>(C + (long)(r0+8)*N + col) = make_float2(v2, v3);
            }
        }
    }
}

// ---------------------------------------------------------------------
// gemm2 (fp32 B) — preamble only (K=300 guard, bias, acc). Unchanged.
// ---------------------------------------------------------------------
template<bool RELU, bool ACC, bool RBIAS, bool KG>
__global__ __launch_bounds__(256, 2) void gemm2(
    const float* __restrict__ A0, const float* __restrict__ A1,
    const float* __restrict__ A2, long strA,
    const float* __restrict__ B0, long strB,
    float* __restrict__ C0, long strC,
    const float* __restrict__ bias,
    int M, int N, int K)
{
    extern __shared__ unsigned smg[];

    const int tid = threadIdx.x, warp = tid >> 5, lane = tid & 31;
    const int g = lane >> 2, tg = lane & 3;
    const int wr = warp >> 2, wc = warp & 3;
    const int z = blockIdx.z;

    const float* A = ((z == 0) ? A0 : (z == 1 ? A1 : A2)) + (long)z * strA;
    const float* At = A + (long)blockIdx.y * 64 * K;
    const float* Bt = B0 + (long)z * strB + blockIdx.x * 128;
    float* C = C0 + (long)z * strC;

    const int aR = tid >> 3;
    const int aC = (tid & 7) * 4;
    const int kp = tid >> 5;
    const int bC = (tid & 31) * 4;
    const int bw = (tid & 31) * 2;

    const int laneRow = (lane & 7) + ((lane >> 3) & 1) * 8;
    const int laneSeg = (lane >> 4) * 4;
    const unsigned vbase = (unsigned)__cvta_generic_to_shared(smg);
    const unsigned aLane = vbase + ((wr*32 + laneRow)*VP + laneSeg) * 4;
    const int kRow = lane & 15;
    const int nSel = lane >> 4;
    const unsigned bLane = vbase + (64*VP + kRow*WPB + wc*16 + nSel*4) * 4;

    float4 ra[2], rb[4];
    auto ldA = [&](int p, int k0) -> float4 {
        long row = aR + p*32;
        if (!KG || (k0 + aC + 4 <= K))
            return *reinterpret_cast<const float4*>(At + row*K + k0 + aC);
        float4 v = make_float4(0.f, 0.f, 0.f, 0.f);
        if (k0 + aC     < K) v.x = At[row*K + k0 + aC];
        if (k0 + aC + 1 < K) v.y = At[row*K + k0 + aC + 1];
        if (k0 + aC + 2 < K) v.z = At[row*K + k0 + aC + 2];
        if (k0 + aC + 3 < K) v.w = At[row*K + k0 + aC + 3];
        return v;
    };
    auto ldB = [&](int r, int k0) -> float4 {
        int row = k0 + r;
        if (!KG || row < K)
            return *reinterpret_cast<const float4*>(Bt + (long)row*N + bC);
        return make_float4(0.f, 0.f, 0.f, 0.f);
    };

    #pragma unroll
    for (int p = 0; p < 2; p++) ra[p] = ldA(p, 0);
    rb[0] = ldB(2*kp,      0);
    rb[1] = ldB(2*kp + 1,  0);
    rb[2] = ldB(2*kp + 16, 0);
    rb[3] = ldB(2*kp + 17, 0);

    auto sts = [&](int buf) {
        unsigned* V = smg + buf*BUFW;
        unsigned* W = V + 64*VP;
        #pragma unroll
        for (int p = 0; p < 2; p++) {
            int m = aR + p*32;
            uint2 w;
            w.x = pack_h2(ra[p].x, ra[p].y);
            w.y = pack_h2(ra[p].z, ra[p].w);
            *reinterpret_cast<uint2*>(&V[m*VP + (aC >> 1)]) = w;
        }
        {
            uint2 w;
            w.x = pack_h2(rb[0].x, rb[0].y); w.y = pack_h2(rb[0].z, rb[0].w);
            *reinterpret_cast<uint2*>(&W[(2*kp     )*WPB + bw]) = w;
            w.x = pack_h2(rb[1].x, rb[1].y); w.y = pack_h2(rb[1].z, rb[1].w);
            *reinterpret_cast<uint2*>(&W[(2*kp + 1 )*WPB + bw]) = w;
            w.x = pack_h2(rb[2].x, rb[2].y); w.y = pack_h2(rb[2].z, rb[2].w);
            *reinterpret_cast<uint2*>(&W[(2*kp + 16)*WPB + bw]) = w;
            w.x = pack_h2(rb[3].x, rb[3].y); w.y = pack_h2(rb[3].z, rb[3].w);
            *reinterpret_cast<uint2*>(&W[(2*kp + 17)*WPB + bw]) = w;
        }
    };
    sts(0);
    __syncthreads();

    float acc[8][4];
    #pragma unroll
    for (int i = 0; i < 8; i++) { acc[i][0]=0.f; acc[i][1]=0.f; acc[i][2]=0.f; acc[i][3]=0.f; }

    int cur = 0;
    for (int k0 = 0; k0 < K; k0 += 32) {
        const bool nxt = (k0 + 32) < K;
        if (nxt) {
            #pragma unroll
            for (int p = 0; p < 2; p++) ra[p] = ldA(p, k0 + 32);
            rb[0] = ldB(2*kp,      k0 + 32);
            rb[1] = ldB(2*kp + 1,  k0 + 32);
            rb[2] = ldB(2*kp + 16, k0 + 32);
            rb[3] = ldB(2*kp + 17, k0 + 32);
        }
        const unsigned aBuf = aLane + cur*BUFW*4;
        const unsigned bBuf = bLane + cur*BUFW*4;
        #pragma unroll
        for (int kt = 0; kt < 2; kt++) {
            unsigned a[2][4], b[4][2];
            #pragma unroll
            for (int mi = 0; mi < 2; mi++)
                ldsm_x4(a[mi][0], a[mi][1], a[mi][2], a[mi][3],
                        aBuf + mi*16*VP*4 + kt*32);
            {
                unsigned r0, r1, r2, r3;
                ldsm_x4_t(r0, r1, r2, r3, bBuf + kt*16*WPB*4);
                b[0][0]=r0; b[0][1]=r1; b[1][0]=r2; b[1][1]=r3;
                ldsm_x4_t(r0, r1, r2, r3, bBuf + kt*16*WPB*4 + 32);
                b[2][0]=r0; b[2][1]=r1; b[3][0]=r2; b[3][1]=r3;
            }
            #pragma unroll
            for (int mi = 0; mi < 2; mi++)
                #pragma unroll
                for (int nj = 0; nj < 4; nj++)
                    mma_f16(acc[mi*4+nj], a[mi][0],a[mi][1],a[mi][2],a[mi][3],
                            b[nj][0], b[nj][1]);
        }
        if (nxt) {
            sts(cur ^ 1);
            __syncthreads();
            cur ^= 1;
        }
    }

    #pragma unroll
    for (int mi = 0; mi < 2; mi++) {
        #pragma unroll
        for (int nj = 0; nj < 4; nj++) {
            float* d = acc[mi*4+nj];
            int r0 = blockIdx.y*64 + wr*32 + mi*16 + g;
            int col = blockIdx.x*128 + wc*32 + nj*8 + tg*2;
            float b0 = RBIAS ? bias[r0] : 0.f;
            float b1 = RBIAS ? bias[r0+8] : 0.f;
            float2 v0 = make_float2(d[0]+b0, d[1]+b0);
            float2 v1 = make_float2(d[2]+b1, d[3]+b1);
            float2* p0 = reinterpret_cast<float2*>(C + (long)r0*N + col);
            float2* p1 = reinterpret_cast<float2*>(C + (long)(r0+8)*N + col);
            if (ACC) { float2 o0 = *p0, o1 = *p1; v0.x+=o0.x; v0.y+=o0.y; v1.x+=o1.x; v1.y+=o1.y; }
            if (RELU) { v0.x=fmaxf(v0.x,0.f); v0.y=fmaxf(v0.y,0.f); v1.x=fmaxf(v1.x,0.f); v1.y=fmaxf(v1.y,0.f); }
            *p0 = v0; *p1 = v1;
        }
    }
}

// ---------------------------------------------------------------------
// attn_fused: INH = half q/k/v inputs (and half ctx output when CTX).
// ---------------------------------------------------------------------
#define QP 36
#define KP 36
#define VBP 68
#define PP 132

template<int MASK, bool CTX, bool INH>
__global__ __launch_bounds__(256) void attn_fused(
    const void* __restrict__ Qp, const void* __restrict__ Kp,
    const void* __restrict__ Vp, float* __restrict__ P,
    void* __restrict__ Cctx,
    int Kdim, int lda, int ldb,
    long strA, long offHA, long strB, long offHB,
    int Hh, float scale, const int* __restrict__ tok, int tokStride)
{
    extern __shared__ unsigned sma[];
    unsigned* Qs = sma;
    unsigned* Ks = sma + 64*QP;
    unsigned* Vs = sma + 64*QP + 256*KP;
    unsigned* Ps = sma;
    __shared__ float red[64*4];

    const int tid = threadIdx.x, warp = tid >> 5, lane = tid & 31;
    const int g = lane >> 2, tg = lane & 3;
    const int wr = warp >> 2, wc = warp & 3;
    const int z = blockIdx.y;
    const int bb = z / Hh, hh = z - bb*Hh;
    const int rowTile = blockIdx.x;
    const int rowBase = rowTile * 64;

    float acc[16][4];
    #pragma unroll
    for (int i = 0; i < 16; i++) { acc[i][0]=0.f; acc[i][1]=0.f; acc[i][2]=0.f; acc[i][3]=0.f; }

    for (int k0 = 0; k0 < Kdim; k0 += 64) {
        if (INH) {
            const __half* Qb = (const __half*)Qp + (long)bb*strA + (long)hh*offHA + (long)rowBase*lda;
            const __half* Kb = (const __half*)Kp + (long)bb*strB + (long)hh*offHB;
            #pragma unroll
            for (int p = 0; p < 4; p++) {
                int idx = tid + p*256;
                int r = idx >> 4, c4 = idx & 15;
                uint2 w = *reinterpret_cast<const uint2*>(Qb + (long)r*lda + k0 + c4*4);
                *reinterpret_cast<uint2*>(&Qs[r*QP + c4*2]) = w;
            }
            #pragma unroll
            for (int p = 0; p < 16; p++) {
                int idx = tid + p*256;
                int r = idx >> 4, c4 = idx & 15;
                uint2 w = *reinterpret_cast<const uint2*>(Kb + (long)r*ldb + k0 + c4*4);
                *reinterpret_cast<uint2*>(&Ks[r*KP + c4*2]) = w;
            }
            if (CTX && k0 == 0) {
                const __half* Vb = (const __half*)Vp + (long)bb*strB + (long)hh*offHB;
                #pragma unroll
                for (int p = 0; p < 8; p++) {
                    int idx = tid + p*256;
                    int r2 = idx >> 4, c4 = idx & 15;
                    uint2 a0 = *reinterpret_cast<const uint2*>(Vb + (long)(2*r2  )*ldb + c4*4);
                    uint2 b0 = *reinterpret_cast<const uint2*>(Vb + (long)(2*r2+1)*ldb + c4*4);
                    uint4 w;
                    w.x = __byte_perm(a0.x, b0.x, 0x5410);
                    w.y = __byte_perm(a0.x, b0.x, 0x7632);
                    w.z = __byte_perm(a0.y, b0.y, 0x5410);
                    w.w = __byte_perm(a0.y, b0.y, 0x7632);
                    *reinterpret_cast<uint4*>(&Vs[r2*VBP + c4*4]) = w;
                }
            }
        } else {
            const float* Qb = (const float*)Qp + (long)bb*strA + (long)hh*offHA + (long)rowBase*lda;
            const float* Kb = (const float*)Kp + (long)bb*strB + (long)hh*offHB;
            #pragma unroll
            for (int p = 0; p < 4; p++) {
                int idx = tid + p*256;
                int r = idx >> 4, c4 = idx & 15;
                float4 v = *reinterpret_cast<const float4*>(Qb + (long)r*lda + k0 + c4*4);
                uint2 w; w.x = pack_h2(v.x, v.y); w.y = pack_h2(v.z, v.w);
                *reinterpret_cast<uint2*>(&Qs[r*QP + c4*2]) = w;
            }
            #pragma unroll
            for (int p = 0; p < 16; p++) {
                int idx = tid + p*256;
                int r = idx >> 4, c4 = idx & 15;
                float4 v = *reinterpret_cast<const float4*>(Kb + (long)r*ldb + k0 + c4*4);
                uint2 w; w.x = pack_h2(v.x, v.y); w.y = pack_h2(v.z, v.w);
                *reinterpret_cast<uint2*>(&Ks[r*KP + c4*2]) = w;
            }
        }
        __syncthreads();
        #pragma unroll
        for (int kt = 0; kt < 4; kt++) {
            unsigned a[2][4], b[8][2];
            #pragma unroll
            for (int mi = 0; mi < 2; mi++) {
                int mb = wr*32 + mi*16;
                a[mi][0] = Qs[(mb+g  )*QP + kt*8 + tg];
                a[mi][1] = Qs[(mb+g+8)*QP + kt*8 + tg];
                a[mi][2] = Qs[(mb+g  )*QP + kt*8 + tg + 4];
                a[mi][3] = Qs[(mb+g+8)*QP + kt*8 + tg + 4];
            }
            #pragma unroll
            for (int nj = 0; nj < 8; nj++) {
                int nb = wc*64 + nj*8;
                b[nj][0] = Ks[(nb+g)*KP + kt*8 + tg];
                b[nj][1] = Ks[(nb+g)*KP + kt*8 + tg + 4];
            }
            #pragma unroll
            for (int mi = 0; mi < 2; mi++)
                #pragma unroll
                for (int nj = 0; nj < 8; nj++)
                    mma_f16(acc[mi*8+nj], a[mi][0],a[mi][1],a[mi][2],a[mi][3],
                            b[nj][0], b[nj][1]);
        }
        if (k0 + 64 < Kdim) __syncthreads();
    }

    // ---- scale + mask ----
    #pragma unroll
    for (int mi = 0; mi < 2; mi++) {
        #pragma unroll
        for (int nj = 0; nj < 8; nj++) {
            float* d = acc[mi*8+nj];
            int col = wc*64 + nj*8 + tg*2;
            int lr0 = wr*32 + mi*16 + g;
            #pragma unroll
            for (int c = 0; c < 4; c++) {
                int gcol = col + (c & 1);
                int grow = rowBase + lr0 + ((c >> 1) * 8);
                float v = d[c] * scale;
                if (MASK == 1) {
                    if (tok[bb*tokStride + gcol] == 0 || gcol > grow) v = -1e9f;
                } else if (MASK == 2) {
                    if (tok[bb*tokStride + gcol] == 0) v = -1e9f;
                }
                d[c] = v;
            }
        }
    }

    // ---- softmax (fp32) ----
    float rmax[4];
    #pragma unroll
    for (int mi = 0; mi < 2; mi++) {
        float m0 = -1e30f, m1 = -1e30f;
        #pragma unroll
        for (int nj = 0; nj < 8; nj++) {
            float* d = acc[mi*8+nj];
            m0 = fmaxf(m0, fmaxf(d[0], d[1]));
            m1 = fmaxf(m1, fmaxf(d[2], d[3]));
        }
        rmax[mi*2+0] = m0; rmax[mi*2+1] = m1;
    }
    #pragma unroll
    for (int i = 0; i < 4; i++) {
        rmax[i] = fmaxf(rmax[i], __shfl_xor_sync(0xffffffffu, rmax[i], 1));
        rmax[i] = fmaxf(rmax[i], __shfl_xor_sync(0xffffffffu, rmax[i], 2));
    }
    if (tg == 0) {
        #pragma unroll
        for (int mi = 0; mi < 2; mi++) {
            red[(wr*32 + mi*16 + g    )*4 + wc] = rmax[mi*2+0];
            red[(wr*32 + mi*16 + g + 8)*4 + wc] = rmax[mi*2+1];
        }
    }
    __syncthreads();
    float fmax4[4];
    #pragma unroll
    for (int mi = 0; mi < 2; mi++) {
        int r0 = wr*32 + mi*16 + g, r1 = r0 + 8;
        fmax4[mi*2+0] = fmaxf(fmaxf(red[r0*4+0], red[r0*4+1]), fmaxf(red[r0*4+2], red[r0*4+3]));
        fmax4[mi*2+1] = fmaxf(fmaxf(red[r1*4+0], red[r1*4+1]), fmaxf(red[r1*4+2], red[r1*4+3]));
    }
    __syncthreads();

    float rsum[4] = {0.f, 0.f, 0.f, 0.f};
    #pragma unroll
    for (int mi = 0; mi < 2; mi++) {
        #pragma unroll
        for (int nj = 0; nj < 8; nj++) {
            float* d = acc[mi*8+nj];
            d[0] = __expf(d[0] - fmax4[mi*2+0]);
            d[1] = __expf(d[1] - fmax4[mi*2+0]);
            d[2] = __expf(d[2] - fmax4[mi*2+1]);
            d[3] = __expf(d[3] - fmax4[mi*2+1]);
            rsum[mi*2+0] += d[0] + d[1];
            rsum[mi*2+1] += d[2] + d[3];
        }
    }
    #pragma unroll
    for (int i = 0; i < 4; i++) {
        rsum[i] += __shfl_xor_sync(0xffffffffu, rsum[i], 1);
        rsum[i] += __shfl_xor_sync(0xffffffffu, rsum[i], 2);
    }
    if (tg == 0) {
        #pragma unroll
        for (int mi = 0; mi < 2; mi++) {
            red[(wr*32 + mi*16 + g    )*4 + wc] = rsum[mi*2+0];
            red[(wr*32 + mi*16 + g + 8)*4 + wc] = rsum[mi*2+1];
        }
    }
    __syncthreads();
    float rinv[4];
    #pragma unroll
    for (int mi = 0; mi < 2; mi++) {
        int r0 = wr*32 + mi*16 + g, r1 = r0 + 8;
        rinv[mi*2+0] = 1.f / (red[r0*4+0] + red[r0*4+1] + red[r0*4+2] + red[r0*4+3]);
        rinv[mi*2+1] = 1.f / (red[r1*4+0] + red[r1*4+1] + red[r1*4+2] + red[r1*4+3]);
    }

    float* Pb = P + (long)z * 65536L + (long)rowBase * 256;
    #pragma unroll
    for (int mi = 0; mi < 2; mi++) {
        #pragma unroll
        for (int nj = 0; nj < 8; nj++) {
            float* d = acc[mi*8+nj];
            int col = wc*64 + nj*8 + tg*2;
            int r0 = wr*32 + mi*16 + g;
            float p0 = d[0]*rinv[mi*2+0], p1 = d[1]*rinv[mi*2+0];
            float p2 = d[2]*rinv[mi*2+1], p3 = d[3]*rinv[mi*2+1];
            *reinterpret_cast<float2*>(Pb + (long)r0*256 + col) = make_float2(p0, p1);
            *reinterpret_cast<float2*>(Pb + (long)(r0+8)*256 + col) = make_float2(p2, p3);
            if (CTX) {
                int k2 = wc*32 + nj*4 + tg;
                Ps[r0*PP + k2]     = pack_h2(p0, p1);
                Ps[(r0+8)*PP + k2] = pack_h2(p2, p3);
            }
        }
    }

    if (CTX) {
        __syncthreads();
        float acc2[4][4];
        #pragma unroll
        for (int i = 0; i < 4; i++) { acc2[i][0]=0.f; acc2[i][1]=0.f; acc2[i][2]=0.f; acc2[i][3]=0.f; }
        #pragma unroll
        for (int kt = 0; kt < 16; kt++) {
            unsigned a[2][4], b[2][2];
            #pragma unroll
            for (int mi = 0; mi < 2; mi++) {
                int mb = wr*32 + mi*16;
                a[mi][0] = Ps[(mb+g  )*PP + kt*8 + tg];
                a[mi][1] = Ps[(mb+g+8)*PP + kt*8 + tg];
                a[mi][2] = Ps[(mb+g  )*PP + kt*8 + tg + 4];
                a[mi][3] = Ps[(mb+g+8)*PP + kt*8 + tg + 4];
            }
            #pragma unroll
            for (int nj = 0; nj < 2; nj++) {
                int nb = wc*16 + nj*8 + g;
                b[nj][0] = Vs[(kt*8 + tg    )*VBP + nb];
                b[nj][1] = Vs[(kt*8 + tg + 4)*VBP + nb];
            }
            #pragma unroll
            for (int mi = 0; mi < 2; mi++)
                #pragma unroll
                for (int nj = 0; nj < 2; nj++)
                    mma_f16(acc2[mi*2+nj], a[mi][0],a[mi][1],a[mi][2],a[mi][3],
                            b[nj][0], b[nj][1]);
        }
        __half* Cb = (__half*)Cctx + (long)bb*TT*DD + hh*64;
        #pragma unroll
        for (int mi = 0; mi < 2; mi++) {
            #pragma unroll
            for (int nj = 0; nj < 2; nj++) {
                float* d = acc2[mi*2+nj];
                int r0 = rowBase + wr*32 + mi*16 + g;
                int col = wc*16 + nj*8 + tg*2;
                *reinterpret_cast<unsigned*>(Cb + (long)r0*DD + col) = pack_h2(d[0], d[1]);
                *reinterpret_cast<unsigned*>(Cb + (long)(r0+8)*DD + col) = pack_h2(d[2], d[3]);
            }
        }
    }
}

// ---------------------------------------------------------------------
__global__ __launch_bounds__(128) void add_ln(
    const float* __restrict__ a, const float* __restrict__ b,
    float* __restrict__ out, const float* __restrict__ g,
    const float* __restrict__ beta)
{
    long off = (long)blockIdx.x * DD;
    int t = threadIdx.x;
    int warp = t >> 5, lane = t & 31;
    float4 va = *reinterpret_cast<const float4*>(a + off + t*4);
    float4 vb = *reinterpret_cast<const float4*>(b + off + t*4);
    float4 v;
    v.x = va.x + vb.x; v.y = va.y + vb.y; v.z = va.z + vb.z; v.w = va.w + vb.w;
    __shared__ float ws[4], ws2[4];

    float s = v.x + v.y + v.z + v.w;
    #pragma unroll
    for (int o = 16; o > 0; o >>= 1) s += __shfl_xor_sync(0xffffffffu, s, o);
    if (lane == 0) ws[warp] = s;
    __syncthreads();
    float mu = (ws[0]+ws[1]+ws[2]+ws[3]) * (1.f/DD);

    float4 d;
    d.x = v.x - mu; d.y = v.y - mu; d.z = v.z - mu; d.w = v.w - mu;
    float q = d.x*d.x + d.y*d.y + d.z*d.z + d.w*d.w;
    #pragma unroll
    for (int o = 16; o > 0; o >>= 1) q += __shfl_xor_sync(0xffffffffu, q, o);
    if (lane == 0) ws2[warp] = q;
    __syncthreads();
    float rstd = rsqrtf((ws2[0]+ws2[1]+ws2[2]+ws2[3]) * (1.f/DD) + 1e-5f);

    float4 gg = g ? *reinterpret_cast<const float4*>(g + t*4)
                  : make_float4(1.f, 1.f, 1.f, 1.f);
    float4 bb = beta ? *reinterpret_cast<const float4*>(beta + t*4)
                     : make_float4(0.f, 0.f, 0.f, 0.f);
    float4 o;
    o.x = d.x * rstd * gg.x + bb.x;
    o.y = d.y * rstd * gg.y + bb.y;
    o.z = d.z * rstd * gg.z + bb.z;
    o.w = d.w * rstd * gg.w + bb.w;
    *reinterpret_cast<float4*>(out + off + t*4) = o;
}

__global__ void embed_pe(const int* __restrict__ dec,
                         const float* __restrict__ emb,
                         float* __restrict__ x)
{
    long idx = (long)blockIdx.x * blockDim.x + threadIdx.x;
    if (idx >= (long)BT*DD) return;
    int d  = (int)(idx % DD);
    long bt = idx / DD;
    int t  = (int)(bt % TT);
    int tokidx = dec[bt];
    int d2 = d & ~1;
    float div = expf(-logf(10000.f) * (float)d2 / (float)DD);
    float ang = (float)t * div;
    float pe = (d & 1) ? cosf(ang) : sinf(ang);
    x[idx] = emb[(long)tokidx*DD + d] + pe;
}

__global__ void add3(const float* __restrict__ a, const float* __restrict__ bias,
                     const float* __restrict__ c, float* __restrict__ out, long n)
{
    long i = (long)blockIdx.x * blockDim.x + threadIdx.x;
    if (i >= n) return;
    out[i] = a[i] + bias[i % DD] + c[i];
}

__global__ void copyk4(const float4* __restrict__ src, float4* __restrict__ dst, long n4)
{
    long i = (long)blockIdx.x * blockDim.x + threadIdx.x;
    if (i < n4) dst[i] = src[i];
}

// ---------------------------------------------------------------------
extern "C" void kernel_launch(void* const* d_in, const int* in_sizes, int n_in,
                              void* d_out, int out_size)
{
    const int*   dec     = (const int*)  d_in[0];
    const int*   enc     = (const int*)  d_in[1];
    const float* enc_out = (const float*)d_in[2];
    const float* ast_out = (const float*)d_in[3];
    const float* src_emb = (const float*)d_in[4];
    const float* ast_emb = (const float*)d_in[5];
    const float* emb     = (const float*)d_in[7];
    const float* attn_W  = (const float*)d_in[8];
    const float* ln_g    = (const float*)d_in[9];
    const float* ln_b    = (const float*)d_in[10];
    const float* W1      = (const float*)d_in[11];
    const float* W2      = (const float*)d_in[12];
    const float* conv_w  = (const float*)d_in[13];
    const float* conv_b  = (const float*)d_in[14];
    const float* mffnW   = (const float*)d_in[15];
    const float* mffnb   = (const float*)d_in[16];
    float* out = (float*)d_out;

    float *x,*t,*pt,*multi,*ast1,*aste,*mm,*mmctx;
    __half *wb, *qkvh, *ch, *hh;
    cudaGetSymbolAddress((void**)&x,     g_x);
    cudaGetSymbolAddress((void**)&t,     g_t);
    cudaGetSymbolAddress((void**)&pt,    g_pt);
    cudaGetSymbolAddress((void**)&qkvh,  g_qkvh);
    cudaGetSymbolAddress((void**)&ch,    g_ch);
    cudaGetSymbolAddress((void**)&hh,    g_hh);
    cudaGetSymbolAddress((void**)&multi, g_multi);
    cudaGetSymbolAddress((void**)&ast1,  g_ast1);
    cudaGetSymbolAddress((void**)&aste,  g_aste);
    cudaGetSymbolAddress((void**)&mm,    g_mm);
    cudaGetSymbolAddress((void**)&mmctx, g_mmctx);
    cudaGetSymbolAddress((void**)&wb,    g_wb);

    const int GM_SMEM  = 2*BUFW*4;
    const int AT_SMEM  = (64*QP + 256*KP + 128*VBP)*4;
    const int MM_SMEM  = (64*QP + 256*KP)*4;
    cudaFuncSetAttribute((const void*)gemm2<false,false,false,false>, cudaFuncAttributeMaxDynamicSharedMemorySize, GM_SMEM);
    cudaFuncSetAttribute((const void*)gemm2<false,true ,false,false>, cudaFuncAttributeMaxDynamicSharedMemorySize, GM_SMEM);
    cudaFuncSetAttribute((const void*)gemm2<false,false,true ,true >, cudaFuncAttributeMaxDynamicSharedMemorySize, GM_SMEM);
    cudaFuncSetAttribute((const void*)gemm2h<false,false,true >, cudaFuncAttributeMaxDynamicSharedMemorySize, GM_SMEM);
    cudaFuncSetAttribute((const void*)gemm2h<true ,false,true >, cudaFuncAttributeMaxDynamicSharedMemorySize, GM_SMEM);
    cudaFuncSetAttribute((const void*)gemm2h<false,true ,false>, cudaFuncAttributeMaxDynamicSharedMemorySize, GM_SMEM);
    cudaFuncSetAttribute((const void*)attn_fused<0,false,false>, cudaFuncAttributeMaxDynamicSharedMemorySize, MM_SMEM);
    cudaFuncSetAttribute((const void*)attn_fused<0,true ,true >, cudaFuncAttributeMaxDynamicSharedMemorySize, AT_SMEM);
    cudaFuncSetAttribute((const void*)attn_fused<1,true ,true >, cudaFuncAttributeMaxDynamicSharedMemorySize, AT_SMEM);
    cudaFuncSetAttribute((const void*)attn_fused<2,true ,true >, cudaFuncAttributeMaxDynamicSharedMemorySize, AT_SMEM);

    __half* q = qkvh;
    __half* k = qkvh + (long)BT*DD;
    __half* v = qkvh + 2L*BT*DD;

    // ---- weight conversion to fp16 (main stream; feeds layer 0) ----
    w2h<<<(int)((18874368/4 + 255)/256), 256>>>(attn_W, wb + WB_ATTN, 18874368/4);
    w2h<<<(int)((6291456/4  + 255)/256), 256>>>(W1,     wb + WB_W1,   6291456/4);
    w2h<<<(int)((6291456/4  + 255)/256), 256>>>(W2,     wb + WB_W2,   6291456/4);

    // ---- fork: preamble on s2 (uses ONLY pt/ast1/aste/mm/mmctx/multi) ----
    cudaStream_t s2;
    cudaStreamCreate(&s2);
    cudaEvent_t evF, evJ;
    cudaEventCreateWithFlags(&evF, cudaEventDisableTiming);
    cudaEventCreateWithFlags(&evJ, cudaEventDisableTiming);
    cudaEventRecord(evF, 0);
    cudaStreamWaitEvent(s2, evF, 0);

    {
        dim3 gc(DD/128, SS/64, BB);
        gemm2<false,false,true,true><<<gc, 256, GM_SMEM, s2>>>(
            conv_w, conv_w, conv_w, 0L, ast_out, (long)NA*DD,
            ast1, (long)SS*DD, conv_b, SS, DD, NA);
        gemm2<false,false,true,true><<<gc, 256, GM_SMEM, s2>>>(
            conv_w, conv_w, conv_w, 0L, ast_emb, (long)NA*DD,
            aste, (long)SS*DD, conv_b, SS, DD, NA);
        dim3 gs(SS/64, BB);
        attn_fused<0,false,false><<<gs, 256, MM_SMEM, s2>>>(ast1, enc_out, nullptr, mm, nullptr,
            DD, DD, DD, (long)SS*DD, 0L, (long)SS*DD, 0L,
            1, 0.125f, nullptr, 0);
        dim3 gm(DD/128, SS/64, BB);
        gemm2<false,false,false,false><<<gm, 256, GM_SMEM, s2>>>(
            mm, mm, mm, (long)SS*SS, enc_out, (long)SS*DD,
            mmctx, (long)SS*DD, nullptr, SS, DD, SS);
        dim3 gp(DD/128, BT/64, 1);
        gemm2<false,false,false,false><<<gp, 256, GM_SMEM, s2>>>(
            src_emb, src_emb, src_emb, 0L, mffnW, 0L, pt, 0L, nullptr, BT, DD, DD);
        gemm2<false,true ,false,false><<<gp, 256, GM_SMEM, s2>>>(
            aste, aste, aste, 0L, mffnW + DD*DD, 0L, pt, 0L, nullptr, BT, DD, DD);
        long n = (long)BB*SS*DD;
        add3<<<(int)((n + 255)/256), 256, 0, s2>>>(pt, mffnb, mmctx, multi, n);
    }
    cudaEventRecord(evJ, s2);

    // ---------------- main path ----------------
    embed_pe<<<(BT*DD + 255)/256, 256>>>(dec, emb, x);

    dim3 gQKV(DD/128, BT/64, 3);
    dim3 gProj(DD/128, BT/64, 1);
    dim3 gF1(DFF/128, BT/64, 1);
    dim3 gScore(TT/64, BB*HH);

    for (int l = 0; l < LL; l++) {
        for (int a = 0; a < 3; a++) {
            const __half* wqkv = wb + WB_ATTN + (long)((l*3 + a)*4) * 262144;
            const __half* wo   = wb + WB_ATTN + (long)((l*3 + a)*4 + 3) * 262144;
            const float* xk = (a == 0) ? x : (a == 1 ? enc_out : multi);

            if (l == 0 && a == 2) cudaStreamWaitEvent(0, evJ, 0);

            gemm2h<false,false,true><<<gQKV, 256, GM_SMEM>>>(
                x, xk, xk, 0L, wqkv, 262144L, qkvh, (long)BT*DD, BT, DD, DD);

            long attnBase = (a == 0 ? SELF_OFF : (a == 1 ? ENC_OFF : AST_OFF))
                            + (long)l * BHTT;
            float* P = out + attnBase;

            if (a == 0)
                attn_fused<1,true,true><<<gScore, 256, AT_SMEM>>>(q, k, v, P, ch,
                    DKK, DD, DD, (long)TT*DD, 64L, (long)TT*DD, 64L,
                    HH, 0.125f, dec, TT);
            else if (a == 1)
                attn_fused<2,true,true><<<gScore, 256, AT_SMEM>>>(q, k, v, P, ch,
                    DKK, DD, DD, (long)TT*DD, 64L, (long)TT*DD, 64L,
                    HH, 0.125f, enc, SS);
            else
                attn_fused<0,true,true><<<gScore, 256, AT_SMEM>>>(q, k, v, P, ch,
                    DKK, DD, DD, (long)TT*DD, 64L, (long)TT*DD, 64L,
                    HH, 0.125f, nullptr, 0);

            gemm2h<false,true,false><<<gProj, 256, GM_SMEM>>>(
                ch, ch, ch, 0L, wo, 0L, t, 0L, BT, DD, DD);
            add_ln<<<BT, 128>>>(t, x, x,
                ln_g + (long)(l*3 + a)*DD, ln_b + (long)(l*3 + a)*DD);
        }
        gemm2h<true,false,true><<<gF1, 256, GM_SMEM>>>(
            x, x, x, 0L, wb + WB_W1 + (long)l*1048576, 0L, hh, 0L, BT, DFF, DD);
        gemm2h<false,true,false><<<gProj, 256, GM_SMEM>>>(
            hh, hh, hh, 0L, wb + WB_W2 + (long)l*1048576, 0L, t, 0L, BT, DD, DFF);
        add_ln<<<BT, 128>>>(t, x, x, nullptr, nullptr);
    }

    copyk4<<<(BT*DD/4 + 255)/256, 256>>>(
        reinterpret_cast<const float4*>(x), reinterpret_cast<float4*>(out),
        (long)BT*DD/4);

    cudaStreamDestroy(s2);
    cudaEventDestroy(evF);
    cudaEventDestroy(evJ);
}

// round 16
// speedup vs baseline: 1.3675x; 1.0433x over previous
#include <cuda_runtime.h>
#include <cuda_fp16.h>
#include <math.h>

// Problem dims
#define BB 16
#define TT 256
#define SS 256
#define NA 300
#define DD 512
#define HH 8
#define DKK 64
#define DFF 2048
#define LL 6

#define BT (BB*TT)                 // 4096
#define BHTT ((long)BB*HH*TT*TT)   // 8388608

#define SELF_OFF 2097152L
#define ENC_OFF  (SELF_OFF + (long)LL*BHTT)
#define AST_OFF  (ENC_OFF  + (long)LL*BHTT)

// ------------- scratch -------------
__device__ float g_x[BT*DD];
__device__ __half g_xh[BT*DD];
__device__ float g_t[BT*DD];
__device__ float g_pt[BT*DD];          // preamble-only temp
__device__ __half g_qkvh[3*BT*DD];
__device__ __half g_ch[BT*DD];
__device__ __half g_hh[BT*DFF];
__device__ __half g_ench[BB*SS*DD];
__device__ __half g_multih[BB*SS*DD];
__device__ float g_ast1[BB*SS*DD];
__device__ float g_aste[BB*SS*DD];
__device__ float g_mm[BB*SS*SS];
__device__ float g_mmctx[BB*SS*DD];

// fp16 weights: attn (72 x 512x512) | W1 (6 x 512x2048) | W2 (6 x 2048x512)
#define WB_ATTN 0L
#define WB_W1   18874368L
#define WB_W2   25165824L
__device__ __half g_wb[31457280];

// ------------- helpers -------------
__device__ __forceinline__ unsigned pack_h2(float x, float y) {
    __half2 h = __floats2half2_rn(x, y);
    return *reinterpret_cast<unsigned*>(&h);
}
__device__ __forceinline__ void mma_f16(float* d,
    unsigned a0, unsigned a1, unsigned a2, unsigned a3,
    unsigned b0, unsigned b1)
{
    asm volatile(
        "mma.sync.aligned.m16n8k16.row.col.f32.f16.f16.f32 "
        "{%0,%1,%2,%3},{%4,%5,%6,%7},{%8,%9},{%0,%1,%2,%3};\n"
        : "+f"(d[0]), "+f"(d[1]), "+f"(d[2]), "+f"(d[3])
        : "r"(a0), "r"(a1), "r"(a2), "r"(a3), "r"(b0), "r"(b1));
}
__device__ __forceinline__ void ldsm_x4(unsigned& r0, unsigned& r1,
                                        unsigned& r2, unsigned& r3, unsigned addr)
{
    asm volatile("ldmatrix.sync.aligned.m8n8.x4.shared.b16 {%0,%1,%2,%3}, [%4];"
        : "=r"(r0), "=r"(r1), "=r"(r2), "=r"(r3) : "r"(addr));
}
__device__ __forceinline__ void ldsm_x4_t(unsigned& r0, unsigned& r1,
                                          unsigned& r2, unsigned& r3, unsigned addr)
{
    asm volatile("ldmatrix.sync.aligned.m8n8.x4.trans.shared.b16 {%0,%1,%2,%3}, [%4];"
        : "=r"(r0), "=r"(r1), "=r"(r2), "=r"(r3) : "r"(addr));
}

// f32 -> f16 elementwise (vectorized by 4)
__global__ void w2h(const float* __restrict__ in, __half* __restrict__ outp, long n4)
{
    long i = (long)blockIdx.x * blockDim.x + threadIdx.x;
    if (i >= n4) return;
    float4 v = reinterpret_cast<const float4*>(in)[i];
    uint2 w; w.x = pack_h2(v.x, v.y); w.y = pack_h2(v.z, v.w);
    *reinterpret_cast<uint2*>(outp + i*4) = w;
}

#define VP 20
#define WPB 68
#define BUFW (64*VP + 32*WPB)   // 3456 words

// ---------------------------------------------------------------------
// gemm2h: C[M,N] = A[M,K] @ B[K,N](f16). AH: A is f16; OUTH: C is f16.
// ---------------------------------------------------------------------
template<bool RELU, bool AH, bool OUTH>
__global__ __launch_bounds__(256, 2) void gemm2h(
    const void* __restrict__ A0, const void* __restrict__ A1,
    const void* __restrict__ A2, long strA,
    const __half* __restrict__ B0, long strB,
    void* __restrict__ C0, long strC,
    int M, int N, int K)
{
    extern __shared__ unsigned smg[];

    const int tid = threadIdx.x, warp = tid >> 5, lane = tid & 31;
    const int g = lane >> 2, tg = lane & 3;
    const int wr = warp >> 2, wc = warp & 3;
    const int z = blockIdx.z;

    const void* Ap = (z == 0) ? A0 : (z == 1 ? A1 : A2);
    const float*  Atf = AH ? nullptr : ((const float*)Ap + (long)z*strA + (long)blockIdx.y*64*K);
    const __half* Ath = AH ? ((const __half*)Ap + (long)z*strA + (long)blockIdx.y*64*K) : nullptr;
    const __half* Bt = B0 + (long)z * strB + blockIdx.x * 128;

    const int aR = tid >> 3;
    const int aC = (tid & 7) * 4;
    const int bR = tid >> 4;
    const int bC8 = (tid & 15) * 8;

    const int laneRow = (lane & 7) + ((lane >> 3) & 1) * 8;
    const int laneSeg = (lane >> 4) * 4;
    const unsigned vbase = (unsigned)__cvta_generic_to_shared(smg);
    const unsigned aLane = vbase + ((wr*32 + laneRow)*VP + laneSeg) * 4;
    const int kRow = lane & 15;
    const int nSel = lane >> 4;
    const unsigned bLane = vbase + (64*VP + kRow*WPB + wc*16 + nSel*4) * 4;

    float4 raf[2];
    uint2  rah[2];
    uint4  rbh[2];

    auto ldA = [&](int p, int k0) {
        long row = aR + p*32;
        if (AH) rah[p] = *reinterpret_cast<const uint2*>(Ath + row*K + k0 + aC);
        else    raf[p] = *reinterpret_cast<const float4*>(Atf + row*K + k0 + aC);
    };
    auto ldB = [&](int p, int k0) {
        rbh[p] = *reinterpret_cast<const uint4*>(Bt + (long)(k0 + bR + p*16)*N + bC8);
    };

    #pragma unroll
    for (int p = 0; p < 2; p++) { ldA(p, 0); ldB(p, 0); }

    auto sts = [&](int buf) {
        unsigned* V = smg + buf*BUFW;
        unsigned* W = V + 64*VP;
        #pragma unroll
        for (int p = 0; p < 2; p++) {
            int m = aR + p*32;
            uint2 w;
            if (AH) w = rah[p];
            else { w.x = pack_h2(raf[p].x, raf[p].y); w.y = pack_h2(raf[p].z, raf[p].w); }
            *reinterpret_cast<uint2*>(&V[m*VP + (aC >> 1)]) = w;
        }
        #pragma unroll
        for (int p = 0; p < 2; p++)
            *reinterpret_cast<uint4*>(&W[(bR + p*16)*WPB + (bC8 >> 1)]) = rbh[p];
    };
    sts(0);
    __syncthreads();

    float acc[8][4];
    #pragma unroll
    for (int i = 0; i < 8; i++) { acc[i][0]=0.f; acc[i][1]=0.f; acc[i][2]=0.f; acc[i][3]=0.f; }

    int cur = 0;
    for (int k0 = 0; k0 < K; k0 += 32) {
        const bool nxt = (k0 + 32) < K;
        if (nxt) {
            #pragma unroll
            for (int p = 0; p < 2; p++) { ldA(p, k0 + 32); ldB(p, k0 + 32); }
        }
        const unsigned aBuf = aLane + cur*BUFW*4;
        const unsigned bBuf = bLane + cur*BUFW*4;
        #pragma unroll
        for (int kt = 0; kt < 2; kt++) {
            unsigned a[2][4], b[4][2];
            #pragma unroll
            for (int mi = 0; mi < 2; mi++)
                ldsm_x4(a[mi][0], a[mi][1], a[mi][2], a[mi][3],
                        aBuf + mi*16*VP*4 + kt*32);
            {
                unsigned r0, r1, r2, r3;
                ldsm_x4_t(r0, r1, r2, r3, bBuf + kt*16*WPB*4);
                b[0][0]=r0; b[0][1]=r1; b[1][0]=r2; b[1][1]=r3;
                ldsm_x4_t(r0, r1, r2, r3, bBuf + kt*16*WPB*4 + 32);
                b[2][0]=r0; b[2][1]=r1; b[3][0]=r2; b[3][1]=r3;
            }
            #pragma unroll
            for (int mi = 0; mi < 2; mi++)
                #pragma unroll
                for (int nj = 0; nj < 4; nj++)
                    mma_f16(acc[mi*4+nj], a[mi][0],a[mi][1],a[mi][2],a[mi][3],
                            b[nj][0], b[nj][1]);
        }
        if (nxt) {
            sts(cur ^ 1);
            __syncthreads();
            cur ^= 1;
        }
    }

    #pragma unroll
    for (int mi = 0; mi < 2; mi++) {
        #pragma unroll
        for (int nj = 0; nj < 4; nj++) {
            float* d = acc[mi*4+nj];
            int r0 = blockIdx.y*64 + wr*32 + mi*16 + g;
            int col = blockIdx.x*128 + wc*32 + nj*8 + tg*2;
            float v0 = d[0], v1 = d[1], v2 = d[2], v3 = d[3];
            if (RELU) {
                v0=fmaxf(v0,0.f); v1=fmaxf(v1,0.f); v2=fmaxf(v2,0.f); v3=fmaxf(v3,0.f);
            }
            if (OUTH) {
                __half* C = (__half*)C0 + (long)z * strC;
                *reinterpret_cast<unsigned*>(C + (long)r0*N + col) = pack_h2(v0, v1);
                *reinterpret_cast<unsigned*>(C + (long)(r0+8)*N + col) = pack_h2(v2, v3);
            } else {
                float* C = (float*)C0 + (long)z * strC;
                *reinterpret_cast<float2*>(C + (long)r0*N + col) = make_float2(v0, v1);
                *reinterpret_cast<float2*>(C + (long)(r0+8)*N + col) = make_float2(v2, v3);
            }
        }
    }
}

// ---------------------------------------------------------------------
// gemm2 (fp32 B) — preamble only (K=300 guard, bias, acc). Unchanged.
// ---------------------------------------------------------------------
template<bool RELU, bool ACC, bool RBIAS, bool KG>
__global__ __launch_bounds__(256, 2) void gemm2(
    const float* __restrict__ A0, const float* __restrict__ A1,
    const float* __restrict__ A2, long strA,
    const float* __restrict__ B0, long strB,
    float* __restrict__ C0, long strC,
    const float* __restrict__ bias,
    int M, int N, int K)
{
    extern __shared__ unsigned smg[];

    const int tid = threadIdx.x, warp = tid >> 5, lane = tid & 31;
    const int g = lane >> 2, tg = lane & 3;
    const int wr = warp >> 2, wc = warp & 3;
    const int z = blockIdx.z;

    const float* A = ((z == 0) ? A0 : (z == 1 ? A1 : A2)) + (long)z * strA;
    const float* At = A + (long)blockIdx.y * 64 * K;
    const float* Bt = B0 + (long)z * strB + blockIdx.x * 128;
    float* C = C0 + (long)z * strC;

    const int aR = tid >> 3;
    const int aC = (tid & 7) * 4;
    const int kp = tid >> 5;
    const int bC = (tid & 31) * 4;
    const int bw = (tid & 31) * 2;

    const int laneRow = (lane & 7) + ((lane >> 3) & 1) * 8;
    const int laneSeg = (lane >> 4) * 4;
    const unsigned vbase = (unsigned)__cvta_generic_to_shared(smg);
    const unsigned aLane = vbase + ((wr*32 + laneRow)*VP + laneSeg) * 4;
    const int kRow = lane & 15;
    const int nSel = lane >> 4;
    const unsigned bLane = vbase + (64*VP + kRow*WPB + wc*16 + nSel*4) * 4;

    float4 ra[2], rb[4];
    auto ldA = [&](int p, int k0) -> float4 {
        long row = aR + p*32;
        if (!KG || (k0 + aC + 4 <= K))
            return *reinterpret_cast<const float4*>(At + row*K + k0 + aC);
        float4 v = make_float4(0.f, 0.f, 0.f, 0.f);
        if (k0 + aC     < K) v.x = At[row*K + k0 + aC];
        if (k0 + aC + 1 < K) v.y = At[row*K + k0 + aC + 1];
        if (k0 + aC + 2 < K) v.z = At[row*K + k0 + aC + 2];
        if (k0 + aC + 3 < K) v.w = At[row*K + k0 + aC + 3];
        return v;
    };
    auto ldB = [&](int r, int k0) -> float4 {
        int row = k0 + r;
        if (!KG || row < K)
            return *reinterpret_cast<const float4*>(Bt + (long)row*N + bC);
        return make_float4(0.f, 0.f, 0.f, 0.f);
    };

    #pragma unroll
    for (int p = 0; p < 2; p++) ra[p] = ldA(p, 0);
    rb[0] = ldB(2*kp,      0);
    rb[1] = ldB(2*kp + 1,  0);
    rb[2] = ldB(2*kp + 16, 0);
    rb[3] = ldB(2*kp + 17, 0);

    auto sts = [&](int buf) {
        unsigned* V = smg + buf*BUFW;
        unsigned* W = V + 64*VP;
        #pragma unroll
        for (int p = 0; p < 2; p++) {
            int m = aR + p*32;
            uint2 w;
            w.x = pack_h2(ra[p].x, ra[p].y);
            w.y = pack_h2(ra[p].z, ra[p].w);
            *reinterpret_cast<uint2*>(&V[m*VP + (aC >> 1)]) = w;
        }
        {
            uint2 w;
            w.x = pack_h2(rb[0].x, rb[0].y); w.y = pack_h2(rb[0].z, rb[0].w);
            *reinterpret_cast<uint2*>(&W[(2*kp     )*WPB + bw]) = w;
            w.x = pack_h2(rb[1].x, rb[1].y); w.y = pack_h2(rb[1].z, rb[1].w);
            *reinterpret_cast<uint2*>(&W[(2*kp + 1 )*WPB + bw]) = w;
            w.x = pack_h2(rb[2].x, rb[2].y); w.y = pack_h2(rb[2].z, rb[2].w);
            *reinterpret_cast<uint2*>(&W[(2*kp + 16)*WPB + bw]) = w;
            w.x = pack_h2(rb[3].x, rb[3].y); w.y = pack_h2(rb[3].z, rb[3].w);
            *reinterpret_cast<uint2*>(&W[(2*kp + 17)*WPB + bw]) = w;
        }
    };
    sts(0);
    __syncthreads();

    float acc[8][4];
    #pragma unroll
    for (int i = 0; i < 8; i++) { acc[i][0]=0.f; acc[i][1]=0.f; acc[i][2]=0.f; acc[i][3]=0.f; }

    int cur = 0;
    for (int k0 = 0; k0 < K; k0 += 32) {
        const bool nxt = (k0 + 32) < K;
        if (nxt) {
            #pragma unroll
            for (int p = 0; p < 2; p++) ra[p] = ldA(p, k0 + 32);
            rb[0] = ldB(2*kp,      k0 + 32);
            rb[1] = ldB(2*kp + 1,  k0 + 32);
            rb[2] = ldB(2*kp + 16, k0 + 32);
            rb[3] = ldB(2*kp + 17, k0 + 32);
        }
        const unsigned aBuf = aLane + cur*BUFW*4;
        const unsigned bBuf = bLane + cur*BUFW*4;
        #pragma unroll
        for (int kt = 0; kt < 2; kt++) {
            unsigned a[2][4], b[4][2];
            #pragma unroll
            for (int mi = 0; mi < 2; mi++)
                ldsm_x4(a[mi][0], a[mi][1], a[mi][2], a[mi][3],
                        aBuf + mi*16*VP*4 + kt*32);
            {
                unsigned r0, r1, r2, r3;
                ldsm_x4_t(r0, r1, r2, r3, bBuf + kt*16*WPB*4);
                b[0][0]=r0; b[0][1]=r1; b[1][0]=r2; b[1][1]=r3;
                ldsm_x4_t(r0, r1, r2, r3, bBuf + kt*16*WPB*4 + 32);
                b[2][0]=r0; b[2][1]=r1; b[3][0]=r2; b[3][1]=r3;
            }
            #pragma unroll
            for (int mi = 0; mi < 2; mi++)
                #pragma unroll
                for (int nj = 0; nj < 4; nj++)
                    mma_f16(acc[mi*4+nj], a[mi][0],a[mi][1],a[mi][2],a[mi][3],
                            b[nj][0], b[nj][1]);
        }
        if (nxt) {
            sts(cur ^ 1);
            __syncthreads();
            cur ^= 1;
        }
    }

    #pragma unroll
    for (int mi = 0; mi < 2; mi++) {
        #pragma unroll
        for (int nj = 0; nj < 4; nj++) {
            float* d = acc[mi*4+nj];
            int r0 = blockIdx.y*64 + wr*32 + mi*16 + g;
            int col = blockIdx.x*128 + wc*32 + nj*8 + tg*2;
            float b0 = RBIAS ? bias[r0] : 0.f;
            float b1 = RBIAS ? bias[r0+8] : 0.f;
            float2 v0 = make_float2(d[0]+b0, d[1]+b0);
            float2 v1 = make_float2(d[2]+b1, d[3]+b1);
            float2* p0 = reinterpret_cast<float2*>(C + (long)r0*N + col);
            float2* p1 = reinterpret_cast<float2*>(C + (long)(r0+8)*N + col);
            if (ACC) { float2 o0 = *p0, o1 = *p1; v0.x+=o0.x; v0.y+=o0.y; v1.x+=o1.x; v1.y+=o1.y; }
            if (RELU) { v0.x=fmaxf(v0.x,0.f); v0.y=fmaxf(v0.y,0.f); v1.x=fmaxf(v1.x,0.f); v1.y=fmaxf(v1.y,0.f); }
            *p0 = v0; *p1 = v1;
        }
    }
}

// ---------------------------------------------------------------------
// attn_fused: INH = half q/k/v inputs (and half ctx output when CTX).
// ---------------------------------------------------------------------
#define QP 36
#define KP 36
#define VBP 68
#define PP 132

template<int MASK, bool CTX, bool INH>
__global__ __launch_bounds__(256) void attn_fused(
    const void* __restrict__ Qp, const void* __restrict__ Kp,
    const void* __restrict__ Vp, float* __restrict__ P,
    void* __restrict__ Cctx,
    int Kdim, int lda, int ldb,
    long strA, long offHA, long strB, long offHB,
    int Hh, float scale, const int* __restrict__ tok, int tokStride)
{
    extern __shared__ unsigned sma[];
    unsigned* Qs = sma;
    unsigned* Ks = sma + 64*QP;
    unsigned* Vs = sma + 64*QP + 256*KP;
    unsigned* Ps = sma;
    __shared__ float red[64*4];

    const int tid = threadIdx.x, warp = tid >> 5, lane = tid & 31;
    const int g = lane >> 2, tg = lane & 3;
    const int wr = warp >> 2, wc = warp & 3;
    const int z = blockIdx.y;
    const int bb = z / Hh, hh = z - bb*Hh;
    const int rowTile = blockIdx.x;
    const int rowBase = rowTile * 64;

    float acc[16][4];
    #pragma unroll
    for (int i = 0; i < 16; i++) { acc[i][0]=0.f; acc[i][1]=0.f; acc[i][2]=0.f; acc[i][3]=0.f; }

    for (int k0 = 0; k0 < Kdim; k0 += 64) {
        if (INH) {
            const __half* Qb = (const __half*)Qp + (long)bb*strA + (long)hh*offHA + (long)rowBase*lda;
            const __half* Kb = (const __half*)Kp + (long)bb*strB + (long)hh*offHB;
            #pragma unroll
            for (int p = 0; p < 4; p++) {
                int idx = tid + p*256;
                int r = idx >> 4, c4 = idx & 15;
                uint2 w = *reinterpret_cast<const uint2*>(Qb + (long)r*lda + k0 + c4*4);
                *reinterpret_cast<uint2*>(&Qs[r*QP + c4*2]) = w;
            }
            #pragma unroll
            for (int p = 0; p < 16; p++) {
                int idx = tid + p*256;
                int r = idx >> 4, c4 = idx & 15;
                uint2 w = *reinterpret_cast<const uint2*>(Kb + (long)r*ldb + k0 + c4*4);
                *reinterpret_cast<uint2*>(&Ks[r*KP + c4*2]) = w;
            }
            if (CTX && k0 == 0) {
                const __half* Vb = (const __half*)Vp + (long)bb*strB + (long)hh*offHB;
                #pragma unroll
                for (int p = 0; p < 8; p++) {
                    int idx = tid + p*256;
                    int r2 = idx >> 4, c4 = idx & 15;
                    uint2 a0 = *reinterpret_cast<const uint2*>(Vb + (long)(2*r2  )*ldb + c4*4);
                    uint2 b0 = *reinterpret_cast<const uint2*>(Vb + (long)(2*r2+1)*ldb + c4*4);
                    uint4 w;
                    w.x = __byte_perm(a0.x, b0.x, 0x5410);
                    w.y = __byte_perm(a0.x, b0.x, 0x7632);
                    w.z = __byte_perm(a0.y, b0.y, 0x5410);
                    w.w = __byte_perm(a0.y, b0.y, 0x7632);
                    *reinterpret_cast<uint4*>(&Vs[r2*VBP + c4*4]) = w;
                }
            }
        } else {
            const float* Qb = (const float*)Qp + (long)bb*strA + (long)hh*offHA + (long)rowBase*lda;
            const float* Kb = (const float*)Kp + (long)bb*strB + (long)hh*offHB;
            #pragma unroll
            for (int p = 0; p < 4; p++) {
                int idx = tid + p*256;
                int r = idx >> 4, c4 = idx & 15;
                float4 v = *reinterpret_cast<const float4*>(Qb + (long)r*lda + k0 + c4*4);
                uint2 w; w.x = pack_h2(v.x, v.y); w.y = pack_h2(v.z, v.w);
                *reinterpret_cast<uint2*>(&Qs[r*QP + c4*2]) = w;
            }
            #pragma unroll
            for (int p = 0; p < 16; p++) {
                int idx = tid + p*256;
                int r = idx >> 4, c4 = idx & 15;
                float4 v = *reinterpret_cast<const float4*>(Kb + (long)r*ldb + k0 + c4*4);
                uint2 w; w.x = pack_h2(v.x, v.y); w.y = pack_h2(v.z, v.w);
                *reinterpret_cast<uint2*>(&Ks[r*KP + c4*2]) = w;
            }
        }
        __syncthreads();
        #pragma unroll
        for (int kt = 0; kt < 4; kt++) {
            unsigned a[2][4], b[8][2];
            #pragma unroll
            for (int mi = 0; mi < 2; mi++) {
                int mb = wr*32 + mi*16;
                a[mi][0] = Qs[(mb+g  )*QP + kt*8 + tg];
                a[mi][1] = Qs[(mb+g+8)*QP + kt*8 + tg];
                a[mi][2] = Qs[(mb+g  )*QP + kt*8 + tg + 4];
                a[mi][3] = Qs[(mb+g+8)*QP + kt*8 + tg + 4];
            }
            #pragma unroll
            for (int nj = 0; nj < 8; nj++) {
                int nb = wc*64 + nj*8;
                b[nj][0] = Ks[(nb+g)*KP + kt*8 + tg];
                b[nj][1] = Ks[(nb+g)*KP + kt*8 + tg + 4];
            }
            #pragma unroll
            for (int mi = 0; mi < 2; mi++)
                #pragma unroll
                for (int nj = 0; nj < 8; nj++)
                    mma_f16(acc[mi*8+nj], a[mi][0],a[mi][1],a[mi][2],a[mi][3],
                            b[nj][0], b[nj][1]);
        }
        if (k0 + 64 < Kdim) __syncthreads();
    }

    // ---- scale + mask ----
    #pragma unroll
    for (int mi = 0; mi < 2; mi++) {
        #pragma unroll
        for (int nj = 0; nj < 8; nj++) {
            float* d = acc[mi*8+nj];
            int col = wc*64 + nj*8 + tg*2;
            int lr0 = wr*32 + mi*16 + g;
            #pragma unroll
            for (int c = 0; c < 4; c++) {
                int gcol = col + (c & 1);
                int grow = rowBase + lr0 + ((c >> 1) * 8);
                float v = d[c] * scale;
                if (MASK == 1) {
                    if (tok[bb*tokStride + gcol] == 0 || gcol > grow) v = -1e9f;
                } else if (MASK == 2) {
                    if (tok[bb*tokStride + gcol] == 0) v = -1e9f;
                }
                d[c] = v;
            }
        }
    }

    // ---- softmax (fp32) ----
    float rmax[4];
    #pragma unroll
    for (int mi = 0; mi < 2; mi++) {
        float m0 = -1e30f, m1 = -1e30f;
        #pragma unroll
        for (int nj = 0; nj < 8; nj++) {
            float* d = acc[mi*8+nj];
            m0 = fmaxf(m0, fmaxf(d[0], d[1]));
            m1 = fmaxf(m1, fmaxf(d[2], d[3]));
        }
        rmax[mi*2+0] = m0; rmax[mi*2+1] = m1;
    }
    #pragma unroll
    for (int i = 0; i < 4; i++) {
        rmax[i] = fmaxf(rmax[i], __shfl_xor_sync(0xffffffffu, rmax[i], 1));
        rmax[i] = fmaxf(rmax[i], __shfl_xor_sync(0xffffffffu, rmax[i], 2));
    }
    if (tg == 0) {
        #pragma unroll
        for (int mi = 0; mi < 2; mi++) {
            red[(wr*32 + mi*16 + g    )*4 + wc] = rmax[mi*2+0];
            red[(wr*32 + mi*16 + g + 8)*4 + wc] = rmax[mi*2+1];
        }
    }
    __syncthreads();
    float fmax4[4];
    #pragma unroll
    for (int mi = 0; mi < 2; mi++) {
        int r0 = wr*32 + mi*16 + g, r1 = r0 + 8;
        fmax4[mi*2+0] = fmaxf(fmaxf(red[r0*4+0], red[r0*4+1]), fmaxf(red[r0*4+2], red[r0*4+3]));
        fmax4[mi*2+1] = fmaxf(fmaxf(red[r1*4+0], red[r1*4+1]), fmaxf(red[r1*4+2], red[r1*4+3]));
    }
    __syncthreads();

    float rsum[4] = {0.f, 0.f, 0.f, 0.f};
    #pragma unroll
    for (int mi = 0; mi < 2; mi++) {
        #pragma unroll
        for (int nj = 0; nj < 8; nj++) {
            float* d = acc[mi*8+nj];
            d[0] = __expf(d[0] - fmax4[mi*2+0]);
            d[1] = __expf(d[1] - fmax4[mi*2+0]);
            d[2] = __expf(d[2] - fmax4[mi*2+1]);
            d[3] = __expf(d[3] - fmax4[mi*2+1]);
            rsum[mi*2+0] += d[0] + d[1];
            rsum[mi*2+1] += d[2] + d[3];
        }
    }
    #pragma unroll
    for (int i = 0; i < 4; i++) {
        rsum[i] += __shfl_xor_sync(0xffffffffu, rsum[i], 1);
        rsum[i] += __shfl_xor_sync(0xffffffffu, rsum[i], 2);
    }
    if (tg == 0) {
        #pragma unroll
        for (int mi = 0; mi < 2; mi++) {
            red[(wr*32 + mi*16 + g    )*4 + wc] = rsum[mi*2+0];
            red[(wr*32 + mi*16 + g + 8)*4 + wc] = rsum[mi*2+1];
        }
    }
    __syncthreads();
    float rinv[4];
    #pragma unroll
    for (int mi = 0; mi < 2; mi++) {
        int r0 = wr*32 + mi*16 + g, r1 = r0 + 8;
        rinv[mi*2+0] = 1.f / (red[r0*4+0] + red[r0*4+1] + red[r0*4+2] + red[r0*4+3]);
        rinv[mi*2+1] = 1.f / (red[r1*4+0] + red[r1*4+1] + red[r1*4+2] + red[r1*4+3]);
    }

    float* Pb = P + (long)z * 65536L + (long)rowBase * 256;
    #pragma unroll
    for (int mi = 0; mi < 2; mi++) {
        #pragma unroll
        for (int nj = 0; nj < 8; nj++) {
            float* d = acc[mi*8+nj];
            int col = wc*64 + nj*8 + tg*2;
            int r0 = wr*32 + mi*16 + g;
            float p0 = d[0]*rinv[mi*2+0], p1 = d[1]*rinv[mi*2+0];
            float p2 = d[2]*rinv[mi*2+1], p3 = d[3]*rinv[mi*2+1];
            *reinterpret_cast<float2*>(Pb + (long)r0*256 + col) = make_float2(p0, p1);
            *reinterpret_cast<float2*>(Pb + (long)(r0+8)*256 + col) = make_float2(p2, p3);
            if (CTX) {
                int k2 = wc*32 + nj*4 + tg;
                Ps[r0*PP + k2]     = pack_h2(p0, p1);
                Ps[(r0+8)*PP + k2] = pack_h2(p2, p3);
            }
        }
    }

    if (CTX) {
        __syncthreads();
        float acc2[4][4];
        #pragma unroll
        for (int i = 0; i < 4; i++) { acc2[i][0]=0.f; acc2[i][1]=0.f; acc2[i][2]=0.f; acc2[i][3]=0.f; }
        #pragma unroll
        for (int kt = 0; kt < 16; kt++) {
            unsigned a[2][4], b[2][2];
            #pragma unroll
            for (int mi = 0; mi < 2; mi++) {
                int mb = wr*32 + mi*16;
                a[mi][0] = Ps[(mb+g  )*PP + kt*8 + tg];
                a[mi][1] = Ps[(mb+g+8)*PP + kt*8 + tg];
                a[mi][2] = Ps[(mb+g  )*PP + kt*8 + tg + 4];
                a[mi][3] = Ps[(mb+g+8)*PP + kt*8 + tg + 4];
            }
            #pragma unroll
            for (int nj = 0; nj < 2; nj++) {
                int nb = wc*16 + nj*8 + g;
                b[nj][0] = Vs[(kt*8 + tg    )*VBP + nb];
                b[nj][1] = Vs[(kt*8 + tg + 4)*VBP + nb];
            }
            #pragma unroll
            for (int mi = 0; mi < 2; mi++)
                #pragma unroll
                for (int nj = 0; nj < 2; nj++)
                    mma_f16(acc2[mi*2+nj], a[mi][0],a[mi][1],a[mi][2],a[mi][3],
                            b[nj][0], b[nj][1]);
        }
        __half* Cb = (__half*)Cctx + (long)bb*TT*DD + hh*64;
        #pragma unroll
        for (int mi = 0; mi < 2; mi++) {
            #pragma unroll
            for (int nj = 0; nj < 2; nj++) {
                float* d = acc2[mi*2+nj];
                int r0 = rowBase + wr*32 + mi*16 + g;
                int col = wc*16 + nj*8 + tg*2;
                *reinterpret_cast<unsigned*>(Cb + (long)r0*DD + col) = pack_h2(d[0], d[1]);
                *reinterpret_cast<unsigned*>(Cb + (long)(r0+8)*DD + col) = pack_h2(d[2], d[3]);
            }
        }
    }
}

// ---------------------------------------------------------------------
// add_ln: dual output (fp32 + fp16). out may alias a/b; outh separate.
// ---------------------------------------------------------------------
__global__ __launch_bounds__(128) void add_ln(
    const float* __restrict__ a, const float* __restrict__ b,
    float* __restrict__ out, __half* __restrict__ outh,
    const float* __restrict__ g, const float* __restrict__ beta)
{
    long off = (long)blockIdx.x * DD;
    int t = threadIdx.x;
    int warp = t >> 5, lane = t & 31;
    float4 va = *reinterpret_cast<const float4*>(a + off + t*4);
    float4 vb = *reinterpret_cast<const float4*>(b + off + t*4);
    float4 v;
    v.x = va.x + vb.x; v.y = va.y + vb.y; v.z = va.z + vb.z; v.w = va.w + vb.w;
    __shared__ float ws[4], ws2[4];

    float s = v.x + v.y + v.z + v.w;
    #pragma unroll
    for (int o = 16; o > 0; o >>= 1) s += __shfl_xor_sync(0xffffffffu, s, o);
    if (lane == 0) ws[warp] = s;
    __syncthreads();
    float mu = (ws[0]+ws[1]+ws[2]+ws[3]) * (1.f/DD);

    float4 d;
    d.x = v.x - mu; d.y = v.y - mu; d.z = v.z - mu; d.w = v.w - mu;
    float q = d.x*d.x + d.y*d.y + d.z*d.z + d.w*d.w;
    #pragma unroll
    for (int o = 16; o > 0; o >>= 1) q += __shfl_xor_sync(0xffffffffu, q, o);
    if (lane == 0) ws2[warp] = q;
    __syncthreads();
    float rstd = rsqrtf((ws2[0]+ws2[1]+ws2[2]+ws2[3]) * (1.f/DD) + 1e-5f);

    float4 gg = g ? *reinterpret_cast<const float4*>(g + t*4)
                  : make_float4(1.f, 1.f, 1.f, 1.f);
    float4 bb = beta ? *reinterpret_cast<const float4*>(beta + t*4)
                     : make_float4(0.f, 0.f, 0.f, 0.f);
    float4 o;
    o.x = d.x * rstd * gg.x + bb.x;
    o.y = d.y * rstd * gg.y + bb.y;
    o.z = d.z * rstd * gg.z + bb.z;
    o.w = d.w * rstd * gg.w + bb.w;
    *reinterpret_cast<float4*>(out + off + t*4) = o;
    uint2 oh; oh.x = pack_h2(o.x, o.y); oh.y = pack_h2(o.z, o.w);
    *reinterpret_cast<uint2*>(outh + off + t*4) = oh;
}

__global__ void embed_pe(const int* __restrict__ dec,
                         const float* __restrict__ emb,
                         float* __restrict__ x, __half* __restrict__ xh)
{
    long idx = (long)blockIdx.x * blockDim.x + threadIdx.x;
    if (idx >= (long)BT*DD) return;
    int d  = (int)(idx % DD);
    long bt = idx / DD;
    int t  = (int)(bt % TT);
    int tokidx = dec[bt];
    int d2 = d & ~1;
    float div = expf(-logf(10000.f) * (float)d2 / (float)DD);
    float ang = (float)t * div;
    float pe = (d & 1) ? cosf(ang) : sinf(ang);
    float v = emb[(long)tokidx*DD + d] + pe;
    x[idx] = v;
    xh[idx] = __float2half(v);
}

// out(f32 multi not needed) -> write multih half
__global__ void add3h(const float* __restrict__ a, const float* __restrict__ bias,
                      const float* __restrict__ c, __half* __restrict__ outh, long n)
{
    long i = (long)blockIdx.x * blockDim.x + threadIdx.x;
    if (i >= n) return;
    outh[i] = __float2half(a[i] + bias[i % DD] + c[i]);
}

__global__ void copyk4(const float4* __restrict__ src, float4* __restrict__ dst, long n4)
{
    long i = (long)blockIdx.x * blockDim.x + threadIdx.x;
    if (i < n4) dst[i] = src[i];
}

// ---------------------------------------------------------------------
extern "C" void kernel_launch(void* const* d_in, const int* in_sizes, int n_in,
                              void* d_out, int out_size)
{
    const int*   dec     = (const int*)  d_in[0];
    const int*   enc     = (const int*)  d_in[1];
    const float* enc_out = (const float*)d_in[2];
    const float* ast_out = (const float*)d_in[3];
    const float* src_emb = (const float*)d_in[4];
    const float* ast_emb = (const float*)d_in[5];
    const float* emb     = (const float*)d_in[7];
    const float* attn_W  = (const float*)d_in[8];
    const float* ln_g    = (const float*)d_in[9];
    const float* ln_b    = (const float*)d_in[10];
    const float* W1      = (const float*)d_in[11];
    const float* W2      = (const float*)d_in[12];
    const float* conv_w  = (const float*)d_in[13];
    const float* conv_b  = (const float*)d_in[14];
    const float* mffnW   = (const float*)d_in[15];
    const float* mffnb   = (const float*)d_in[16];
    float* out = (float*)d_out;

    float *x,*t,*pt,*ast1,*aste,*mm,*mmctx;
    __half *wb, *qkvh, *ch, *hh, *xh, *ench, *multih;
    cudaGetSymbolAddress((void**)&x,     g_x);
    cudaGetSymbolAddress((void**)&xh,    g_xh);
    cudaGetSymbolAddress((void**)&t,     g_t);
    cudaGetSymbolAddress((void**)&pt,    g_pt);
    cudaGetSymbolAddress((void**)&qkvh,  g_qkvh);
    cudaGetSymbolAddress((void**)&ch,    g_ch);
    cudaGetSymbolAddress((void**)&hh,    g_hh);
    cudaGetSymbolAddress((void**)&ench,  g_ench);
    cudaGetSymbolAddress((void**)&multih,g_multih);
    cudaGetSymbolAddress((void**)&ast1,  g_ast1);
    cudaGetSymbolAddress((void**)&aste,  g_aste);
    cudaGetSymbolAddress((void**)&mm,    g_mm);
    cudaGetSymbolAddress((void**)&mmctx, g_mmctx);
    cudaGetSymbolAddress((void**)&wb,    g_wb);

    const int GM_SMEM  = 2*BUFW*4;
    const int AT_SMEM  = (64*QP + 256*KP + 128*VBP)*4;
    const int MM_SMEM  = (64*QP + 256*KP)*4;
    cudaFuncSetAttribute((const void*)gemm2<false,false,false,false>, cudaFuncAttributeMaxDynamicSharedMemorySize, GM_SMEM);
    cudaFuncSetAttribute((const void*)gemm2<false,true ,false,false>, cudaFuncAttributeMaxDynamicSharedMemorySize, GM_SMEM);
    cudaFuncSetAttribute((const void*)gemm2<false,false,true ,true >, cudaFuncAttributeMaxDynamicSharedMemorySize, GM_SMEM);
    cudaFuncSetAttribute((const void*)gemm2h<false,true ,true >, cudaFuncAttributeMaxDynamicSharedMemorySize, GM_SMEM);
    cudaFuncSetAttribute((const void*)gemm2h<true ,true ,true >, cudaFuncAttributeMaxDynamicSharedMemorySize, GM_SMEM);
    cudaFuncSetAttribute((const void*)gemm2h<false,true ,false>, cudaFuncAttributeMaxDynamicSharedMemorySize, GM_SMEM);
    cudaFuncSetAttribute((const void*)attn_fused<0,false,false>, cudaFuncAttributeMaxDynamicSharedMemorySize, MM_SMEM);
    cudaFuncSetAttribute((const void*)attn_fused<0,true ,true >, cudaFuncAttributeMaxDynamicSharedMemorySize, AT_SMEM);
    cudaFuncSetAttribute((const void*)attn_fused<1,true ,true >, cudaFuncAttributeMaxDynamicSharedMemorySize, AT_SMEM);
    cudaFuncSetAttribute((const void*)attn_fused<2,true ,true >, cudaFuncAttributeMaxDynamicSharedMemorySize, AT_SMEM);

    __half* q = qkvh;
    __half* k = qkvh + (long)BT*DD;
    __half* v = qkvh + 2L*BT*DD;

    // ---- one-time conversions (main stream; feed layer 0) ----
    w2h<<<(int)((18874368/4 + 255)/256), 256>>>(attn_W, wb + WB_ATTN, 18874368/4);
    w2h<<<(int)((6291456/4  + 255)/256), 256>>>(W1,     wb + WB_W1,   6291456/4);
    w2h<<<(int)((6291456/4  + 255)/256), 256>>>(W2,     wb + WB_W2,   6291456/4);
    w2h<<<(int)(((long)BB*SS*DD/4 + 255)/256), 256>>>(enc_out, ench, (long)BB*SS*DD/4);

    // ---- fork: preamble on s2 (writes ONLY pt/ast1/aste/mm/mmctx/multih) ----
    cudaStream_t s2;
    cudaStreamCreate(&s2);
    cudaEvent_t evF, evJ;
    cudaEventCreateWithFlags(&evF, cudaEventDisableTiming);
    cudaEventCreateWithFlags(&evJ, cudaEventDisableTiming);
    cudaEventRecord(evF, 0);
    cudaStreamWaitEvent(s2, evF, 0);

    {
        dim3 gc(DD/128, SS/64, BB);
        gemm2<false,false,true,true><<<gc, 256, GM_SMEM, s2>>>(
            conv_w, conv_w, conv_w, 0L, ast_out, (long)NA*DD,
            ast1, (long)SS*DD, conv_b, SS, DD, NA);
        gemm2<false,false,true,true><<<gc, 256, GM_SMEM, s2>>>(
            conv_w, conv_w, conv_w, 0L, ast_emb, (long)NA*DD,
            aste, (long)SS*DD, conv_b, SS, DD, NA);
        dim3 gs(SS/64, BB);
        attn_fused<0,false,false><<<gs, 256, MM_SMEM, s2>>>(ast1, enc_out, nullptr, mm, nullptr,
            DD, DD, DD, (long)SS*DD, 0L, (long)SS*DD, 0L,
            1, 0.125f, nullptr, 0);
        dim3 gm(DD/128, SS/64, BB);
        gemm2<false,false,false,false><<<gm, 256, GM_SMEM, s2>>>(
            mm, mm, mm, (long)SS*SS, enc_out, (long)SS*DD,
            mmctx, (long)SS*DD, nullptr, SS, DD, SS);
        dim3 gp(DD/128, BT/64, 1);
        gemm2<false,false,false,false><<<gp, 256, GM_SMEM, s2>>>(
            src_emb, src_emb, src_emb, 0L, mffnW, 0L, pt, 0L, nullptr, BT, DD, DD);
        gemm2<false,true ,false,false><<<gp, 256, GM_SMEM, s2>>>(
            aste, aste, aste, 0L, mffnW + DD*DD, 0L, pt, 0L, nullptr, BT, DD, DD);
        long n = (long)BB*SS*DD;
        add3h<<<(int)((n + 255)/256), 256, 0, s2>>>(pt, mffnb, mmctx, multih, n);
    }
    cudaEventRecord(evJ, s2);

    // ---------------- main path ----------------
    embed_pe<<<(BT*DD + 255)/256, 256>>>(dec, emb, x, xh);

    dim3 gQKV(DD/128, BT/64, 3);
    dim3 gProj(DD/128, BT/64, 1);
    dim3 gF1(DFF/128, BT/64, 1);
    dim3 gScore(TT/64, BB*HH);

    for (int l = 0; l < LL; l++) {
        for (int a = 0; a < 3; a++) {
            const __half* wqkv = wb + WB_ATTN + (long)((l*3 + a)*4) * 262144;
            const __half* wo   = wb + WB_ATTN + (long)((l*3 + a)*4 + 3) * 262144;
            const __half* xk = (a == 0) ? xh : (a == 1 ? ench : multih);

            if (l == 0 && a == 2) cudaStreamWaitEvent(0, evJ, 0);

            gemm2h<false,true,true><<<gQKV, 256, GM_SMEM>>>(
                xh, xk, xk, 0L, wqkv, 262144L, qkvh, (long)BT*DD, BT, DD, DD);

            long attnBase = (a == 0 ? SELF_OFF : (a == 1 ? ENC_OFF : AST_OFF))
                            + (long)l * BHTT;
            float* P = out + attnBase;

            if (a == 0)
                attn_fused<1,true,true><<<gScore, 256, AT_SMEM>>>(q, k, v, P, ch,
                    DKK, DD, DD, (long)TT*DD, 64L, (long)TT*DD, 64L,
                    HH, 0.125f, dec, TT);
            else if (a == 1)
                attn_fused<2,true,true><<<gScore, 256, AT_SMEM>>>(q, k, v, P, ch,
                    DKK, DD, DD, (long)TT*DD, 64L, (long)TT*DD, 64L,
                    HH, 0.125f, enc, SS);
            else
                attn_fused<0,true,true><<<gScore, 256, AT_SMEM>>>(q, k, v, P, ch,
                    DKK, DD, DD, (long)TT*DD, 64L, (long)TT*DD, 64L,
                    HH, 0.125f, nullptr, 0);

            gemm2h<false,true,false><<<gProj, 256, GM_SMEM>>>(
                ch, ch, ch, 0L, wo, 0L, t, 0L, BT, DD, DD);
            add_ln<<<BT, 128>>>(t, x, x, xh,
                ln_g + (long)(l*3 + a)*DD, ln_b + (long)(l*3 + a)*DD);
        }
        gemm2h<true,true,true><<<gF1, 256, GM_SMEM>>>(
            xh, xh, xh, 0L, wb + WB_W1 + (long)l*1048576, 0L, hh, 0L, BT, DFF, DD);
        gemm2h<false,true,false><<<gProj, 256, GM_SMEM>>>(
            hh, hh, hh, 0L, wb + WB_W2 + (long)l*1048576, 0L, t, 0L, BT, DD, DFF);
        add_ln<<<BT, 128>>>(t, x, x, xh, nullptr, nullptr);
    }

    copyk4<<<(BT*DD/4 + 255)/256, 256>>>(
        reinterpret_cast<const float4*>(x), reinterpret_cast<float4*>(out),
        (long)BT*DD/4);

    cudaStreamDestroy(s2);
    cudaEventDestroy(evF);
    cudaEventDestroy(evJ);
}

// round 17
// speedup vs baseline: 1.3857x; 1.0133x over previous
#include <cuda_runtime.h>
#include <cuda_fp16.h>
#include <math.h>

// Problem dims
#define BB 16
#define TT 256
#define SS 256
#define NA 300
#define DD 512
#define HH 8
#define DKK 64
#define DFF 2048
#define LL 6

#define BT (BB*TT)                 // 4096
#define BHTT ((long)BB*HH*TT*TT)   // 8388608

#define SELF_OFF 2097152L
#define ENC_OFF  (SELF_OFF + (long)LL*BHTT)
#define AST_OFF  (ENC_OFF  + (long)LL*BHTT)

// ------------- scratch -------------
__device__ float g_x[BT*DD];
__device__ __half g_xh[BT*DD];
__device__ float g_t[BT*DD];
__device__ float g_pt[BT*DD];          // preamble-only temp
__device__ __half g_qkvh[3*BT*DD];
__device__ __half g_ch[BT*DD];
__device__ __half g_hh[BT*DFF];
__device__ __half g_ench[BB*SS*DD];
__device__ __half g_multih[BB*SS*DD];
__device__ float g_ast1[BB*SS*DD];
__device__ float g_aste[BB*SS*DD];
__device__ float g_mm[BB*SS*SS];
__device__ float g_mmctx[BB*SS*DD];

// fp16 weights: attn (72 x 512x512) | W1 (6 x 512x2048) | W2 (6 x 2048x512)
#define WB_ATTN 0L
#define WB_W1   18874368L
#define WB_W2   25165824L
__device__ __half g_wb[31457280];

// ------------- helpers -------------
__device__ __forceinline__ unsigned pack_h2(float x, float y) {
    __half2 h = __floats2half2_rn(x, y);
    return *reinterpret_cast<unsigned*>(&h);
}
__device__ __forceinline__ void mma_f16(float* d,
    unsigned a0, unsigned a1, unsigned a2, unsigned a3,
    unsigned b0, unsigned b1)
{
    asm volatile(
        "mma.sync.aligned.m16n8k16.row.col.f32.f16.f16.f32 "
        "{%0,%1,%2,%3},{%4,%5,%6,%7},{%8,%9},{%0,%1,%2,%3};\n"
        : "+f"(d[0]), "+f"(d[1]), "+f"(d[2]), "+f"(d[3])
        : "r"(a0), "r"(a1), "r"(a2), "r"(a3), "r"(b0), "r"(b1));
}
__device__ __forceinline__ void ldsm_x4(unsigned& r0, unsigned& r1,
                                        unsigned& r2, unsigned& r3, unsigned addr)
{
    asm volatile("ldmatrix.sync.aligned.m8n8.x4.shared.b16 {%0,%1,%2,%3}, [%4];"
        : "=r"(r0), "=r"(r1), "=r"(r2), "=r"(r3) : "r"(addr));
}
__device__ __forceinline__ void ldsm_x4_t(unsigned& r0, unsigned& r1,
                                          unsigned& r2, unsigned& r3, unsigned addr)
{
    asm volatile("ldmatrix.sync.aligned.m8n8.x4.trans.shared.b16 {%0,%1,%2,%3}, [%4];"
        : "=r"(r0), "=r"(r1), "=r"(r2), "=r"(r3) : "r"(addr));
}

// f32 -> f16 elementwise (vectorized by 4)
__global__ void w2h(const float* __restrict__ in, __half* __restrict__ outp, long n4)
{
    long i = (long)blockIdx.x * blockDim.x + threadIdx.x;
    if (i >= n4) return;
    float4 v = reinterpret_cast<const float4*>(in)[i];
    uint2 w; w.x = pack_h2(v.x, v.y); w.y = pack_h2(v.z, v.w);
    *reinterpret_cast<uint2*>(outp + i*4) = w;
}

#define VP 20
#define WPB 68
#define BUFW (64*VP + 32*WPB)   // 3456 words

// ---------------------------------------------------------------------
// gemm2h: C[M,N] = A[M,K] @ B[K,N](f16). AH: A is f16; OUTH: C is f16.
// ---------------------------------------------------------------------
template<bool RELU, bool AH, bool OUTH>
__global__ __launch_bounds__(256, 2) void gemm2h(
    const void* __restrict__ A0, const void* __restrict__ A1,
    const void* __restrict__ A2, long strA,
    const __half* __restrict__ B0, long strB,
    void* __restrict__ C0, long strC,
    int M, int N, int K)
{
    extern __shared__ unsigned smg[];

    const int tid = threadIdx.x, warp = tid >> 5, lane = tid & 31;
    const int g = lane >> 2, tg = lane & 3;
    const int wr = warp >> 2, wc = warp & 3;
    const int z = blockIdx.z;

    const void* Ap = (z == 0) ? A0 : (z == 1 ? A1 : A2);
    const float*  Atf = AH ? nullptr : ((const float*)Ap + (long)z*strA + (long)blockIdx.y*64*K);
    const __half* Ath = AH ? ((const __half*)Ap + (long)z*strA + (long)blockIdx.y*64*K) : nullptr;
    const __half* Bt = B0 + (long)z * strB + blockIdx.x * 128;

    const int aR = tid >> 3;
    const int aC = (tid & 7) * 4;
    const int bR = tid >> 4;
    const int bC8 = (tid & 15) * 8;

    const int laneRow = (lane & 7) + ((lane >> 3) & 1) * 8;
    const int laneSeg = (lane >> 4) * 4;
    const unsigned vbase = (unsigned)__cvta_generic_to_shared(smg);
    const unsigned aLane = vbase + ((wr*32 + laneRow)*VP + laneSeg) * 4;
    const int kRow = lane & 15;
    const int nSel = lane >> 4;
    const unsigned bLane = vbase + (64*VP + kRow*WPB + wc*16 + nSel*4) * 4;

    float4 raf[2];
    uint2  rah[2];
    uint4  rbh[2];

    auto ldA = [&](int p, int k0) {
        long row = aR + p*32;
        if (AH) rah[p] = *reinterpret_cast<const uint2*>(Ath + row*K + k0 + aC);
        else    raf[p] = *reinterpret_cast<const float4*>(Atf + row*K + k0 + aC);
    };
    auto ldB = [&](int p, int k0) {
        rbh[p] = *reinterpret_cast<const uint4*>(Bt + (long)(k0 + bR + p*16)*N + bC8);
    };

    #pragma unroll
    for (int p = 0; p < 2; p++) { ldA(p, 0); ldB(p, 0); }

    auto sts = [&](int buf) {
        unsigned* V = smg + buf*BUFW;
        unsigned* W = V + 64*VP;
        #pragma unroll
        for (int p = 0; p < 2; p++) {
            int m = aR + p*32;
            uint2 w;
            if (AH) w = rah[p];
            else { w.x = pack_h2(raf[p].x, raf[p].y); w.y = pack_h2(raf[p].z, raf[p].w); }
            *reinterpret_cast<uint2*>(&V[m*VP + (aC >> 1)]) = w;
        }
        #pragma unroll
        for (int p = 0; p < 2; p++)
            *reinterpret_cast<uint4*>(&W[(bR + p*16)*WPB + (bC8 >> 1)]) = rbh[p];
    };
    sts(0);
    __syncthreads();

    float acc[8][4];
    #pragma unroll
    for (int i = 0; i < 8; i++) { acc[i][0]=0.f; acc[i][1]=0.f; acc[i][2]=0.f; acc[i][3]=0.f; }

    int cur = 0;
    for (int k0 = 0; k0 < K; k0 += 32) {
        const bool nxt = (k0 + 32) < K;
        if (nxt) {
            #pragma unroll
            for (int p = 0; p < 2; p++) { ldA(p, k0 + 32); ldB(p, k0 + 32); }
        }
        const unsigned aBuf = aLane + cur*BUFW*4;
        const unsigned bBuf = bLane + cur*BUFW*4;
        #pragma unroll
        for (int kt = 0; kt < 2; kt++) {
            unsigned a[2][4], b[4][2];
            #pragma unroll
            for (int mi = 0; mi < 2; mi++)
                ldsm_x4(a[mi][0], a[mi][1], a[mi][2], a[mi][3],
                        aBuf + mi*16*VP*4 + kt*32);
            {
                unsigned r0, r1, r2, r3;
                ldsm_x4_t(r0, r1, r2, r3, bBuf + kt*16*WPB*4);
                b[0][0]=r0; b[0][1]=r1; b[1][0]=r2; b[1][1]=r3;
                ldsm_x4_t(r0, r1, r2, r3, bBuf + kt*16*WPB*4 + 32);
                b[2][0]=r0; b[2][1]=r1; b[3][0]=r2; b[3][1]=r3;
            }
            #pragma unroll
            for (int mi = 0; mi < 2; mi++)
                #pragma unroll
                for (int nj = 0; nj < 4; nj++)
                    mma_f16(acc[mi*4+nj], a[mi][0],a[mi][1],a[mi][2],a[mi][3],
                            b[nj][0], b[nj][1]);
        }
        if (nxt) {
            sts(cur ^ 1);
            __syncthreads();
            cur ^= 1;
        }
    }

    #pragma unroll
    for (int mi = 0; mi < 2; mi++) {
        #pragma unroll
        for (int nj = 0; nj < 4; nj++) {
            float* d = acc[mi*4+nj];
            int r0 = blockIdx.y*64 + wr*32 + mi*16 + g;
            int col = blockIdx.x*128 + wc*32 + nj*8 + tg*2;
            float v0 = d[0], v1 = d[1], v2 = d[2], v3 = d[3];
            if (RELU) {
                v0=fmaxf(v0,0.f); v1=fmaxf(v1,0.f); v2=fmaxf(v2,0.f); v3=fmaxf(v3,0.f);
            }
            if (OUTH) {
                __half* C = (__half*)C0 + (long)z * strC;
                *reinterpret_cast<unsigned*>(C + (long)r0*N + col) = pack_h2(v0, v1);
                *reinterpret_cast<unsigned*>(C + (long)(r0+8)*N + col) = pack_h2(v2, v3);
            } else {
                float* C = (float*)C0 + (long)z * strC;
                *reinterpret_cast<float2*>(C + (long)r0*N + col) = make_float2(v0, v1);
                *reinterpret_cast<float2*>(C + (long)(r0+8)*N + col) = make_float2(v2, v3);
            }
        }
    }
}

// ---------------------------------------------------------------------
// gemm2 (fp32 B) — preamble only (K=300 guard, bias, acc). Unchanged.
// ---------------------------------------------------------------------
template<bool RELU, bool ACC, bool RBIAS, bool KG>
__global__ __launch_bounds__(256, 2) void gemm2(
    const float* __restrict__ A0, const float* __restrict__ A1,
    const float* __restrict__ A2, long strA,
    const float* __restrict__ B0, long strB,
    float* __restrict__ C0, long strC,
    const float* __restrict__ bias,
    int M, int N, int K)
{
    extern __shared__ unsigned smg[];

    const int tid = threadIdx.x, warp = tid >> 5, lane = tid & 31;
    const int g = lane >> 2, tg = lane & 3;
    const int wr = warp >> 2, wc = warp & 3;
    const int z = blockIdx.z;

    const float* A = ((z == 0) ? A0 : (z == 1 ? A1 : A2)) + (long)z * strA;
    const float* At = A + (long)blockIdx.y * 64 * K;
    const float* Bt = B0 + (long)z * strB + blockIdx.x * 128;
    float* C = C0 + (long)z * strC;

    const int aR = tid >> 3;
    const int aC = (tid & 7) * 4;
    const int kp = tid >> 5;
    const int bC = (tid & 31) * 4;
    const int bw = (tid & 31) * 2;

    const int laneRow = (lane & 7) + ((lane >> 3) & 1) * 8;
    const int laneSeg = (lane >> 4) * 4;
    const unsigned vbase = (unsigned)__cvta_generic_to_shared(smg);
    const unsigned aLane = vbase + ((wr*32 + laneRow)*VP + laneSeg) * 4;
    const int kRow = lane & 15;
    const int nSel = lane >> 4;
    const unsigned bLane = vbase + (64*VP + kRow*WPB + wc*16 + nSel*4) * 4;

    float4 ra[2], rb[4];
    auto ldA = [&](int p, int k0) -> float4 {
        long row = aR + p*32;
        if (!KG || (k0 + aC + 4 <= K))
            return *reinterpret_cast<const float4*>(At + row*K + k0 + aC);
        float4 v = make_float4(0.f, 0.f, 0.f, 0.f);
        if (k0 + aC     < K) v.x = At[row*K + k0 + aC];
        if (k0 + aC + 1 < K) v.y = At[row*K + k0 + aC + 1];
        if (k0 + aC + 2 < K) v.z = At[row*K + k0 + aC + 2];
        if (k0 + aC + 3 < K) v.w = At[row*K + k0 + aC + 3];
        return v;
    };
    auto ldB = [&](int r, int k0) -> float4 {
        int row = k0 + r;
        if (!KG || row < K)
            return *reinterpret_cast<const float4*>(Bt + (long)row*N + bC);
        return make_float4(0.f, 0.f, 0.f, 0.f);
    };

    #pragma unroll
    for (int p = 0; p < 2; p++) ra[p] = ldA(p, 0);
    rb[0] = ldB(2*kp,      0);
    rb[1] = ldB(2*kp + 1,  0);
    rb[2] = ldB(2*kp + 16, 0);
    rb[3] = ldB(2*kp + 17, 0);

    auto sts = [&](int buf) {
        unsigned* V = smg + buf*BUFW;
        unsigned* W = V + 64*VP;
        #pragma unroll
        for (int p = 0; p < 2; p++) {
            int m = aR + p*32;
            uint2 w;
            w.x = pack_h2(ra[p].x, ra[p].y);
            w.y = pack_h2(ra[p].z, ra[p].w);
            *reinterpret_cast<uint2*>(&V[m*VP + (aC >> 1)]) = w;
        }
        {
            uint2 w;
            w.x = pack_h2(rb[0].x, rb[0].y); w.y = pack_h2(rb[0].z, rb[0].w);
            *reinterpret_cast<uint2*>(&W[(2*kp     )*WPB + bw]) = w;
            w.x = pack_h2(rb[1].x, rb[1].y); w.y = pack_h2(rb[1].z, rb[1].w);
            *reinterpret_cast<uint2*>(&W[(2*kp + 1 )*WPB + bw]) = w;
            w.x = pack_h2(rb[2].x, rb[2].y); w.y = pack_h2(rb[2].z, rb[2].w);
            *reinterpret_cast<uint2*>(&W[(2*kp + 16)*WPB + bw]) = w;
            w.x = pack_h2(rb[3].x, rb[3].y); w.y = pack_h2(rb[3].z, rb[3].w);
            *reinterpret_cast<uint2*>(&W[(2*kp + 17)*WPB + bw]) = w;
        }
    };
    sts(0);
    __syncthreads();

    float acc[8][4];
    #pragma unroll
    for (int i = 0; i < 8; i++) { acc[i][0]=0.f; acc[i][1]=0.f; acc[i][2]=0.f; acc[i][3]=0.f; }

    int cur = 0;
    for (int k0 = 0; k0 < K; k0 += 32) {
        const bool nxt = (k0 + 32) < K;
        if (nxt) {
            #pragma unroll
            for (int p = 0; p < 2; p++) ra[p] = ldA(p, k0 + 32);
            rb[0] = ldB(2*kp,      k0 + 32);
            rb[1] = ldB(2*kp + 1,  k0 + 32);
            rb[2] = ldB(2*kp + 16, k0 + 32);
            rb[3] = ldB(2*kp + 17, k0 + 32);
        }
        const unsigned aBuf = aLane + cur*BUFW*4;
        const unsigned bBuf = bLane + cur*BUFW*4;
        #pragma unroll
        for (int kt = 0; kt < 2; kt++) {
            unsigned a[2][4], b[4][2];
            #pragma unroll
            for (int mi = 0; mi < 2; mi++)
                ldsm_x4(a[mi][0], a[mi][1], a[mi][2], a[mi][3],
                        aBuf + mi*16*VP*4 + kt*32);
            {
                unsigned r0, r1, r2, r3;
                ldsm_x4_t(r0, r1, r2, r3, bBuf + kt*16*WPB*4);
                b[0][0]=r0; b[0][1]=r1; b[1][0]=r2; b[1][1]=r3;
                ldsm_x4_t(r0, r1, r2, r3, bBuf + kt*16*WPB*4 + 32);
                b[2][0]=r0; b[2][1]=r1; b[3][0]=r2; b[3][1]=r3;
            }
            #pragma unroll
            for (int mi = 0; mi < 2; mi++)
                #pragma unroll
                for (int nj = 0; nj < 4; nj++)
                    mma_f16(acc[mi*4+nj], a[mi][0],a[mi][1],a[mi][2],a[mi][3],
                            b[nj][0], b[nj][1]);
        }
        if (nxt) {
            sts(cur ^ 1);
            __syncthreads();
            cur ^= 1;
        }
    }

    #pragma unroll
    for (int mi = 0; mi < 2; mi++) {
        #pragma unroll
        for (int nj = 0; nj < 4; nj++) {
            float* d = acc[mi*4+nj];
            int r0 = blockIdx.y*64 + wr*32 + mi*16 + g;
            int col = blockIdx.x*128 + wc*32 + nj*8 + tg*2;
            float b0 = RBIAS ? bias[r0] : 0.f;
            float b1 = RBIAS ? bias[r0+8] : 0.f;
            float2 v0 = make_float2(d[0]+b0, d[1]+b0);
            float2 v1 = make_float2(d[2]+b1, d[3]+b1);
            float2* p0 = reinterpret_cast<float2*>(C + (long)r0*N + col);
            float2* p1 = reinterpret_cast<float2*>(C + (long)(r0+8)*N + col);
            if (ACC) { float2 o0 = *p0, o1 = *p1; v0.x+=o0.x; v0.y+=o0.y; v1.x+=o1.x; v1.y+=o1.y; }
            if (RELU) { v0.x=fmaxf(v0.x,0.f); v0.y=fmaxf(v0.y,0.f); v1.x=fmaxf(v1.x,0.f); v1.y=fmaxf(v1.y,0.f); }
            *p0 = v0; *p1 = v1;
        }
    }
}

// ---------------------------------------------------------------------
// attn_fused: INH = half q/k/v inputs (and half ctx output when CTX).
// Now __launch_bounds__(256, 2) for 2 CTAs/SM (smem 80.9KB fits twice).
// ---------------------------------------------------------------------
#define QP 36
#define KP 36
#define VBP 68
#define PP 132

template<int MASK, bool CTX, bool INH>
__global__ __launch_bounds__(256, 2) void attn_fused(
    const void* __restrict__ Qp, const void* __restrict__ Kp,
    const void* __restrict__ Vp, float* __restrict__ P,
    void* __restrict__ Cctx,
    int Kdim, int lda, int ldb,
    long strA, long offHA, long strB, long offHB,
    int Hh, float scale, const int* __restrict__ tok, int tokStride)
{
    extern __shared__ unsigned sma[];
    unsigned* Qs = sma;
    unsigned* Ks = sma + 64*QP;
    unsigned* Vs = sma + 64*QP + 256*KP;
    unsigned* Ps = sma;
    __shared__ float red[64*4];

    const int tid = threadIdx.x, warp = tid >> 5, lane = tid & 31;
    const int g = lane >> 2, tg = lane & 3;
    const int wr = warp >> 2, wc = warp & 3;
    const int z = blockIdx.y;
    const int bb = z / Hh, hh = z - bb*Hh;
    const int rowTile = blockIdx.x;
    const int rowBase = rowTile * 64;

    float acc[16][4];
    #pragma unroll
    for (int i = 0; i < 16; i++) { acc[i][0]=0.f; acc[i][1]=0.f; acc[i][2]=0.f; acc[i][3]=0.f; }

    for (int k0 = 0; k0 < Kdim; k0 += 64) {
        if (INH) {
            const __half* Qb = (const __half*)Qp + (long)bb*strA + (long)hh*offHA + (long)rowBase*lda;
            const __half* Kb = (const __half*)Kp + (long)bb*strB + (long)hh*offHB;
            #pragma unroll
            for (int p = 0; p < 4; p++) {
                int idx = tid + p*256;
                int r = idx >> 4, c4 = idx & 15;
                uint2 w = *reinterpret_cast<const uint2*>(Qb + (long)r*lda + k0 + c4*4);
                *reinterpret_cast<uint2*>(&Qs[r*QP + c4*2]) = w;
            }
            #pragma unroll
            for (int p = 0; p < 16; p++) {
                int idx = tid + p*256;
                int r = idx >> 4, c4 = idx & 15;
                uint2 w = *reinterpret_cast<const uint2*>(Kb + (long)r*ldb + k0 + c4*4);
                *reinterpret_cast<uint2*>(&Ks[r*KP + c4*2]) = w;
            }
            if (CTX && k0 == 0) {
                const __half* Vb = (const __half*)Vp + (long)bb*strB + (long)hh*offHB;
                #pragma unroll
                for (int p = 0; p < 8; p++) {
                    int idx = tid + p*256;
                    int r2 = idx >> 4, c4 = idx & 15;
                    uint2 a0 = *reinterpret_cast<const uint2*>(Vb + (long)(2*r2  )*ldb + c4*4);
                    uint2 b0 = *reinterpret_cast<const uint2*>(Vb + (long)(2*r2+1)*ldb + c4*4);
                    uint4 w;
                    w.x = __byte_perm(a0.x, b0.x, 0x5410);
                    w.y = __byte_perm(a0.x, b0.x, 0x7632);
                    w.z = __byte_perm(a0.y, b0.y, 0x5410);
                    w.w = __byte_perm(a0.y, b0.y, 0x7632);
                    *reinterpret_cast<uint4*>(&Vs[r2*VBP + c4*4]) = w;
                }
            }
        } else {
            const float* Qb = (const float*)Qp + (long)bb*strA + (long)hh*offHA + (long)rowBase*lda;
            const float* Kb = (const float*)Kp + (long)bb*strB + (long)hh*offHB;
            #pragma unroll
            for (int p = 0; p < 4; p++) {
                int idx = tid + p*256;
                int r = idx >> 4, c4 = idx & 15;
                float4 v = *reinterpret_cast<const float4*>(Qb + (long)r*lda + k0 + c4*4);
                uint2 w; w.x = pack_h2(v.x, v.y); w.y = pack_h2(v.z, v.w);
                *reinterpret_cast<uint2*>(&Qs[r*QP + c4*2]) = w;
            }
            #pragma unroll
            for (int p = 0; p < 16; p++) {
                int idx = tid + p*256;
                int r = idx >> 4, c4 = idx & 15;
                float4 v = *reinterpret_cast<const float4*>(Kb + (long)r*ldb + k0 + c4*4);
                uint2 w; w.x = pack_h2(v.x, v.y); w.y = pack_h2(v.z, v.w);
                *reinterpret_cast<uint2*>(&Ks[r*KP + c4*2]) = w;
            }
        }
        __syncthreads();
        #pragma unroll
        for (int kt = 0; kt < 4; kt++) {
            unsigned a[2][4], b[8][2];
            #pragma unroll
            for (int mi = 0; mi < 2; mi++) {
                int mb = wr*32 + mi*16;
                a[mi][0] = Qs[(mb+g  )*QP + kt*8 + tg];
                a[mi][1] = Qs[(mb+g+8)*QP + kt*8 + tg];
                a[mi][2] = Qs[(mb+g  )*QP + kt*8 + tg + 4];
                a[mi][3] = Qs[(mb+g+8)*QP + kt*8 + tg + 4];
            }
            #pragma unroll
            for (int nj = 0; nj < 8; nj++) {
                int nb = wc*64 + nj*8;
                b[nj][0] = Ks[(nb+g)*KP + kt*8 + tg];
                b[nj][1] = Ks[(nb+g)*KP + kt*8 + tg + 4];
            }
            #pragma unroll
            for (int mi = 0; mi < 2; mi++)
                #pragma unroll
                for (int nj = 0; nj < 8; nj++)
                    mma_f16(acc[mi*8+nj], a[mi][0],a[mi][1],a[mi][2],a[mi][3],
                            b[nj][0], b[nj][1]);
        }
        if (k0 + 64 < Kdim) __syncthreads();
    }

    // ---- scale + mask ----
    #pragma unroll
    for (int mi = 0; mi < 2; mi++) {
        #pragma unroll
        for (int nj = 0; nj < 8; nj++) {
            float* d = acc[mi*8+nj];
            int col = wc*64 + nj*8 + tg*2;
            int lr0 = wr*32 + mi*16 + g;
            #pragma unroll
            for (int c = 0; c < 4; c++) {
                int gcol = col + (c & 1);
                int grow = rowBase + lr0 + ((c >> 1) * 8);
                float v = d[c] * scale;
                if (MASK == 1) {
                    if (tok[bb*tokStride + gcol] == 0 || gcol > grow) v = -1e9f;
                } else if (MASK == 2) {
                    if (tok[bb*tokStride + gcol] == 0) v = -1e9f;
                }
                d[c] = v;
            }
        }
    }

    // ---- softmax (fp32) ----
    float rmax[4];
    #pragma unroll
    for (int mi = 0; mi < 2; mi++) {
        float m0 = -1e30f, m1 = -1e30f;
        #pragma unroll
        for (int nj = 0; nj < 8; nj++) {
            float* d = acc[mi*8+nj];
            m0 = fmaxf(m0, fmaxf(d[0], d[1]));
            m1 = fmaxf(m1, fmaxf(d[2], d[3]));
        }
        rmax[mi*2+0] = m0; rmax[mi*2+1] = m1;
    }
    #pragma unroll
    for (int i = 0; i < 4; i++) {
        rmax[i] = fmaxf(rmax[i], __shfl_xor_sync(0xffffffffu, rmax[i], 1));
        rmax[i] = fmaxf(rmax[i], __shfl_xor_sync(0xffffffffu, rmax[i], 2));
    }
    if (tg == 0) {
        #pragma unroll
        for (int mi = 0; mi < 2; mi++) {
            red[(wr*32 + mi*16 + g    )*4 + wc] = rmax[mi*2+0];
            red[(wr*32 + mi*16 + g + 8)*4 + wc] = rmax[mi*2+1];
        }
    }
    __syncthreads();
    float fmax4[4];
    #pragma unroll
    for (int mi = 0; mi < 2; mi++) {
        int r0 = wr*32 + mi*16 + g, r1 = r0 + 8;
        fmax4[mi*2+0] = fmaxf(fmaxf(red[r0*4+0], red[r0*4+1]), fmaxf(red[r0*4+2], red[r0*4+3]));
        fmax4[mi*2+1] = fmaxf(fmaxf(red[r1*4+0], red[r1*4+1]), fmaxf(red[r1*4+2], red[r1*4+3]));
    }
    __syncthreads();

    float rsum[4] = {0.f, 0.f, 0.f, 0.f};
    #pragma unroll
    for (int mi = 0; mi < 2; mi++) {
        #pragma unroll
        for (int nj = 0; nj < 8; nj++) {
            float* d = acc[mi*8+nj];
            d[0] = __expf(d[0] - fmax4[mi*2+0]);
            d[1] = __expf(d[1] - fmax4[mi*2+0]);
            d[2] = __expf(d[2] - fmax4[mi*2+1]);
            d[3] = __expf(d[3] - fmax4[mi*2+1]);
            rsum[mi*2+0] += d[0] + d[1];
            rsum[mi*2+1] += d[2] + d[3];
        }
    }
    #pragma unroll
    for (int i = 0; i < 4; i++) {
        rsum[i] += __shfl_xor_sync(0xffffffffu, rsum[i], 1);
        rsum[i] += __shfl_xor_sync(0xffffffffu, rsum[i], 2);
    }
    if (tg == 0) {
        #pragma unroll
        for (int mi = 0; mi < 2; mi++) {
            red[(wr*32 + mi*16 + g    )*4 + wc] = rsum[mi*2+0];
            red[(wr*32 + mi*16 + g + 8)*4 + wc] = rsum[mi*2+1];
        }
    }
    __syncthreads();
    float rinv[4];
    #pragma unroll
    for (int mi = 0; mi < 2; mi++) {
        int r0 = wr*32 + mi*16 + g, r1 = r0 + 8;
        rinv[mi*2+0] = 1.f / (red[r0*4+0] + red[r0*4+1] + red[r0*4+2] + red[r0*4+3]);
        rinv[mi*2+1] = 1.f / (red[r1*4+0] + red[r1*4+1] + red[r1*4+2] + red[r1*4+3]);
    }

    float* Pb = P + (long)z * 65536L + (long)rowBase * 256;
    #pragma unroll
    for (int mi = 0; mi < 2; mi++) {
        #pragma unroll
        for (int nj = 0; nj < 8; nj++) {
            float* d = acc[mi*8+nj];
            int col = wc*64 + nj*8 + tg*2;
            int r0 = wr*32 + mi*16 + g;
            float p0 = d[0]*rinv[mi*2+0], p1 = d[1]*rinv[mi*2+0];
            float p2 = d[2]*rinv[mi*2+1], p3 = d[3]*rinv[mi*2+1];
            *reinterpret_cast<float2*>(Pb + (long)r0*256 + col) = make_float2(p0, p1);
            *reinterpret_cast<float2*>(Pb + (long)(r0+8)*256 + col) = make_float2(p2, p3);
            if (CTX) {
                int k2 = wc*32 + nj*4 + tg;
                Ps[r0*PP + k2]     = pack_h2(p0, p1);
                Ps[(r0+8)*PP + k2] = pack_h2(p2, p3);
            }
        }
    }

    if (CTX) {
        __syncthreads();
        float acc2[4][4];
        #pragma unroll
        for (int i = 0; i < 4; i++) { acc2[i][0]=0.f; acc2[i][1]=0.f; acc2[i][2]=0.f; acc2[i][3]=0.f; }
        #pragma unroll
        for (int kt = 0; kt < 16; kt++) {
            unsigned a[2][4], b[2][2];
            #pragma unroll
            for (int mi = 0; mi < 2; mi++) {
                int mb = wr*32 + mi*16;
                a[mi][0] = Ps[(mb+g  )*PP + kt*8 + tg];
                a[mi][1] = Ps[(mb+g+8)*PP + kt*8 + tg];
                a[mi][2] = Ps[(mb+g  )*PP + kt*8 + tg + 4];
                a[mi][3] = Ps[(mb+g+8)*PP + kt*8 + tg + 4];
            }
            #pragma unroll
            for (int nj = 0; nj < 2; nj++) {
                int nb = wc*16 + nj*8 + g;
                b[nj][0] = Vs[(kt*8 + tg    )*VBP + nb];
                b[nj][1] = Vs[(kt*8 + tg + 4)*VBP + nb];
            }
            #pragma unroll
            for (int mi = 0; mi < 2; mi++)
                #pragma unroll
                for (int nj = 0; nj < 2; nj++)
                    mma_f16(acc2[mi*2+nj], a[mi][0],a[mi][1],a[mi][2],a[mi][3],
                            b[nj][0], b[nj][1]);
        }
        __half* Cb = (__half*)Cctx + (long)bb*TT*DD + hh*64;
        #pragma unroll
        for (int mi = 0; mi < 2; mi++) {
            #pragma unroll
            for (int nj = 0; nj < 2; nj++) {
                float* d = acc2[mi*2+nj];
                int r0 = rowBase + wr*32 + mi*16 + g;
                int col = wc*16 + nj*8 + tg*2;
                *reinterpret_cast<unsigned*>(Cb + (long)r0*DD + col) = pack_h2(d[0], d[1]);
                *reinterpret_cast<unsigned*>(Cb + (long)(r0+8)*DD + col) = pack_h2(d[2], d[3]);
            }
        }
    }
}

// ---------------------------------------------------------------------
// add_ln: dual output (fp32 + fp16). out may alias a/b; outh separate.
// ---------------------------------------------------------------------
__global__ __launch_bounds__(128) void add_ln(
    const float* __restrict__ a, const float* __restrict__ b,
    float* __restrict__ out, __half* __restrict__ outh,
    const float* __restrict__ g, const float* __restrict__ beta)
{
    long off = (long)blockIdx.x * DD;
    int t = threadIdx.x;
    int warp = t >> 5, lane = t & 31;
    float4 va = *reinterpret_cast<const float4*>(a + off + t*4);
    float4 vb = *reinterpret_cast<const float4*>(b + off + t*4);
    float4 v;
    v.x = va.x + vb.x; v.y = va.y + vb.y; v.z = va.z + vb.z; v.w = va.w + vb.w;
    __shared__ float ws[4], ws2[4];

    float s = v.x + v.y + v.z + v.w;
    #pragma unroll
    for (int o = 16; o > 0; o >>= 1) s += __shfl_xor_sync(0xffffffffu, s, o);
    if (lane == 0) ws[warp] = s;
    __syncthreads();
    float mu = (ws[0]+ws[1]+ws[2]+ws[3]) * (1.f/DD);

    float4 d;
    d.x = v.x - mu; d.y = v.y - mu; d.z = v.z - mu; d.w = v.w - mu;
    float q = d.x*d.x + d.y*d.y + d.z*d.z + d.w*d.w;
    #pragma unroll
    for (int o = 16; o > 0; o >>= 1) q += __shfl_xor_sync(0xffffffffu, q, o);
    if (lane == 0) ws2[warp] = q;
    __syncthreads();
    float rstd = rsqrtf((ws2[0]+ws2[1]+ws2[2]+ws2[3]) * (1.f/DD) + 1e-5f);

    float4 gg = g ? *reinterpret_cast<const float4*>(g + t*4)
                  : make_float4(1.f, 1.f, 1.f, 1.f);
    float4 bb = beta ? *reinterpret_cast<const float4*>(beta + t*4)
                     : make_float4(0.f, 0.f, 0.f, 0.f);
    float4 o;
    o.x = d.x * rstd * gg.x + bb.x;
    o.y = d.y * rstd * gg.y + bb.y;
    o.z = d.z * rstd * gg.z + bb.z;
    o.w = d.w * rstd * gg.w + bb.w;
    *reinterpret_cast<float4*>(out + off + t*4) = o;
    uint2 oh; oh.x = pack_h2(o.x, o.y); oh.y = pack_h2(o.z, o.w);
    *reinterpret_cast<uint2*>(outh + off + t*4) = oh;
}

__global__ void embed_pe(const int* __restrict__ dec,
                         const float* __restrict__ emb,
                         float* __restrict__ x, __half* __restrict__ xh)
{
    long idx = (long)blockIdx.x * blockDim.x + threadIdx.x;
    if (idx >= (long)BT*DD) return;
    int d  = (int)(idx % DD);
    long bt = idx / DD;
    int t  = (int)(bt % TT);
    int tokidx = dec[bt];
    int d2 = d & ~1;
    float div = expf(-logf(10000.f) * (float)d2 / (float)DD);
    float ang = (float)t * div;
    float pe = (d & 1) ? cosf(ang) : sinf(ang);
    float v = emb[(long)tokidx*DD + d] + pe;
    x[idx] = v;
    xh[idx] = __float2half(v);
}

// multi -> half directly
__global__ void add3h(const float* __restrict__ a, const float* __restrict__ bias,
                      const float* __restrict__ c, __half* __restrict__ outh, long n)
{
    long i = (long)blockIdx.x * blockDim.x + threadIdx.x;
    if (i >= n) return;
    outh[i] = __float2half(a[i] + bias[i % DD] + c[i]);
}

// ---------------------------------------------------------------------
extern "C" void kernel_launch(void* const* d_in, const int* in_sizes, int n_in,
                              void* d_out, int out_size)
{
    const int*   dec     = (const int*)  d_in[0];
    const int*   enc     = (const int*)  d_in[1];
    const float* enc_out = (const float*)d_in[2];
    const float* ast_out = (const float*)d_in[3];
    const float* src_emb = (const float*)d_in[4];
    const float* ast_emb = (const float*)d_in[5];
    const float* emb     = (const float*)d_in[7];
    const float* attn_W  = (const float*)d_in[8];
    const float* ln_g    = (const float*)d_in[9];
    const float* ln_b    = (const float*)d_in[10];
    const float* W1      = (const float*)d_in[11];
    const float* W2      = (const float*)d_in[12];
    const float* conv_w  = (const float*)d_in[13];
    const float* conv_b  = (const float*)d_in[14];
    const float* mffnW   = (const float*)d_in[15];
    const float* mffnb   = (const float*)d_in[16];
    float* out = (float*)d_out;

    float *x,*t,*pt,*ast1,*aste,*mm,*mmctx;
    __half *wb, *qkvh, *ch, *hh, *xh, *ench, *multih;
    cudaGetSymbolAddress((void**)&x,     g_x);
    cudaGetSymbolAddress((void**)&xh,    g_xh);
    cudaGetSymbolAddress((void**)&t,     g_t);
    cudaGetSymbolAddress((void**)&pt,    g_pt);
    cudaGetSymbolAddress((void**)&qkvh,  g_qkvh);
    cudaGetSymbolAddress((void**)&ch,    g_ch);
    cudaGetSymbolAddress((void**)&hh,    g_hh);
    cudaGetSymbolAddress((void**)&ench,  g_ench);
    cudaGetSymbolAddress((void**)&multih,g_multih);
    cudaGetSymbolAddress((void**)&ast1,  g_ast1);
    cudaGetSymbolAddress((void**)&aste,  g_aste);
    cudaGetSymbolAddress((void**)&mm,    g_mm);
    cudaGetSymbolAddress((void**)&mmctx, g_mmctx);
    cudaGetSymbolAddress((void**)&wb,    g_wb);

    const int GM_SMEM  = 2*BUFW*4;
    const int AT_SMEM  = (64*QP + 256*KP + 128*VBP)*4;
    const int MM_SMEM  = (64*QP + 256*KP)*4;
    cudaFuncSetAttribute((const void*)gemm2<false,false,false,false>, cudaFuncAttributeMaxDynamicSharedMemorySize, GM_SMEM);
    cudaFuncSetAttribute((const void*)gemm2<false,true ,false,false>, cudaFuncAttributeMaxDynamicSharedMemorySize, GM_SMEM);
    cudaFuncSetAttribute((const void*)gemm2<false,false,true ,true >, cudaFuncAttributeMaxDynamicSharedMemorySize, GM_SMEM);
    cudaFuncSetAttribute((const void*)gemm2h<false,true ,true >, cudaFuncAttributeMaxDynamicSharedMemorySize, GM_SMEM);
    cudaFuncSetAttribute((const void*)gemm2h<true ,true ,true >, cudaFuncAttributeMaxDynamicSharedMemorySize, GM_SMEM);
    cudaFuncSetAttribute((const void*)gemm2h<false,true ,false>, cudaFuncAttributeMaxDynamicSharedMemorySize, GM_SMEM);
    cudaFuncSetAttribute((const void*)attn_fused<0,false,false>, cudaFuncAttributeMaxDynamicSharedMemorySize, MM_SMEM);
    cudaFuncSetAttribute((const void*)attn_fused<0,true ,true >, cudaFuncAttributeMaxDynamicSharedMemorySize, AT_SMEM);
    cudaFuncSetAttribute((const void*)attn_fused<1,true ,true >, cudaFuncAttributeMaxDynamicSharedMemorySize, AT_SMEM);
    cudaFuncSetAttribute((const void*)attn_fused<2,true ,true >, cudaFuncAttributeMaxDynamicSharedMemorySize, AT_SMEM);

    __half* q = qkvh;
    __half* k = qkvh + (long)BT*DD;
    __half* v = qkvh + 2L*BT*DD;

    // ---- one-time conversions (main stream; feed layer 0) ----
    w2h<<<(int)((18874368/4 + 255)/256), 256>>>(attn_W, wb + WB_ATTN, 18874368/4);
    w2h<<<(int)((6291456/4  + 255)/256), 256>>>(W1,     wb + WB_W1,   6291456/4);
    w2h<<<(int)((6291456/4  + 255)/256), 256>>>(W2,     wb + WB_W2,   6291456/4);
    w2h<<<(int)(((long)BB*SS*DD/4 + 255)/256), 256>>>(enc_out, ench, (long)BB*SS*DD/4);

    // ---- fork: preamble on s2 (writes ONLY pt/ast1/aste/mm/mmctx/multih) ----
    cudaStream_t s2;
    cudaStreamCreate(&s2);
    cudaEvent_t evF, evJ;
    cudaEventCreateWithFlags(&evF, cudaEventDisableTiming);
    cudaEventCreateWithFlags(&evJ, cudaEventDisableTiming);
    cudaEventRecord(evF, 0);
    cudaStreamWaitEvent(s2, evF, 0);

    {
        dim3 gc(DD/128, SS/64, BB);
        gemm2<false,false,true,true><<<gc, 256, GM_SMEM, s2>>>(
            conv_w, conv_w, conv_w, 0L, ast_out, (long)NA*DD,
            ast1, (long)SS*DD, conv_b, SS, DD, NA);
        gemm2<false,false,true,true><<<gc, 256, GM_SMEM, s2>>>(
            conv_w, conv_w, conv_w, 0L, ast_emb, (long)NA*DD,
            aste, (long)SS*DD, conv_b, SS, DD, NA);
        dim3 gs(SS/64, BB);
        attn_fused<0,false,false><<<gs, 256, MM_SMEM, s2>>>(ast1, enc_out, nullptr, mm, nullptr,
            DD, DD, DD, (long)SS*DD, 0L, (long)SS*DD, 0L,
            1, 0.125f, nullptr, 0);
        dim3 gm(DD/128, SS/64, BB);
        gemm2<false,false,false,false><<<gm, 256, GM_SMEM, s2>>>(
            mm, mm, mm, (long)SS*SS, enc_out, (long)SS*DD,
            mmctx, (long)SS*DD, nullptr, SS, DD, SS);
        dim3 gp(DD/128, BT/64, 1);
        gemm2<false,false,false,false><<<gp, 256, GM_SMEM, s2>>>(
            src_emb, src_emb, src_emb, 0L, mffnW, 0L, pt, 0L, nullptr, BT, DD, DD);
        gemm2<false,true ,false,false><<<gp, 256, GM_SMEM, s2>>>(
            aste, aste, aste, 0L, mffnW + DD*DD, 0L, pt, 0L, nullptr, BT, DD, DD);
        long n = (long)BB*SS*DD;
        add3h<<<(int)((n + 255)/256), 256, 0, s2>>>(pt, mffnb, mmctx, multih, n);
    }
    cudaEventRecord(evJ, s2);

    // ---------------- main path ----------------
    embed_pe<<<(BT*DD + 255)/256, 256>>>(dec, emb, x, xh);

    dim3 gQKV(DD/128, BT/64, 3);
    dim3 gProj(DD/128, BT/64, 1);
    dim3 gF1(DFF/128, BT/64, 1);
    dim3 gScore(TT/64, BB*HH);

    for (int l = 0; l < LL; l++) {
        for (int a = 0; a < 3; a++) {
            const __half* wqkv = wb + WB_ATTN + (long)((l*3 + a)*4) * 262144;
            const __half* wo   = wb + WB_ATTN + (long)((l*3 + a)*4 + 3) * 262144;
            const __half* xk = (a == 0) ? xh : (a == 1 ? ench : multih);

            if (l == 0 && a == 2) cudaStreamWaitEvent(0, evJ, 0);

            gemm2h<false,true,true><<<gQKV, 256, GM_SMEM>>>(
                xh, xk, xk, 0L, wqkv, 262144L, qkvh, (long)BT*DD, BT, DD, DD);

            long attnBase = (a == 0 ? SELF_OFF : (a == 1 ? ENC_OFF : AST_OFF))
                            + (long)l * BHTT;
            float* P = out + attnBase;

            if (a == 0)
                attn_fused<1,true,true><<<gScore, 256, AT_SMEM>>>(q, k, v, P, ch,
                    DKK, DD, DD, (long)TT*DD, 64L, (long)TT*DD, 64L,
                    HH, 0.125f, dec, TT);
            else if (a == 1)
                attn_fused<2,true,true><<<gScore, 256, AT_SMEM>>>(q, k, v, P, ch,
                    DKK, DD, DD, (long)TT*DD, 64L, (long)TT*DD, 64L,
                    HH, 0.125f, enc, SS);
            else
                attn_fused<0,true,true><<<gScore, 256, AT_SMEM>>>(q, k, v, P, ch,
                    DKK, DD, DD, (long)TT*DD, 64L, (long)TT*DD, 64L,
                    HH, 0.125f, nullptr, 0);

            gemm2h<false,true,false><<<gProj, 256, GM_SMEM>>>(
                ch, ch, ch, 0L, wo, 0L, t, 0L, BT, DD, DD);
            add_ln<<<BT, 128>>>(t, x, x, xh,
                ln_g + (long)(l*3 + a)*DD, ln_b + (long)(l*3 + a)*DD);
        }
        gemm2h<true,true,true><<<gF1, 256, GM_SMEM>>>(
            xh, xh, xh, 0L, wb + WB_W1 + (long)l*1048576, 0L, hh, 0L, BT, DFF, DD);
        gemm2h<false,true,false><<<gProj, 256, GM_SMEM>>>(
            hh, hh, hh, 0L, wb + WB_W2 + (long)l*1048576, 0L, t, 0L, BT, DD, DFF);
        // final LN writes x directly into d_out (region disjoint from P slices)
        float* lnOut = (l == LL-1) ? out : x;
        add_ln<<<BT, 128>>>(t, x, lnOut, xh, nullptr, nullptr);
    }

    cudaStreamDestroy(s2);
    cudaEventDestroy(evF);
    cudaEventDestroy(evJ);
}